// round 2
// baseline (speedup 1.0000x reference)
#include <cuda_runtime.h>
#include <math.h>

#define NT 256
#define ROWS_PER_CTA 128
#define GRID_CTAS 296          // 148 SMs * 2 CTAs

// ---- shared memory layout (float offsets) ----
#define OFF_CWT   0        // [8][16][64] chart_w (c,l,h)      8192
#define OFF_TEXWT 8192     // [16][64]    tex_w (l,h)          1024
#define OFF_W1T   9216     // [64][64]    w1 (k,o)             4096
#define OFF_W2T   13312    // [64][32]    w2 (k,o)             2048
#define OFF_CB    15360    // [8][64]                           512
#define OFF_CEN   15872    // [8][16]                           128
#define OFF_RW    16000    // [8][16]                           128
#define OFF_RB    16128    // [8]                                 8
#define OFF_TEXB  16136    // [64]                               64
#define OFF_LNG   16200    // [64]                               64
#define OFF_LNB   16264    // [64]                               64
#define OFF_B1    16328    // [64]                               64
#define OFF_B2    16392    // [32]                               32
#define OFF_RWS   16424    // [8][128]  router weights per row 1024
#define OFF_GS    17448    // [64][128] gelu staging per row   8192
#define SMEM_FLOATS 25640  // 102560 bytes -> 2 CTAs/SM

typedef unsigned long long u64t;

__device__ __forceinline__ u64t pack2(float x) {
    u64t r; asm("mov.b64 %0, {%1, %1};" : "=l"(r) : "f"(x)); return r;
}
__device__ __forceinline__ void ffma2(u64t &a, u64t w, u64t c) {
    asm("fma.rn.f32x2 %0, %1, %2, %0;" : "+l"(a) : "l"(w), "l"(c));
}
__device__ __forceinline__ float2 unpk(u64t v) {
    float lo, hi; asm("mov.b64 {%0, %1}, %2;" : "=f"(lo), "=f"(hi) : "l"(v));
    return make_float2(lo, hi);
}
__device__ __forceinline__ float gelu_exact(float x) { return x * normcdff(x); }

__global__ __launch_bounds__(NT, 2)
void topo_decoder_kernel(
    const float* __restrict__ z_geo, const float* __restrict__ z_tex,
    const float* __restrict__ chart_w, const float* __restrict__ chart_b,
    const float* __restrict__ router_w, const float* __restrict__ router_b,
    const float* __restrict__ centers,
    const float* __restrict__ tex_w, const float* __restrict__ tex_b,
    const float* __restrict__ ln_g, const float* __restrict__ ln_b,
    const float* __restrict__ w1, const float* __restrict__ b1,
    const float* __restrict__ w2, const float* __restrict__ b2,
    float* __restrict__ out, int B)
{
    extern __shared__ float sm[];
    const int tid = threadIdx.x;

    // ---- cooperative weight staging (transposed so h/o is contiguous) ----
    for (int i = tid; i < 8192; i += NT) {
        int c = i >> 10, r = i & 1023, hh = r >> 4, l = r & 15;
        sm[OFF_CWT + (c << 10) + (l << 6) + hh] = chart_w[i];
    }
    for (int i = tid; i < 1024; i += NT) {
        int hh = i >> 4, l = i & 15;
        sm[OFF_TEXWT + l * 64 + hh] = tex_w[i];
    }
    for (int i = tid; i < 4096; i += NT) {
        int o = i >> 6, k = i & 63;
        sm[OFF_W1T + k * 64 + o] = w1[i];
    }
    for (int i = tid; i < 2048; i += NT) {
        int o = i >> 6, k = i & 63;
        sm[OFF_W2T + k * 32 + o] = w2[i];
    }
    for (int i = tid; i < 512; i += NT) sm[OFF_CB + i] = chart_b[i];
    if (tid < 128) { sm[OFF_CEN + tid] = centers[tid]; sm[OFF_RW + tid] = router_w[tid]; }
    if (tid < 64)  { sm[OFF_TEXB + tid] = tex_b[tid]; sm[OFF_LNG + tid] = ln_g[tid];
                     sm[OFF_LNB + tid] = ln_b[tid];   sm[OFF_B1 + tid]  = b1[tid]; }
    if (tid < 32)  sm[OFF_B2 + tid] = b2[tid];
    if (tid < 8)   sm[OFF_RB + tid] = router_b[tid];
    __syncthreads();

    const int half = tid & 1;        // which 32 of the 64 hidden dims this thread owns
    const int rl   = tid >> 1;       // row within tile [0,128)
    const int h0   = half << 5;      // 0 or 32
    const int nTiles = B / ROWS_PER_CTA;

    for (int tile = blockIdx.x; tile < nTiles; tile += GRID_CTAS) {
        const int row = tile * ROWS_PER_CTA + rl;

        // ---- load latents (each thread of the pair loads full vectors) ----
        float zg[16], zt[16];
        {
            const float4* p = (const float4*)(z_geo + (size_t)row * 16);
            #pragma unroll
            for (int q = 0; q < 4; ++q) {
                float4 v = p[q];
                zg[q*4+0]=v.x; zg[q*4+1]=v.y; zg[q*4+2]=v.z; zg[q*4+3]=v.w;
            }
            const float4* p2 = (const float4*)(z_tex + (size_t)row * 16);
            #pragma unroll
            for (int q = 0; q < 4; ++q) {
                float4 v = p2[q];
                zt[q*4+0]=v.x; zt[q*4+1]=v.y; zt[q*4+2]=v.z; zt[q*4+3]=v.w;
            }
        }

        float z_sq = 0.f;
        #pragma unroll
        for (int l = 0; l < 16; ++l) z_sq = fmaf(zg[l], zg[l], z_sq);
        const float one_minus = 1.0f - z_sq;
        const float tau = fmaxf(2.0f * fmaxf(one_minus, 0.001f), 0.01f);
        const float inv_tau = 1.0f / tau;

        // ---- router (duplicated in both threads of the pair) ----
        float w[8];
        float mx = -1e30f;
        #pragma unroll
        for (int c = 0; c < 8; ++c) {
            float ds = 0.f, cs = 0.f, dr = 0.f;
            #pragma unroll
            for (int l = 0; l < 16; ++l) {
                float cv = sm[OFF_CEN + c * 16 + l];
                float d  = zg[l] - cv;
                ds = fmaf(d, d, ds);
                cs = fmaf(cv, cv, cs);
                dr = fmaf(zg[l], sm[OFF_RW + c * 16 + l], dr);
            }
            float denom = one_minus * (1.0f - cs);
            float arg = fmaf(2.0f * ds, 1.0f / (denom + 0.001f), 1.0f);
            arg = fmaxf(arg, 1.0f + 0.001f);
            float dist = acoshf(arg);
            float s = (-dist + 0.1f * (dr + sm[OFF_RB + c])) * inv_tau;
            w[c] = s;
            mx = fmaxf(mx, s);
        }
        float ssum = 0.f;
        #pragma unroll
        for (int c = 0; c < 8; ++c) { w[c] = expf(w[c] - mx); ssum += w[c]; }
        const float inv_sum = 1.0f / ssum;
        #pragma unroll
        for (int c = 0; c < 8; ++c) w[c] *= inv_sum;

        if (half == 0) {
            float* rout = out + (size_t)B * 32 + (size_t)row * 8;
            ((float4*)rout)[0] = make_float4(w[0], w[1], w[2], w[3]);
            ((float4*)rout)[1] = make_float4(w[4], w[5], w[6], w[7]);
            #pragma unroll
            for (int c = 0; c < 8; ++c) sm[OFF_RWS + c * 128 + rl] = w[c];
        }

        // ---- bias init: h = tex_b + sum_c w_c * chart_b[c] (this thread's 32 dims) ----
        float hf[32];
        #pragma unroll
        for (int i = 0; i < 32; ++i) hf[i] = sm[OFF_TEXB + h0 + i];
        #pragma unroll
        for (int c = 0; c < 8; ++c) {
            float wc = w[c];
            #pragma unroll
            for (int i = 0; i < 32; ++i)
                hf[i] = fmaf(wc, sm[OFF_CB + c * 64 + h0 + i], hf[i]);
        }
        u64t h2[16];
        #pragma unroll
        for (int q = 0; q < 16; ++q) {
            asm("mov.b64 %0, {%1, %2};" : "=l"(h2[q]) : "f"(hf[2*q]), "f"(hf[2*q+1]));
        }

        // ---- tex projection (zt in regs, fully unrolled) ----
        #pragma unroll
        for (int l = 0; l < 16; ++l) {
            u64t c2 = pack2(zt[l]);
            const ulonglong2* p = (const ulonglong2*)&sm[OFF_TEXWT + l * 64 + h0];
            #pragma unroll
            for (int q = 0; q < 8; ++q) {
                ulonglong2 v = p[q];
                ffma2(h2[2*q],   v.x, c2);
                ffma2(h2[2*q+1], v.y, c2);
            }
        }

        __syncwarp();

        // ---- chart projections: runtime c loop, zg in regs ----
        #pragma unroll 1
        for (int c = 0; c < 8; ++c) {
            float wc = sm[OFF_RWS + c * 128 + rl];
            const float* base = &sm[OFF_CWT + c * 1024 + h0];
            #pragma unroll
            for (int l = 0; l < 16; ++l) {
                u64t c2 = pack2(wc * zg[l]);
                const ulonglong2* p = (const ulonglong2*)(base + l * 64);
                #pragma unroll
                for (int q = 0; q < 8; ++q) {
                    ulonglong2 v = p[q];
                    ffma2(h2[2*q],   v.x, c2);
                    ffma2(h2[2*q+1], v.y, c2);
                }
            }
        }

        // ---- LayerNorm over the pair + GELU, stage g to smem ----
        #pragma unroll
        for (int q = 0; q < 16; ++q) {
            float2 v = unpk(h2[q]);
            hf[2*q] = v.x; hf[2*q+1] = v.y;
        }
        float s1 = 0.f;
        #pragma unroll
        for (int i = 0; i < 32; ++i) s1 += hf[i];
        s1 += __shfl_xor_sync(0xffffffffu, s1, 1);
        const float mu = s1 * (1.0f / 64.0f);
        float s2 = 0.f;
        #pragma unroll
        for (int i = 0; i < 32; ++i) { float d = hf[i] - mu; s2 = fmaf(d, d, s2); }
        s2 += __shfl_xor_sync(0xffffffffu, s2, 1);
        const float rstd = rsqrtf(s2 * (1.0f / 64.0f) + 1e-5f);
        #pragma unroll
        for (int i = 0; i < 32; ++i) {
            float hn = (hf[i] - mu) * rstd * sm[OFF_LNG + h0 + i] + sm[OFF_LNB + h0 + i];
            sm[OFF_GS + (h0 + i) * 128 + rl] = gelu_exact(hn);
        }
        __syncwarp();

        // ---- h1 = gelu(g @ w1^T + b1), this thread's 32 outputs ----
        u64t a1[16];
        #pragma unroll
        for (int q = 0; q < 16; ++q) a1[q] = 0ull;
        #pragma unroll 1
        for (int k = 0; k < 64; ++k) {
            u64t c2 = pack2(sm[OFF_GS + k * 128 + rl]);
            const ulonglong2* p = (const ulonglong2*)&sm[OFF_W1T + k * 64 + h0];
            #pragma unroll
            for (int q = 0; q < 8; ++q) {
                ulonglong2 v = p[q];
                ffma2(a1[2*q],   v.x, c2);
                ffma2(a1[2*q+1], v.y, c2);
            }
        }
        __syncwarp();
        #pragma unroll
        for (int q = 0; q < 16; ++q) {
            float2 v = unpk(a1[q]);
            sm[OFF_GS + (h0 + 2*q)     * 128 + rl] = gelu_exact(v.x + sm[OFF_B1 + h0 + 2*q]);
            sm[OFF_GS + (h0 + 2*q + 1) * 128 + rl] = gelu_exact(v.y + sm[OFF_B1 + h0 + 2*q + 1]);
        }
        __syncwarp();

        // ---- x_hat = h1 @ w2^T + b2, this thread's 16 outputs ----
        const int o0 = half << 4;   // 0 or 16
        u64t a2[8];
        #pragma unroll
        for (int q = 0; q < 8; ++q) a2[q] = 0ull;
        #pragma unroll 1
        for (int k = 0; k < 64; ++k) {
            u64t c2 = pack2(sm[OFF_GS + k * 128 + rl]);
            const ulonglong2* p = (const ulonglong2*)&sm[OFF_W2T + k * 32 + o0];
            #pragma unroll
            for (int q = 0; q < 4; ++q) {
                ulonglong2 v = p[q];
                ffma2(a2[2*q],   v.x, c2);
                ffma2(a2[2*q+1], v.y, c2);
            }
        }
        {
            float* xo = out + (size_t)row * 32 + o0;
            #pragma unroll
            for (int q = 0; q < 4; ++q) {
                float2 v0 = unpk(a2[2*q]);
                float2 v1 = unpk(a2[2*q+1]);
                float4 v = make_float4(v0.x + sm[OFF_B2 + o0 + 4*q + 0],
                                       v0.y + sm[OFF_B2 + o0 + 4*q + 1],
                                       v1.x + sm[OFF_B2 + o0 + 4*q + 2],
                                       v1.y + sm[OFF_B2 + o0 + 4*q + 3]);
                ((float4*)xo)[q] = v;
            }
        }
        __syncwarp();
    }
}

extern "C" void kernel_launch(void* const* d_in, const int* in_sizes, int n_in,
                              void* d_out, int out_size) {
    const float* z_geo    = (const float*)d_in[0];
    const float* z_tex    = (const float*)d_in[1];
    const float* chart_w  = (const float*)d_in[2];
    const float* chart_b  = (const float*)d_in[3];
    const float* router_w = (const float*)d_in[4];
    const float* router_b = (const float*)d_in[5];
    const float* centers  = (const float*)d_in[6];
    const float* tex_w    = (const float*)d_in[7];
    const float* tex_b    = (const float*)d_in[8];
    const float* ln_g     = (const float*)d_in[9];
    const float* ln_b     = (const float*)d_in[10];
    const float* w1       = (const float*)d_in[11];
    const float* b1       = (const float*)d_in[12];
    const float* w2       = (const float*)d_in[13];
    const float* b2       = (const float*)d_in[14];
    float* out = (float*)d_out;

    const int B = in_sizes[0] / 16;
    const size_t smem_bytes = (size_t)SMEM_FLOATS * sizeof(float);
    cudaFuncSetAttribute(topo_decoder_kernel,
                         cudaFuncAttributeMaxDynamicSharedMemorySize,
                         (int)smem_bytes);
    topo_decoder_kernel<<<GRID_CTAS, NT, smem_bytes>>>(
        z_geo, z_tex, chart_w, chart_b, router_w, router_b, centers,
        tex_w, tex_b, ln_g, ln_b, w1, b1, w2, b2, out, B);
}

// round 4
// speedup vs baseline: 2.3247x; 2.3247x over previous
#include <cuda_runtime.h>
#include <cuda_bf16.h>
#include <math.h>
#include <stdint.h>

#define NT 256
#define TILE 128
#define GRID_CTAS 148

// ---- smem layout (u32 word offsets) ----
#define X_OFF   0                    // [160][132] packed hi|lo  (X k-major, col=row-in-tile)
#define B1_OFF  21120                // [160][68]
#define B2_OFF  32000                // [64][68]
#define B3_OFF  36352                // [64][36]
#define LNG_OFF 38656                // [64] f32
#define LNB_OFF 38720
#define BB1_OFF 38784
#define BB2_OFF 38848                // [32]
#define SMEM_WORDS 38880             // 155520 bytes

__device__ __forceinline__ uint32_t prmtx(uint32_t a, uint32_t b, uint32_t s) {
    uint32_t d; asm("prmt.b32 %0,%1,%2,%3;" : "=r"(d) : "r"(a), "r"(b), "r"(s)); return d;
}
// pack f32 -> (bf16 hi in [15:0]) | (bf16 lo residual in [31:16])
__device__ __forceinline__ uint32_t pack_hl(float x) {
    unsigned short h = __bfloat16_as_ushort(__float2bfloat16(x));
    float hf = __uint_as_float((uint32_t)h << 16);
    unsigned short l = __bfloat16_as_ushort(__float2bfloat16(x - hf));
    return (uint32_t)h | ((uint32_t)l << 16);
}
// pack pair (v0 -> elem0, v1 -> elem1) to bf16x2 hi + residual lo
__device__ __forceinline__ void pack_pair(float v0, float v1, uint32_t &hi, uint32_t &lo) {
    asm("cvt.rn.bf16x2.f32 %0, %1, %2;" : "=r"(hi) : "f"(v1), "f"(v0));
    float h0 = __uint_as_float(hi << 16);
    float h1 = __uint_as_float(hi & 0xffff0000u);
    asm("cvt.rn.bf16x2.f32 %0, %1, %2;" : "=r"(lo) : "f"(v1 - h1), "f"(v0 - h0));
}
__device__ __forceinline__ void mma_bf16(float* c, const uint32_t* a, uint32_t b0, uint32_t b1) {
    asm volatile(
        "mma.sync.aligned.m16n8k16.row.col.f32.bf16.bf16.f32 "
        "{%0,%1,%2,%3}, {%4,%5,%6,%7}, {%8,%9}, {%0,%1,%2,%3};"
        : "+f"(c[0]), "+f"(c[1]), "+f"(c[2]), "+f"(c[3])
        : "r"(a[0]), "r"(a[1]), "r"(a[2]), "r"(a[3]), "r"(b0), "r"(b1));
}
__device__ __forceinline__ float gelu_exact(float x) {
    return 0.5f * x * (1.0f + erff(x * 0.70710678118654752f));
}

__global__ __launch_bounds__(NT, 1)
void topo_decoder_mma(
    const float* __restrict__ z_geo, const float* __restrict__ z_tex,
    const float* __restrict__ chart_w, const float* __restrict__ chart_b,
    const float* __restrict__ router_w, const float* __restrict__ router_b,
    const float* __restrict__ centers,
    const float* __restrict__ tex_w, const float* __restrict__ tex_b,
    const float* __restrict__ ln_g, const float* __restrict__ ln_b,
    const float* __restrict__ w1, const float* __restrict__ b1,
    const float* __restrict__ w2, const float* __restrict__ b2,
    float* __restrict__ out, int B)
{
    extern __shared__ uint32_t smu[];
    float* smf = (float*)smu;
    const int tid = threadIdx.x;
    const int wid = tid >> 5;
    const int lane = tid & 31;
    const int g = lane >> 2;       // mma group id (row within block)
    const int t = lane & 3;        // thread in group (k / col selector)

    // ================== one-time weight packing ==================
    // B1 logical [k=160][h=64]
    for (int i = tid; i < 160 * 64; i += NT) {
        int k = i >> 6, h = i & 63;
        float v;
        if (k < 128)       v = chart_w[(k >> 4) * 1024 + h * 16 + (k & 15)];
        else if (k < 144)  v = tex_w[h * 16 + (k - 128)];
        else if (k < 152)  v = chart_b[(k - 144) * 64 + h];
        else if (k == 152) v = tex_b[h];
        else               v = 0.0f;
        smu[B1_OFF + k * 68 + h] = pack_hl(v);
    }
    // B2 [k=64][o=64] = w1[o][k]
    for (int i = tid; i < 64 * 64; i += NT) {
        int k = i >> 6, n = i & 63;
        smu[B2_OFF + k * 68 + n] = pack_hl(w1[n * 64 + k]);
    }
    // B3 [k=64][o=32] = w2[o][k]
    for (int i = tid; i < 64 * 32; i += NT) {
        int k = i >> 5, n = i & 31;
        smu[B3_OFF + k * 36 + n] = pack_hl(w2[n * 64 + k]);
    }
    if (tid < 64) {
        smf[LNG_OFF + tid] = ln_g[tid];
        smf[LNB_OFF + tid] = ln_b[tid];
        smf[BB1_OFF + tid] = b1[tid];
    }
    if (tid < 32) smf[BB2_OFF + tid] = b2[tid];
    __syncthreads();

    const int nTiles = B / TILE;
    const int xcol = wid * 16;     // this warp's 16 rows within the X tile

    for (int tile = blockIdx.x; tile < nTiles; tile += GRID_CTAS) {
        const int rowbase = tile * TILE + xcol;

        // ================== prologue: router + X staging ==================
        {
            const int rl = xcol + (lane >> 1);          // row-in-tile this thread serves
            const int half = lane & 1;
            const int row = tile * TILE + rl;

            float zg[16];
            {
                const float4* p = (const float4*)(z_geo + (size_t)row * 16);
                #pragma unroll
                for (int q = 0; q < 4; ++q) {
                    float4 v = p[q];
                    zg[q*4+0]=v.x; zg[q*4+1]=v.y; zg[q*4+2]=v.z; zg[q*4+3]=v.w;
                }
            }
            float z_sq = 0.f;
            #pragma unroll
            for (int l = 0; l < 16; ++l) z_sq = fmaf(zg[l], zg[l], z_sq);
            const float one_minus = 1.0f - z_sq;
            const float inv_tau = 1.0f / fmaxf(2.0f * fmaxf(one_minus, 0.001f), 0.01f);

            float w[8], mx = -1e30f;
            #pragma unroll
            for (int c = 0; c < 8; ++c) {
                float ds = 0.f, cs = 0.f, dr = 0.f;
                #pragma unroll
                for (int l = 0; l < 16; ++l) {
                    float cv = centers[c * 16 + l];
                    float d = zg[l] - cv;
                    ds = fmaf(d, d, ds);
                    cs = fmaf(cv, cv, cs);
                    dr = fmaf(zg[l], router_w[c * 16 + l], dr);
                }
                float denom = one_minus * (1.0f - cs);
                float arg = fmaf(2.0f * ds, 1.0f / (denom + 0.001f), 1.0f);
                arg = fmaxf(arg, 1.001f);
                float s = (-acoshf(arg) + 0.1f * (dr + router_b[c])) * inv_tau;
                w[c] = s; mx = fmaxf(mx, s);
            }
            float ssum = 0.f;
            #pragma unroll
            for (int c = 0; c < 8; ++c) { w[c] = expf(w[c] - mx); ssum += w[c]; }
            const float inv_sum = 1.0f / ssum;
            #pragma unroll
            for (int c = 0; c < 8; ++c) w[c] *= inv_sum;

            if (half == 0) {
                float* rout = out + (size_t)B * 32 + (size_t)row * 8;
                ((float4*)rout)[0] = make_float4(w[0], w[1], w[2], w[3]);
                ((float4*)rout)[1] = make_float4(w[4], w[5], w[6], w[7]);
                // k = 0..79 : charts 0..4
                #pragma unroll
                for (int c = 0; c < 5; ++c)
                    #pragma unroll
                    for (int l = 0; l < 16; ++l)
                        smu[X_OFF + (c * 16 + l) * 132 + rl] = pack_hl(w[c] * zg[l]);
            } else {
                float zt[16];
                const float4* p2 = (const float4*)(z_tex + (size_t)row * 16);
                #pragma unroll
                for (int q = 0; q < 4; ++q) {
                    float4 v = p2[q];
                    zt[q*4+0]=v.x; zt[q*4+1]=v.y; zt[q*4+2]=v.z; zt[q*4+3]=v.w;
                }
                #pragma unroll
                for (int c = 5; c < 8; ++c)
                    #pragma unroll
                    for (int l = 0; l < 16; ++l)
                        smu[X_OFF + (c * 16 + l) * 132 + rl] = pack_hl(w[c] * zg[l]);
                #pragma unroll
                for (int l = 0; l < 16; ++l)
                    smu[X_OFF + (128 + l) * 132 + rl] = pack_hl(zt[l]);
                #pragma unroll
                for (int c = 0; c < 8; ++c)
                    smu[X_OFF + (144 + c) * 132 + rl] = pack_hl(w[c]);
                smu[X_OFF + 152 * 132 + rl] = pack_hl(1.0f);
                #pragma unroll
                for (int k = 153; k < 160; ++k)
                    smu[X_OFF + k * 132 + rl] = 0u;
            }
        }
        __syncwarp();

        // ================== GEMM1: [16x160] x [160x64] ==================
        float acc[8][4];
        #pragma unroll
        for (int nb = 0; nb < 8; ++nb)
            #pragma unroll
            for (int j = 0; j < 4; ++j) acc[nb][j] = 0.f;

        #pragma unroll 2
        for (int ks = 0; ks < 10; ++ks) {
            const int kb = ks * 16 + 2 * t;
            uint32_t ah[4], al[4];
            {
                uint32_t w00 = smu[X_OFF + kb * 132 + xcol + g];
                uint32_t w01 = smu[X_OFF + (kb + 1) * 132 + xcol + g];
                uint32_t w10 = smu[X_OFF + kb * 132 + xcol + g + 8];
                uint32_t w11 = smu[X_OFF + (kb + 1) * 132 + xcol + g + 8];
                uint32_t w20 = smu[X_OFF + (kb + 8) * 132 + xcol + g];
                uint32_t w21 = smu[X_OFF + (kb + 9) * 132 + xcol + g];
                uint32_t w30 = smu[X_OFF + (kb + 8) * 132 + xcol + g + 8];
                uint32_t w31 = smu[X_OFF + (kb + 9) * 132 + xcol + g + 8];
                ah[0] = prmtx(w00, w01, 0x5410); al[0] = prmtx(w00, w01, 0x7632);
                ah[1] = prmtx(w10, w11, 0x5410); al[1] = prmtx(w10, w11, 0x7632);
                ah[2] = prmtx(w20, w21, 0x5410); al[2] = prmtx(w20, w21, 0x7632);
                ah[3] = prmtx(w30, w31, 0x5410); al[3] = prmtx(w30, w31, 0x7632);
            }
            #pragma unroll
            for (int nb = 0; nb < 8; ++nb) {
                int n = nb * 8 + g;
                uint32_t u0 = smu[B1_OFF + kb * 68 + n];
                uint32_t u1 = smu[B1_OFF + (kb + 1) * 68 + n];
                uint32_t u2 = smu[B1_OFF + (kb + 8) * 68 + n];
                uint32_t u3 = smu[B1_OFF + (kb + 9) * 68 + n];
                uint32_t bh0 = prmtx(u0, u1, 0x5410), bl0 = prmtx(u0, u1, 0x7632);
                uint32_t bh1 = prmtx(u2, u3, 0x5410), bl1 = prmtx(u2, u3, 0x7632);
                mma_bf16(acc[nb], ah, bh0, bh1);
                mma_bf16(acc[nb], al, bh0, bh1);
                mma_bf16(acc[nb], ah, bl0, bl1);
            }
        }

        // ================== epilogue 1: LayerNorm + GELU -> A2 frags ==================
        uint32_t a2h[4][4], a2l[4][4];
        {
            float sum0 = 0.f, sum1 = 0.f, sq0 = 0.f, sq1 = 0.f;
            #pragma unroll
            for (int nb = 0; nb < 8; ++nb) {
                sum0 += acc[nb][0] + acc[nb][1];
                sum1 += acc[nb][2] + acc[nb][3];
                sq0 = fmaf(acc[nb][0], acc[nb][0], sq0); sq0 = fmaf(acc[nb][1], acc[nb][1], sq0);
                sq1 = fmaf(acc[nb][2], acc[nb][2], sq1); sq1 = fmaf(acc[nb][3], acc[nb][3], sq1);
            }
            sum0 += __shfl_xor_sync(~0u, sum0, 1); sum0 += __shfl_xor_sync(~0u, sum0, 2);
            sum1 += __shfl_xor_sync(~0u, sum1, 1); sum1 += __shfl_xor_sync(~0u, sum1, 2);
            sq0  += __shfl_xor_sync(~0u, sq0, 1);  sq0  += __shfl_xor_sync(~0u, sq0, 2);
            sq1  += __shfl_xor_sync(~0u, sq1, 1);  sq1  += __shfl_xor_sync(~0u, sq1, 2);
            const float mu0 = sum0 * (1.0f / 64.0f), mu1 = sum1 * (1.0f / 64.0f);
            const float rstd0 = rsqrtf(fmaf(-mu0, mu0, sq0 * (1.0f / 64.0f)) + 1e-5f);
            const float rstd1 = rsqrtf(fmaf(-mu1, mu1, sq1 * (1.0f / 64.0f)) + 1e-5f);

            float ge0[8][2], ge1[8][2];
            #pragma unroll
            for (int nb = 0; nb < 8; ++nb) {
                #pragma unroll
                for (int j = 0; j < 2; ++j) {
                    int col = nb * 8 + 2 * t + j;
                    float gma = smf[LNG_OFF + col], bta = smf[LNB_OFF + col];
                    ge0[nb][j] = gelu_exact(fmaf((acc[nb][j]     - mu0) * rstd0, gma, bta));
                    ge1[nb][j] = gelu_exact(fmaf((acc[nb][2 + j] - mu1) * rstd1, gma, bta));
                }
            }
            #pragma unroll
            for (int ks = 0; ks < 4; ++ks) {
                pack_pair(ge0[2*ks][0],   ge0[2*ks][1],   a2h[ks][0], a2l[ks][0]);
                pack_pair(ge1[2*ks][0],   ge1[2*ks][1],   a2h[ks][1], a2l[ks][1]);
                pack_pair(ge0[2*ks+1][0], ge0[2*ks+1][1], a2h[ks][2], a2l[ks][2]);
                pack_pair(ge1[2*ks+1][0], ge1[2*ks+1][1], a2h[ks][3], a2l[ks][3]);
            }
        }

        // ================== GEMM2: [16x64] x [64x64] ==================
        #pragma unroll
        for (int nb = 0; nb < 8; ++nb)
            #pragma unroll
            for (int j = 0; j < 4; ++j) acc[nb][j] = 0.f;
        #pragma unroll
        for (int ks = 0; ks < 4; ++ks) {
            const int kb = ks * 16 + 2 * t;
            #pragma unroll
            for (int nb = 0; nb < 8; ++nb) {
                int n = nb * 8 + g;
                uint32_t u0 = smu[B2_OFF + kb * 68 + n];
                uint32_t u1 = smu[B2_OFF + (kb + 1) * 68 + n];
                uint32_t u2 = smu[B2_OFF + (kb + 8) * 68 + n];
                uint32_t u3 = smu[B2_OFF + (kb + 9) * 68 + n];
                uint32_t bh0 = prmtx(u0, u1, 0x5410), bl0 = prmtx(u0, u1, 0x7632);
                uint32_t bh1 = prmtx(u2, u3, 0x5410), bl1 = prmtx(u2, u3, 0x7632);
                mma_bf16(acc[nb], a2h[ks], bh0, bh1);
                mma_bf16(acc[nb], a2l[ks], bh0, bh1);
                mma_bf16(acc[nb], a2h[ks], bl0, bl1);
            }
        }

        // ================== epilogue 2: +b1, GELU -> A3 frags ==================
        uint32_t a3h[4][4], a3l[4][4];
        {
            float ge0[8][2], ge1[8][2];
            #pragma unroll
            for (int nb = 0; nb < 8; ++nb) {
                #pragma unroll
                for (int j = 0; j < 2; ++j) {
                    int col = nb * 8 + 2 * t + j;
                    float bb = smf[BB1_OFF + col];
                    ge0[nb][j] = gelu_exact(acc[nb][j] + bb);
                    ge1[nb][j] = gelu_exact(acc[nb][2 + j] + bb);
                }
            }
            #pragma unroll
            for (int ks = 0; ks < 4; ++ks) {
                pack_pair(ge0[2*ks][0],   ge0[2*ks][1],   a3h[ks][0], a3l[ks][0]);
                pack_pair(ge1[2*ks][0],   ge1[2*ks][1],   a3h[ks][1], a3l[ks][1]);
                pack_pair(ge0[2*ks+1][0], ge0[2*ks+1][1], a3h[ks][2], a3l[ks][2]);
                pack_pair(ge1[2*ks+1][0], ge1[2*ks+1][1], a3h[ks][3], a3l[ks][3]);
            }
        }

        // ================== GEMM3: [16x64] x [64x32] ==================
        float acc3[4][4];
        #pragma unroll
        for (int nb = 0; nb < 4; ++nb)
            #pragma unroll
            for (int j = 0; j < 4; ++j) acc3[nb][j] = 0.f;
        #pragma unroll
        for (int ks = 0; ks < 4; ++ks) {
            const int kb = ks * 16 + 2 * t;
            #pragma unroll
            for (int nb = 0; nb < 4; ++nb) {
                int n = nb * 8 + g;
                uint32_t u0 = smu[B3_OFF + kb * 36 + n];
                uint32_t u1 = smu[B3_OFF + (kb + 1) * 36 + n];
                uint32_t u2 = smu[B3_OFF + (kb + 8) * 36 + n];
                uint32_t u3 = smu[B3_OFF + (kb + 9) * 36 + n];
                uint32_t bh0 = prmtx(u0, u1, 0x5410), bl0 = prmtx(u0, u1, 0x7632);
                uint32_t bh1 = prmtx(u2, u3, 0x5410), bl1 = prmtx(u2, u3, 0x7632);
                mma_bf16(acc3[nb], a3h[ks], bh0, bh1);
                mma_bf16(acc3[nb], a3l[ks], bh0, bh1);
                mma_bf16(acc3[nb], a3h[ks], bl0, bl1);
            }
        }

        // ================== epilogue 3: +b2 -> out ==================
        #pragma unroll
        for (int nb = 0; nb < 4; ++nb) {
            int col = nb * 8 + 2 * t;
            float b20 = smf[BB2_OFF + col], b21 = smf[BB2_OFF + col + 1];
            float2 v0 = make_float2(acc3[nb][0] + b20, acc3[nb][1] + b21);
            float2 v1 = make_float2(acc3[nb][2] + b20, acc3[nb][3] + b21);
            *(float2*)(out + (size_t)(rowbase + g) * 32 + col) = v0;
            *(float2*)(out + (size_t)(rowbase + g + 8) * 32 + col) = v1;
        }
        __syncwarp();
    }
}

extern "C" void kernel_launch(void* const* d_in, const int* in_sizes, int n_in,
                              void* d_out, int out_size) {
    const float* z_geo    = (const float*)d_in[0];
    const float* z_tex    = (const float*)d_in[1];
    const float* chart_w  = (const float*)d_in[2];
    const float* chart_b  = (const float*)d_in[3];
    const float* router_w = (const float*)d_in[4];
    const float* router_b = (const float*)d_in[5];
    const float* centers  = (const float*)d_in[6];
    const float* tex_w    = (const float*)d_in[7];
    const float* tex_b    = (const float*)d_in[8];
    const float* ln_g     = (const float*)d_in[9];
    const float* ln_b     = (const float*)d_in[10];
    const float* w1       = (const float*)d_in[11];
    const float* b1       = (const float*)d_in[12];
    const float* w2       = (const float*)d_in[13];
    const float* b2       = (const float*)d_in[14];
    float* out = (float*)d_out;

    const int B = in_sizes[0] / 16;
    const int smem_bytes = SMEM_WORDS * 4;
    cudaFuncSetAttribute(topo_decoder_mma,
                         cudaFuncAttributeMaxDynamicSharedMemorySize, smem_bytes);
    topo_decoder_mma<<<GRID_CTAS, NT, smem_bytes>>>(
        z_geo, z_tex, chart_w, chart_b, router_w, router_b, centers,
        tex_w, tex_b, ln_g, ln_b, w1, b1, w2, b2, out, B);
}

// round 5
// speedup vs baseline: 3.9179x; 1.6853x over previous
#include <cuda_runtime.h>
#include <cuda_bf16.h>
#include <math.h>
#include <stdint.h>

#define NT 384
#define TILE 192
#define GRID_CTAS 148
#define RP 196   // padded X row stride (TILE + 4): 2*RP % 32 == 8 -> conflict-free LDS.64

// ---- u32 word offsets in dynamic smem ----
#define XH_OFF   0          // [10 ks][4 t][RP rows] u64 (A frags hi)
#define XL_OFF   15680
#define B1H_OFF  31360      // [10 ks][64 n][4 t] u64
#define B1L_OFF  36480
#define B2H_OFF  41600      // [4][64][4] u64
#define B2L_OFF  43648
#define B3H_OFF  45696      // [4][32][4] u64
#define B3L_OFF  46720
#define LNG_OFF  47744
#define LNB_OFF  47808
#define BB1_OFF  47872
#define BB2_OFF  47936
#define CEN_OFF  47968      // [8][16]
#define RW_OFF   48096      // [8][16]
#define RB_OFF   48224      // [8]
#define CS_OFF   48232      // [8]  (1 - |c|^2)
#define SMEM_WORDS 48240    // 192960 bytes

// pack (v0 -> lo bf16, v1 -> hi bf16) + residual pair
__device__ __forceinline__ void pack_pair(float v0, float v1, uint32_t &hi, uint32_t &lo) {
    asm("cvt.rn.bf16x2.f32 %0, %1, %2;" : "=r"(hi) : "f"(v1), "f"(v0));
    float h0 = __uint_as_float(hi << 16);
    float h1 = __uint_as_float(hi & 0xffff0000u);
    asm("cvt.rn.bf16x2.f32 %0, %1, %2;" : "=r"(lo) : "f"(v1 - h1), "f"(v0 - h0));
}
__device__ __forceinline__ void mma_bf16(float* c, const uint32_t* a, uint32_t b0, uint32_t b1) {
    asm volatile(
        "mma.sync.aligned.m16n8k16.row.col.f32.bf16.bf16.f32 "
        "{%0,%1,%2,%3}, {%4,%5,%6,%7}, {%8,%9}, {%0,%1,%2,%3};"
        : "+f"(c[0]), "+f"(c[1]), "+f"(c[2]), "+f"(c[3])
        : "r"(a[0]), "r"(a[1]), "r"(a[2]), "r"(a[3]), "r"(b0), "r"(b1));
}
__device__ __forceinline__ float gelu_exact(float x) {
    return 0.5f * x * (1.0f + erff(x * 0.70710678118654752f));
}

__device__ __forceinline__ float b1val(int k, int h,
    const float* __restrict__ chart_w, const float* __restrict__ tex_w,
    const float* __restrict__ chart_b, const float* __restrict__ tex_b) {
    if (k < 128)  return chart_w[(k >> 4) * 1024 + h * 16 + (k & 15)];
    if (k < 144)  return tex_w[h * 16 + (k - 128)];
    if (k < 152)  return chart_b[(k - 144) * 64 + h];
    if (k == 152) return tex_b[h];
    return 0.0f;
}

__global__ __launch_bounds__(NT)
void topo_decoder_mma2(
    const float* __restrict__ z_geo, const float* __restrict__ z_tex,
    const float* __restrict__ chart_w, const float* __restrict__ chart_b,
    const float* __restrict__ router_w, const float* __restrict__ router_b,
    const float* __restrict__ centers,
    const float* __restrict__ tex_w, const float* __restrict__ tex_b,
    const float* __restrict__ ln_g, const float* __restrict__ ln_b,
    const float* __restrict__ w1, const float* __restrict__ b1,
    const float* __restrict__ w2, const float* __restrict__ b2,
    float* __restrict__ out, int B)
{
    extern __shared__ uint32_t smu[];
    float* smf = (float*)smu;
    unsigned long long* XH64  = (unsigned long long*)(smu + XH_OFF);
    unsigned long long* XL64  = (unsigned long long*)(smu + XL_OFF);
    const unsigned long long* B1H64 = (const unsigned long long*)(smu + B1H_OFF);
    const unsigned long long* B1L64 = (const unsigned long long*)(smu + B1L_OFF);
    const unsigned long long* B2H64 = (const unsigned long long*)(smu + B2H_OFF);
    const unsigned long long* B2L64 = (const unsigned long long*)(smu + B2L_OFF);
    const unsigned long long* B3H64 = (const unsigned long long*)(smu + B3H_OFF);
    const unsigned long long* B3L64 = (const unsigned long long*)(smu + B3L_OFF);

    const int tid = threadIdx.x;
    const int wid = tid >> 5;
    const int lane = tid & 31;
    const int g = lane >> 2;
    const int t = lane & 3;

    // ================== one-time weight packing ==================
    for (int idx = tid; idx < 5120; idx += NT) {            // B1 frags
        int sel = idx & 1, r = idx >> 1;
        int tt = r & 3, n = (r >> 2) & 63, ks = r >> 8;
        int k0 = ks * 16 + 2 * tt + 8 * sel;
        float v0 = b1val(k0, n, chart_w, tex_w, chart_b, tex_b);
        float v1 = b1val(k0 + 1, n, chart_w, tex_w, chart_b, tex_b);
        uint32_t hi, lo; pack_pair(v0, v1, hi, lo);
        int a = 2 * (ks * 256 + n * 4 + tt) + sel;
        smu[B1H_OFF + a] = hi; smu[B1L_OFF + a] = lo;
    }
    for (int idx = tid; idx < 2048; idx += NT) {            // B2 frags
        int sel = idx & 1, r = idx >> 1;
        int tt = r & 3, n = (r >> 2) & 63, ks = r >> 8;
        int k0 = ks * 16 + 2 * tt + 8 * sel;
        uint32_t hi, lo; pack_pair(w1[n * 64 + k0], w1[n * 64 + k0 + 1], hi, lo);
        int a = 2 * (ks * 256 + n * 4 + tt) + sel;
        smu[B2H_OFF + a] = hi; smu[B2L_OFF + a] = lo;
    }
    for (int idx = tid; idx < 1024; idx += NT) {            // B3 frags
        int sel = idx & 1, r = idx >> 1;
        int tt = r & 3, n = (r >> 2) & 31, ks = r >> 7;
        int k0 = ks * 16 + 2 * tt + 8 * sel;
        uint32_t hi, lo; pack_pair(w2[n * 64 + k0], w2[n * 64 + k0 + 1], hi, lo);
        int a = 2 * (ks * 128 + n * 4 + tt) + sel;
        smu[B3H_OFF + a] = hi; smu[B3L_OFF + a] = lo;
    }
    if (tid < 64) {
        smf[LNG_OFF + tid] = ln_g[tid];
        smf[LNB_OFF + tid] = ln_b[tid];
        smf[BB1_OFF + tid] = b1[tid];
    }
    if (tid < 32) smf[BB2_OFF + tid] = b2[tid];
    if (tid < 128) { smf[CEN_OFF + tid] = centers[tid]; smf[RW_OFF + tid] = router_w[tid]; }
    if (tid < 8) {
        smf[RB_OFF + tid] = router_b[tid];
        float cs = 0.f;
        for (int l = 0; l < 16; ++l) cs = fmaf(centers[tid * 16 + l], centers[tid * 16 + l], cs);
        smf[CS_OFF + tid] = 1.0f - cs;
    }
    __syncthreads();

    const int nTiles = (B + TILE - 1) / TILE;
    const int xcol = wid * 16;

    for (int tile = blockIdx.x; tile < nTiles; tile += GRID_CTAS) {
        const int rowbase = tile * TILE + xcol;

        // ================== prologue: router + X fragment staging ==================
        {
            const int rl = tid >> 1;                 // row-in-tile (this warp's own 16 rows)
            const int half = tid & 1;
            const int rawrow = tile * TILE + rl;
            const int row = rawrow < B ? rawrow : (B - 1);

            float zg[16];
            {
                const float4* p = (const float4*)(z_geo + (size_t)row * 16);
                #pragma unroll
                for (int q = 0; q < 4; ++q) {
                    float4 v = p[q];
                    zg[q*4+0]=v.x; zg[q*4+1]=v.y; zg[q*4+2]=v.z; zg[q*4+3]=v.w;
                }
            }
            float z_sq = 0.f;
            #pragma unroll
            for (int l = 0; l < 16; ++l) z_sq = fmaf(zg[l], zg[l], z_sq);
            const float one_minus = 1.0f - z_sq;
            const float inv_tau = 1.0f / fmaxf(2.0f * fmaxf(one_minus, 0.001f), 0.01f);

            float w[8], mx = -1e30f;
            #pragma unroll
            for (int c = 0; c < 8; ++c) {
                float ds = 0.f, dr = 0.f;
                #pragma unroll
                for (int l = 0; l < 16; ++l) {
                    float cv = smf[CEN_OFF + c * 16 + l];
                    float d = zg[l] - cv;
                    ds = fmaf(d, d, ds);
                    dr = fmaf(zg[l], smf[RW_OFF + c * 16 + l], dr);
                }
                float denom = one_minus * smf[CS_OFF + c];
                float tt2 = fmaxf(2.0f * ds / (denom + 0.001f), 0.001f);
                float dist = __logf(1.0f + tt2 + sqrtf(tt2 * (tt2 + 2.0f)));
                float s = (-dist + 0.1f * (dr + smf[RB_OFF + c])) * inv_tau;
                w[c] = s; mx = fmaxf(mx, s);
            }
            float ssum = 0.f;
            #pragma unroll
            for (int c = 0; c < 8; ++c) { w[c] = __expf(w[c] - mx); ssum += w[c]; }
            const float inv_sum = 1.0f / ssum;
            #pragma unroll
            for (int c = 0; c < 8; ++c) w[c] *= inv_sum;

            // stage this thread's 40 k-pairs directly in fragment layout
            const int kpb = half * 40;
            #pragma unroll
            for (int kp = 0; kp < 40; ++kp) {
                const int kpp = kpb + kp;           // compile-time within each half branchless? kpb runtime
                const int k0 = 2 * kpp;
                float v0, v1;
                if (k0 < 128)       { v0 = w[k0 >> 4] * zg[k0 & 15]; v1 = w[k0 >> 4] * zg[(k0 & 15) + 1]; }
                else if (k0 < 144)  {
                    // zt region: load pair lazily
                    float2 zt2 = *(const float2*)(z_tex + (size_t)row * 16 + (k0 - 128));
                    v0 = zt2.x; v1 = zt2.y;
                }
                else if (k0 < 152)  { v0 = w[k0 - 144]; v1 = w[k0 - 143]; }
                else if (k0 == 152) { v0 = 1.0f; v1 = 0.0f; }
                else                { v0 = 0.0f; v1 = 0.0f; }
                uint32_t hi, lo; pack_pair(v0, v1, hi, lo);
                const int ks = kpp >> 3, r = kpp & 7;
                const int tt = r & 3, sel = r >> 2;
                const int a = 2 * (ks * 4 * RP + tt * RP + rl) + sel;
                smu[XH_OFF + a] = hi; smu[XL_OFF + a] = lo;
            }

            if (half == 0 && rawrow < B) {
                float* rout = out + (size_t)B * 32 + (size_t)rawrow * 8;
                ((float4*)rout)[0] = make_float4(w[0], w[1], w[2], w[3]);
                ((float4*)rout)[1] = make_float4(w[4], w[5], w[6], w[7]);
            }
        }
        __syncwarp();

        // ================== GEMM1: [16x160] x [160x64] ==================
        float acc[8][4];
        #pragma unroll
        for (int nb = 0; nb < 8; ++nb)
            #pragma unroll
            for (int j = 0; j < 4; ++j) acc[nb][j] = 0.f;

        const int abase = t * RP + xcol + g;
        const int bbase = g * 4 + t;

        #pragma unroll
        for (int ks = 0; ks < 10; ++ks) {
            unsigned long long xh0 = XH64[ks * (4 * RP) + abase];
            unsigned long long xh1 = XH64[ks * (4 * RP) + abase + 8];
            unsigned long long xl0 = XL64[ks * (4 * RP) + abase];
            unsigned long long xl1 = XL64[ks * (4 * RP) + abase + 8];
            uint32_t ah[4] = { (uint32_t)xh0, (uint32_t)xh1, (uint32_t)(xh0 >> 32), (uint32_t)(xh1 >> 32) };
            uint32_t al[4] = { (uint32_t)xl0, (uint32_t)xl1, (uint32_t)(xl0 >> 32), (uint32_t)(xl1 >> 32) };
            #pragma unroll
            for (int nb = 0; nb < 8; ++nb) {
                unsigned long long bh = B1H64[ks * 256 + nb * 32 + bbase];
                unsigned long long bl = B1L64[ks * 256 + nb * 32 + bbase];
                mma_bf16(acc[nb], ah, (uint32_t)bh, (uint32_t)(bh >> 32));
                mma_bf16(acc[nb], al, (uint32_t)bh, (uint32_t)(bh >> 32));
                mma_bf16(acc[nb], ah, (uint32_t)bl, (uint32_t)(bl >> 32));
            }
        }

        // ================== epilogue 1: LayerNorm + GELU -> A2 frags ==================
        uint32_t a2h[4][4], a2l[4][4];
        {
            float sum0 = 0.f, sum1 = 0.f, sq0 = 0.f, sq1 = 0.f;
            #pragma unroll
            for (int nb = 0; nb < 8; ++nb) {
                sum0 += acc[nb][0] + acc[nb][1];
                sum1 += acc[nb][2] + acc[nb][3];
                sq0 = fmaf(acc[nb][0], acc[nb][0], sq0); sq0 = fmaf(acc[nb][1], acc[nb][1], sq0);
                sq1 = fmaf(acc[nb][2], acc[nb][2], sq1); sq1 = fmaf(acc[nb][3], acc[nb][3], sq1);
            }
            sum0 += __shfl_xor_sync(~0u, sum0, 1); sum0 += __shfl_xor_sync(~0u, sum0, 2);
            sum1 += __shfl_xor_sync(~0u, sum1, 1); sum1 += __shfl_xor_sync(~0u, sum1, 2);
            sq0  += __shfl_xor_sync(~0u, sq0, 1);  sq0  += __shfl_xor_sync(~0u, sq0, 2);
            sq1  += __shfl_xor_sync(~0u, sq1, 1);  sq1  += __shfl_xor_sync(~0u, sq1, 2);
            const float mu0 = sum0 * (1.0f / 64.0f), mu1 = sum1 * (1.0f / 64.0f);
            const float rstd0 = rsqrtf(fmaf(-mu0, mu0, sq0 * (1.0f / 64.0f)) + 1e-5f);
            const float rstd1 = rsqrtf(fmaf(-mu1, mu1, sq1 * (1.0f / 64.0f)) + 1e-5f);

            float ge0[8][2], ge1[8][2];
            #pragma unroll
            for (int nb = 0; nb < 8; ++nb) {
                #pragma unroll
                for (int j = 0; j < 2; ++j) {
                    int col = nb * 8 + 2 * t + j;
                    float gma = smf[LNG_OFF + col], bta = smf[LNB_OFF + col];
                    ge0[nb][j] = gelu_exact(fmaf((acc[nb][j]     - mu0) * rstd0, gma, bta));
                    ge1[nb][j] = gelu_exact(fmaf((acc[nb][2 + j] - mu1) * rstd1, gma, bta));
                }
            }
            #pragma unroll
            for (int ks = 0; ks < 4; ++ks) {
                pack_pair(ge0[2*ks][0],   ge0[2*ks][1],   a2h[ks][0], a2l[ks][0]);
                pack_pair(ge1[2*ks][0],   ge1[2*ks][1],   a2h[ks][1], a2l[ks][1]);
                pack_pair(ge0[2*ks+1][0], ge0[2*ks+1][1], a2h[ks][2], a2l[ks][2]);
                pack_pair(ge1[2*ks+1][0], ge1[2*ks+1][1], a2h[ks][3], a2l[ks][3]);
            }
        }

        // ================== GEMM2: [16x64] x [64x64] ==================
        #pragma unroll
        for (int nb = 0; nb < 8; ++nb)
            #pragma unroll
            for (int j = 0; j < 4; ++j) acc[nb][j] = 0.f;
        #pragma unroll
        for (int ks = 0; ks < 4; ++ks) {
            #pragma unroll
            for (int nb = 0; nb < 8; ++nb) {
                unsigned long long bh = B2H64[ks * 256 + nb * 32 + bbase];
                unsigned long long bl = B2L64[ks * 256 + nb * 32 + bbase];
                mma_bf16(acc[nb], a2h[ks], (uint32_t)bh, (uint32_t)(bh >> 32));
                mma_bf16(acc[nb], a2l[ks], (uint32_t)bh, (uint32_t)(bh >> 32));
                mma_bf16(acc[nb], a2h[ks], (uint32_t)bl, (uint32_t)(bl >> 32));
            }
        }

        // ================== epilogue 2: +b1, GELU -> A3 frags ==================
        uint32_t a3h[4][4], a3l[4][4];
        {
            float ge0[8][2], ge1[8][2];
            #pragma unroll
            for (int nb = 0; nb < 8; ++nb) {
                #pragma unroll
                for (int j = 0; j < 2; ++j) {
                    int col = nb * 8 + 2 * t + j;
                    float bb = smf[BB1_OFF + col];
                    ge0[nb][j] = gelu_exact(acc[nb][j] + bb);
                    ge1[nb][j] = gelu_exact(acc[nb][2 + j] + bb);
                }
            }
            #pragma unroll
            for (int ks = 0; ks < 4; ++ks) {
                pack_pair(ge0[2*ks][0],   ge0[2*ks][1],   a3h[ks][0], a3l[ks][0]);
                pack_pair(ge1[2*ks][0],   ge1[2*ks][1],   a3h[ks][1], a3l[ks][1]);
                pack_pair(ge0[2*ks+1][0], ge0[2*ks+1][1], a3h[ks][2], a3l[ks][2]);
                pack_pair(ge1[2*ks+1][0], ge1[2*ks+1][1], a3h[ks][3], a3l[ks][3]);
            }
        }

        // ================== GEMM3: [16x64] x [64x32] ==================
        float acc3[4][4];
        #pragma unroll
        for (int nb = 0; nb < 4; ++nb)
            #pragma unroll
            for (int j = 0; j < 4; ++j) acc3[nb][j] = 0.f;
        #pragma unroll
        for (int ks = 0; ks < 4; ++ks) {
            #pragma unroll
            for (int nb = 0; nb < 4; ++nb) {
                unsigned long long bh = B3H64[ks * 128 + nb * 32 + bbase];
                unsigned long long bl = B3L64[ks * 128 + nb * 32 + bbase];
                mma_bf16(acc3[nb], a3h[ks], (uint32_t)bh, (uint32_t)(bh >> 32));
                mma_bf16(acc3[nb], a3l[ks], (uint32_t)bh, (uint32_t)(bh >> 32));
                mma_bf16(acc3[nb], a3h[ks], (uint32_t)bl, (uint32_t)(bl >> 32));
            }
        }

        // ================== epilogue 3: +b2 -> out ==================
        #pragma unroll
        for (int nb = 0; nb < 4; ++nb) {
            int col = nb * 8 + 2 * t;
            float b20 = smf[BB2_OFF + col], b21 = smf[BB2_OFF + col + 1];
            if (rowbase + g < B)
                *(float2*)(out + (size_t)(rowbase + g) * 32 + col) =
                    make_float2(acc3[nb][0] + b20, acc3[nb][1] + b21);
            if (rowbase + g + 8 < B)
                *(float2*)(out + (size_t)(rowbase + g + 8) * 32 + col) =
                    make_float2(acc3[nb][2] + b20, acc3[nb][3] + b21);
        }
        __syncwarp();
    }
}

extern "C" void kernel_launch(void* const* d_in, const int* in_sizes, int n_in,
                              void* d_out, int out_size) {
    const float* z_geo    = (const float*)d_in[0];
    const float* z_tex    = (const float*)d_in[1];
    const float* chart_w  = (const float*)d_in[2];
    const float* chart_b  = (const float*)d_in[3];
    const float* router_w = (const float*)d_in[4];
    const float* router_b = (const float*)d_in[5];
    const float* centers  = (const float*)d_in[6];
    const float* tex_w    = (const float*)d_in[7];
    const float* tex_b    = (const float*)d_in[8];
    const float* ln_g     = (const float*)d_in[9];
    const float* ln_b     = (const float*)d_in[10];
    const float* w1       = (const float*)d_in[11];
    const float* b1       = (const float*)d_in[12];
    const float* w2       = (const float*)d_in[13];
    const float* b2       = (const float*)d_in[14];
    float* out = (float*)d_out;

    const int B = in_sizes[0] / 16;
    const int smem_bytes = SMEM_WORDS * 4;
    cudaFuncSetAttribute(topo_decoder_mma2,
                         cudaFuncAttributeMaxDynamicSharedMemorySize, smem_bytes);
    topo_decoder_mma2<<<GRID_CTAS, NT, smem_bytes>>>(
        z_geo, z_tex, chart_w, chart_b, router_w, router_b, centers,
        tex_w, tex_b, ln_g, ln_b, w1, b1, w2, b2, out, B);
}

// round 6
// speedup vs baseline: 4.0477x; 1.0332x over previous
#include <cuda_runtime.h>
#include <cuda_bf16.h>
#include <math.h>
#include <stdint.h>

#define NT 384
#define TILE 192
#define GRID_CTAS 148

// pack (v0 -> lo bf16, v1 -> hi bf16) + residual pair
__device__ __forceinline__ void pack_pair(float v0, float v1, uint32_t &hi, uint32_t &lo) {
    asm("cvt.rn.bf16x2.f32 %0, %1, %2;" : "=r"(hi) : "f"(v1), "f"(v0));
    float h0 = __uint_as_float(hi << 16);
    float h1 = __uint_as_float(hi & 0xffff0000u);
    asm("cvt.rn.bf16x2.f32 %0, %1, %2;" : "=r"(lo) : "f"(v1 - h1), "f"(v0 - h0));
}
__device__ __forceinline__ void mma_bf16(float* c, const uint32_t* a, uint32_t b0, uint32_t b1) {
    asm volatile(
        "mma.sync.aligned.m16n8k16.row.col.f32.bf16.bf16.f32 "
        "{%0,%1,%2,%3}, {%4,%5,%6,%7}, {%8,%9}, {%0,%1,%2,%3};"
        : "+f"(c[0]), "+f"(c[1]), "+f"(c[2]), "+f"(c[3])
        : "r"(a[0]), "r"(a[1]), "r"(a[2]), "r"(a[3]), "r"(b0), "r"(b1));
}
// branchless gelu: A&S 7.1.26 erf (|err| <= 1.5e-7), no divergent slow path
__device__ __forceinline__ float gelu_fast(float x) {
    float ax = fabsf(x);
    float y = ax * 0.70710678118654752f;
    float t = __fdividef(1.0f, fmaf(0.3275911f, y, 1.0f));
    float p = fmaf(fmaf(fmaf(fmaf(1.061405429f, t, -1.453152027f), t,
                             1.421413741f), t, -0.284496736f), t, 0.254829592f) * t;
    float e = __expf(-y * y);
    return fmaxf(x, 0.0f) - 0.5f * ax * p * e;
}
__device__ __forceinline__ float b1val(int k, int h,
    const float* __restrict__ chart_w, const float* __restrict__ tex_w,
    const float* __restrict__ chart_b, const float* __restrict__ tex_b) {
    if (k < 128)  return chart_w[(k >> 4) * 1024 + h * 16 + (k & 15)];
    if (k < 144)  return tex_w[h * 16 + (k - 128)];
    if (k < 152)  return chart_b[(k - 144) * 64 + h];
    if (k == 152) return tex_b[h];
    return 0.0f;
}

// smem (uint4 units): XI 7680 | B1I 2560 | B2I 1024 | B3I 512 | misc floats
#define XI_N   7680
#define B1I_N  2560
#define B2I_N  1024
#define B3I_N  512
#define MISC_F 512
#define SMEM_BYTES ((XI_N + B1I_N + B2I_N + B3I_N) * 16 + MISC_F * 4)
// misc float offsets
#define F_LNG 0
#define F_LNB 64
#define F_BB1 128
#define F_BB2 192
#define F_CEN 224
#define F_RW  352
#define F_RB  480
#define F_CS  488

__global__ __launch_bounds__(NT)
void topo_decoder_mma3(
    const float* __restrict__ z_geo, const float* __restrict__ z_tex,
    const float* __restrict__ chart_w, const float* __restrict__ chart_b,
    const float* __restrict__ router_w, const float* __restrict__ router_b,
    const float* __restrict__ centers,
    const float* __restrict__ tex_w, const float* __restrict__ tex_b,
    const float* __restrict__ ln_g, const float* __restrict__ ln_b,
    const float* __restrict__ w1, const float* __restrict__ b1,
    const float* __restrict__ w2, const float* __restrict__ b2,
    float* __restrict__ out, int B)
{
    extern __shared__ uint4 smq[];
    uint4* XI  = smq;
    uint4* B1I = XI + XI_N;
    uint4* B2I = B1I + B1I_N;
    uint4* B3I = B2I + B2I_N;
    float* smf = (float*)(B3I + B3I_N);

    const int tid = threadIdx.x;
    const int wid = tid >> 5;
    const int lane = tid & 31;
    const int g = lane >> 2;
    const int t = lane & 3;

    // ================== one-time weight packing (interleaved hi/lo u128) ==================
    for (int idx = tid; idx < B1I_N; idx += NT) {
        int tt = idx & 3, n = (idx >> 2) & 63, ks = idx >> 8;
        int k0 = ks * 16 + 2 * tt;
        uint4 q;
        pack_pair(b1val(k0, n, chart_w, tex_w, chart_b, tex_b),
                  b1val(k0 + 1, n, chart_w, tex_w, chart_b, tex_b), q.x, q.z);
        pack_pair(b1val(k0 + 8, n, chart_w, tex_w, chart_b, tex_b),
                  b1val(k0 + 9, n, chart_w, tex_w, chart_b, tex_b), q.y, q.w);
        B1I[idx] = q;
    }
    for (int idx = tid; idx < B2I_N; idx += NT) {
        int tt = idx & 3, n = (idx >> 2) & 63, ks = idx >> 8;
        int k0 = ks * 16 + 2 * tt;
        uint4 q;
        pack_pair(w1[n * 64 + k0],     w1[n * 64 + k0 + 1], q.x, q.z);
        pack_pair(w1[n * 64 + k0 + 8], w1[n * 64 + k0 + 9], q.y, q.w);
        B2I[idx] = q;
    }
    for (int idx = tid; idx < B3I_N; idx += NT) {
        int tt = idx & 3, n = (idx >> 2) & 31, ks = idx >> 7;
        int k0 = ks * 16 + 2 * tt;
        uint4 q;
        pack_pair(w2[n * 64 + k0],     w2[n * 64 + k0 + 1], q.x, q.z);
        pack_pair(w2[n * 64 + k0 + 8], w2[n * 64 + k0 + 9], q.y, q.w);
        B3I[idx] = q;
    }
    if (tid < 64) {
        smf[F_LNG + tid] = ln_g[tid];
        smf[F_LNB + tid] = ln_b[tid];
        smf[F_BB1 + tid] = b1[tid];
    }
    if (tid < 32) smf[F_BB2 + tid] = b2[tid];
    if (tid < 128) { smf[F_CEN + tid] = centers[tid]; smf[F_RW + tid] = router_w[tid]; }
    if (tid < 8) {
        smf[F_RB + tid] = router_b[tid];
        float cs = 0.f;
        for (int l = 0; l < 16; ++l) cs = fmaf(centers[tid * 16 + l], centers[tid * 16 + l], cs);
        smf[F_CS + tid] = 1.0f - cs;
    }
    __syncthreads();

    const int nTiles = (B + TILE - 1) / TILE;
    const int xcol = wid * 16;

    for (int tile = blockIdx.x; tile < nTiles; tile += GRID_CTAS) {
        const int rowbase = tile * TILE + xcol;

        // ================== prologue: split router + X fragment staging ==================
        {
            const int rl = tid >> 1;
            const int half = tid & 1;
            const int rawrow = tile * TILE + rl;
            const int row = rawrow < B ? rawrow : (B - 1);
            const int cb = half * 4;        // this thread's 4 charts

            float zg[16];
            {
                const float4* p = (const float4*)(z_geo + (size_t)row * 16);
                #pragma unroll
                for (int q = 0; q < 4; ++q) {
                    float4 v = p[q];
                    zg[q*4+0]=v.x; zg[q*4+1]=v.y; zg[q*4+2]=v.z; zg[q*4+3]=v.w;
                }
            }
            float z_sq = 0.f;
            #pragma unroll
            for (int l = 0; l < 16; ++l) z_sq = fmaf(zg[l], zg[l], z_sq);
            const float one_minus = 1.0f - z_sq;
            const float inv_tau = __fdividef(1.0f, fmaxf(2.0f * fmaxf(one_minus, 0.001f), 0.01f));

            float s[4];
            float mx = -1e30f;
            #pragma unroll
            for (int i = 0; i < 4; ++i) {
                const int c = cb + i;
                float ds = 0.f, dr = 0.f;
                #pragma unroll
                for (int l = 0; l < 16; ++l) {
                    float cv = smf[F_CEN + c * 16 + l];
                    float d = zg[l] - cv;
                    ds = fmaf(d, d, ds);
                    dr = fmaf(zg[l], smf[F_RW + c * 16 + l], dr);
                }
                float denom = one_minus * smf[F_CS + c];
                float tt2 = fmaxf(2.0f * __fdividef(ds, denom + 0.001f), 0.001f);
                float rad = tt2 * (tt2 + 2.0f);
                float sq = rad * rsqrtf(rad);
                float dist = __logf(1.0f + tt2 + sq);
                s[i] = (-dist + 0.1f * (dr + smf[F_RB + c])) * inv_tau;
                mx = fmaxf(mx, s[i]);
            }
            mx = fmaxf(mx, __shfl_xor_sync(~0u, mx, 1));
            float w[4], psum = 0.f;
            #pragma unroll
            for (int i = 0; i < 4; ++i) { w[i] = __expf(s[i] - mx); psum += w[i]; }
            float ssum = psum + __shfl_xor_sync(~0u, psum, 1);
            const float inv_sum = __fdividef(1.0f, ssum);
            #pragma unroll
            for (int i = 0; i < 4; ++i) w[i] *= inv_sum;
            // full router vector (peer's 4 via shfl) -- before divergence
            float w8[8];
            #pragma unroll
            for (int i = 0; i < 4; ++i) {
                w8[cb + i] = w[i];
                w8[(cb ^ 4) + i] = __shfl_xor_sync(~0u, w[i], 1);
            }

            if (half == 0) {
                // charts 0..3 (ks 0..3) + zt (ks 8)
                #pragma unroll
                for (int i = 0; i < 4; ++i) {
                    #pragma unroll
                    for (int tt = 0; tt < 4; ++tt) {
                        uint4 q;
                        pack_pair(w[i] * zg[2*tt],   w[i] * zg[2*tt+1], q.x, q.z);
                        pack_pair(w[i] * zg[2*tt+8], w[i] * zg[2*tt+9], q.y, q.w);
                        XI[(i * TILE + rl) * 4 + tt] = q;
                    }
                }
                float zt[16];
                const float4* p2 = (const float4*)(z_tex + (size_t)row * 16);
                #pragma unroll
                for (int q = 0; q < 4; ++q) {
                    float4 v = p2[q];
                    zt[q*4+0]=v.x; zt[q*4+1]=v.y; zt[q*4+2]=v.z; zt[q*4+3]=v.w;
                }
                #pragma unroll
                for (int tt = 0; tt < 4; ++tt) {
                    uint4 q;
                    pack_pair(zt[2*tt],   zt[2*tt+1], q.x, q.z);
                    pack_pair(zt[2*tt+8], zt[2*tt+9], q.y, q.w);
                    XI[(8 * TILE + rl) * 4 + tt] = q;
                }
                if (rawrow < B) {
                    float* rout = out + (size_t)B * 32 + (size_t)rawrow * 8;
                    *(float4*)rout = make_float4(w8[0], w8[1], w8[2], w8[3]);
                }
            } else {
                // charts 4..7 (ks 4..7) + [w | 1 | 0] (ks 9)
                #pragma unroll
                for (int i = 0; i < 4; ++i) {
                    #pragma unroll
                    for (int tt = 0; tt < 4; ++tt) {
                        uint4 q;
                        pack_pair(w[i] * zg[2*tt],   w[i] * zg[2*tt+1], q.x, q.z);
                        pack_pair(w[i] * zg[2*tt+8], w[i] * zg[2*tt+9], q.y, q.w);
                        XI[((4 + i) * TILE + rl) * 4 + tt] = q;
                    }
                }
                #pragma unroll
                for (int tt = 0; tt < 4; ++tt) {
                    uint4 q;
                    pack_pair(w8[2*tt], w8[2*tt+1], q.x, q.z);
                    pack_pair(tt == 0 ? 1.0f : 0.0f, 0.0f, q.y, q.w);
                    XI[(9 * TILE + rl) * 4 + tt] = q;
                }
                if (rawrow < B) {
                    float* rout = out + (size_t)B * 32 + (size_t)rawrow * 8 + 4;
                    *(float4*)rout = make_float4(w8[4], w8[5], w8[6], w8[7]);
                }
            }
        }
        __syncwarp();

        // ================== GEMM1: [16x160] x [160x64] ==================
        float acc[8][4];
        #pragma unroll
        for (int nb = 0; nb < 8; ++nb)
            #pragma unroll
            for (int j = 0; j < 4; ++j) acc[nb][j] = 0.f;

        #pragma unroll
        for (int ks = 0; ks < 10; ++ks) {
            uint4 qa = XI[(ks * TILE + xcol + g) * 4 + t];
            uint4 qb = XI[(ks * TILE + xcol + g + 8) * 4 + t];
            uint32_t ah[4] = { qa.x, qb.x, qa.y, qb.y };
            uint32_t al[4] = { qa.z, qb.z, qa.w, qb.w };
            #pragma unroll
            for (int nb = 0; nb < 8; ++nb) {
                uint4 qB = B1I[(ks * 64 + nb * 8 + g) * 4 + t];
                mma_bf16(acc[nb], ah, qB.x, qB.y);
                mma_bf16(acc[nb], al, qB.x, qB.y);
                mma_bf16(acc[nb], ah, qB.z, qB.w);
            }
        }

        // ================== epilogue 1: LayerNorm + GELU -> A2 frags ==================
        uint32_t a2h[4][4], a2l[4][4];
        {
            float sum0 = 0.f, sum1 = 0.f, sq0 = 0.f, sq1 = 0.f;
            #pragma unroll
            for (int nb = 0; nb < 8; ++nb) {
                sum0 += acc[nb][0] + acc[nb][1];
                sum1 += acc[nb][2] + acc[nb][3];
                sq0 = fmaf(acc[nb][0], acc[nb][0], sq0); sq0 = fmaf(acc[nb][1], acc[nb][1], sq0);
                sq1 = fmaf(acc[nb][2], acc[nb][2], sq1); sq1 = fmaf(acc[nb][3], acc[nb][3], sq1);
            }
            sum0 += __shfl_xor_sync(~0u, sum0, 1); sum0 += __shfl_xor_sync(~0u, sum0, 2);
            sum1 += __shfl_xor_sync(~0u, sum1, 1); sum1 += __shfl_xor_sync(~0u, sum1, 2);
            sq0  += __shfl_xor_sync(~0u, sq0, 1);  sq0  += __shfl_xor_sync(~0u, sq0, 2);
            sq1  += __shfl_xor_sync(~0u, sq1, 1);  sq1  += __shfl_xor_sync(~0u, sq1, 2);
            const float mu0 = sum0 * (1.0f / 64.0f), mu1 = sum1 * (1.0f / 64.0f);
            const float rstd0 = rsqrtf(fmaf(-mu0, mu0, sq0 * (1.0f / 64.0f)) + 1e-5f);
            const float rstd1 = rsqrtf(fmaf(-mu1, mu1, sq1 * (1.0f / 64.0f)) + 1e-5f);

            float ge0[8][2], ge1[8][2];
            #pragma unroll
            for (int nb = 0; nb < 8; ++nb) {
                #pragma unroll
                for (int j = 0; j < 2; ++j) {
                    int col = nb * 8 + 2 * t + j;
                    float gma = smf[F_LNG + col], bta = smf[F_LNB + col];
                    ge0[nb][j] = gelu_fast(fmaf((acc[nb][j]     - mu0) * rstd0, gma, bta));
                    ge1[nb][j] = gelu_fast(fmaf((acc[nb][2 + j] - mu1) * rstd1, gma, bta));
                }
            }
            #pragma unroll
            for (int ks = 0; ks < 4; ++ks) {
                pack_pair(ge0[2*ks][0],   ge0[2*ks][1],   a2h[ks][0], a2l[ks][0]);
                pack_pair(ge1[2*ks][0],   ge1[2*ks][1],   a2h[ks][1], a2l[ks][1]);
                pack_pair(ge0[2*ks+1][0], ge0[2*ks+1][1], a2h[ks][2], a2l[ks][2]);
                pack_pair(ge1[2*ks+1][0], ge1[2*ks+1][1], a2h[ks][3], a2l[ks][3]);
            }
        }

        // ================== GEMM2: [16x64] x [64x64] ==================
        #pragma unroll
        for (int nb = 0; nb < 8; ++nb)
            #pragma unroll
            for (int j = 0; j < 4; ++j) acc[nb][j] = 0.f;
        #pragma unroll
        for (int ks = 0; ks < 4; ++ks) {
            #pragma unroll
            for (int nb = 0; nb < 8; ++nb) {
                uint4 qB = B2I[(ks * 64 + nb * 8 + g) * 4 + t];
                mma_bf16(acc[nb], a2h[ks], qB.x, qB.y);
                mma_bf16(acc[nb], a2l[ks], qB.x, qB.y);
                mma_bf16(acc[nb], a2h[ks], qB.z, qB.w);
            }
        }

        // ================== epilogue 2: +b1, GELU -> A3 frags ==================
        uint32_t a3h[4][4], a3l[4][4];
        {
            float ge0[8][2], ge1[8][2];
            #pragma unroll
            for (int nb = 0; nb < 8; ++nb) {
                #pragma unroll
                for (int j = 0; j < 2; ++j) {
                    int col = nb * 8 + 2 * t + j;
                    float bb = smf[F_BB1 + col];
                    ge0[nb][j] = gelu_fast(acc[nb][j] + bb);
                    ge1[nb][j] = gelu_fast(acc[nb][2 + j] + bb);
                }
            }
            #pragma unroll
            for (int ks = 0; ks < 4; ++ks) {
                pack_pair(ge0[2*ks][0],   ge0[2*ks][1],   a3h[ks][0], a3l[ks][0]);
                pack_pair(ge1[2*ks][0],   ge1[2*ks][1],   a3h[ks][1], a3l[ks][1]);
                pack_pair(ge0[2*ks+1][0], ge0[2*ks+1][1], a3h[ks][2], a3l[ks][2]);
                pack_pair(ge1[2*ks+1][0], ge1[2*ks+1][1], a3h[ks][3], a3l[ks][3]);
            }
        }

        // ================== GEMM3: [16x64] x [64x32] ==================
        float acc3[4][4];
        #pragma unroll
        for (int nb = 0; nb < 4; ++nb)
            #pragma unroll
            for (int j = 0; j < 4; ++j) acc3[nb][j] = 0.f;
        #pragma unroll
        for (int ks = 0; ks < 4; ++ks) {
            #pragma unroll
            for (int nb = 0; nb < 4; ++nb) {
                uint4 qB = B3I[(ks * 32 + nb * 8 + g) * 4 + t];
                mma_bf16(acc3[nb], a3h[ks], qB.x, qB.y);
                mma_bf16(acc3[nb], a3l[ks], qB.x, qB.y);
                mma_bf16(acc3[nb], a3h[ks], qB.z, qB.w);
            }
        }

        // ================== epilogue 3: +b2 -> out ==================
        #pragma unroll
        for (int nb = 0; nb < 4; ++nb) {
            int col = nb * 8 + 2 * t;
            float b20 = smf[F_BB2 + col], b21 = smf[F_BB2 + col + 1];
            if (rowbase + g < B)
                *(float2*)(out + (size_t)(rowbase + g) * 32 + col) =
                    make_float2(acc3[nb][0] + b20, acc3[nb][1] + b21);
            if (rowbase + g + 8 < B)
                *(float2*)(out + (size_t)(rowbase + g + 8) * 32 + col) =
                    make_float2(acc3[nb][2] + b20, acc3[nb][3] + b21);
        }
        __syncwarp();
    }
}

extern "C" void kernel_launch(void* const* d_in, const int* in_sizes, int n_in,
                              void* d_out, int out_size) {
    const float* z_geo    = (const float*)d_in[0];
    const float* z_tex    = (const float*)d_in[1];
    const float* chart_w  = (const float*)d_in[2];
    const float* chart_b  = (const float*)d_in[3];
    const float* router_w = (const float*)d_in[4];
    const float* router_b = (const float*)d_in[5];
    const float* centers  = (const float*)d_in[6];
    const float* tex_w    = (const float*)d_in[7];
    const float* tex_b    = (const float*)d_in[8];
    const float* ln_g     = (const float*)d_in[9];
    const float* ln_b     = (const float*)d_in[10];
    const float* w1       = (const float*)d_in[11];
    const float* b1       = (const float*)d_in[12];
    const float* w2       = (const float*)d_in[13];
    const float* b2       = (const float*)d_in[14];
    float* out = (float*)d_out;

    const int B = in_sizes[0] / 16;
    cudaFuncSetAttribute(topo_decoder_mma3,
                         cudaFuncAttributeMaxDynamicSharedMemorySize, SMEM_BYTES);
    topo_decoder_mma3<<<GRID_CTAS, NT, SMEM_BYTES>>>(
        z_geo, z_tex, chart_w, chart_b, router_w, router_b, centers,
        tex_w, tex_b, ln_g, ln_b, w1, b1, w2, b2, out, B);
}

// round 7
// speedup vs baseline: 4.5159x; 1.1156x over previous
#include <cuda_runtime.h>
#include <cuda_bf16.h>
#include <math.h>
#include <stdint.h>

#define NT 512
#define TILE 256
#define GRID_CTAS 148
#define XSTRIDE 258   // uint4 row stride: pads banks so reads & writes are conflict-free

// smem (uint4 units): XI 5*4*258 | B1I 2560 | B2I 1024 | B3I 512 | misc floats
#define XI_N   (5 * 4 * XSTRIDE)
#define B1I_N  2560
#define B2I_N  1024
#define B3I_N  512
#define MISC_F 512
#define SMEM_BYTES ((XI_N + B1I_N + B2I_N + B3I_N) * 16 + MISC_F * 4)
// misc float offsets
#define F_LNG 0
#define F_LNB 64
#define F_BB1 128
#define F_BB2 192
#define F_CEN 224
#define F_RW  352
#define F_RB  480
#define F_CS  488

// pack (v0 -> lo bf16, v1 -> hi bf16) + residual pair
__device__ __forceinline__ void pack_pair(float v0, float v1, uint32_t &hi, uint32_t &lo) {
    asm("cvt.rn.bf16x2.f32 %0, %1, %2;" : "=r"(hi) : "f"(v1), "f"(v0));
    float h0 = __uint_as_float(hi << 16);
    float h1 = __uint_as_float(hi & 0xffff0000u);
    asm("cvt.rn.bf16x2.f32 %0, %1, %2;" : "=r"(lo) : "f"(v1 - h1), "f"(v0 - h0));
}
__device__ __forceinline__ void mma_bf16(float* c, const uint32_t* a, uint32_t b0, uint32_t b1) {
    asm volatile(
        "mma.sync.aligned.m16n8k16.row.col.f32.bf16.bf16.f32 "
        "{%0,%1,%2,%3}, {%4,%5,%6,%7}, {%8,%9}, {%0,%1,%2,%3};"
        : "+f"(c[0]), "+f"(c[1]), "+f"(c[2]), "+f"(c[3])
        : "r"(a[0]), "r"(a[1]), "r"(a[2]), "r"(a[3]), "r"(b0), "r"(b1));
}
// branchless gelu: A&S 7.1.26 erf (|err| <= 1.5e-7)
__device__ __forceinline__ float gelu_fast(float x) {
    float ax = fabsf(x);
    float y = ax * 0.70710678118654752f;
    float t = __fdividef(1.0f, fmaf(0.3275911f, y, 1.0f));
    float p = fmaf(fmaf(fmaf(fmaf(1.061405429f, t, -1.453152027f), t,
                             1.421413741f), t, -0.284496736f), t, 0.254829592f) * t;
    float e = __expf(-y * y);
    return fmaxf(x, 0.0f) - 0.5f * ax * p * e;
}
__device__ __forceinline__ float b1val(int k, int h,
    const float* __restrict__ chart_w, const float* __restrict__ tex_w,
    const float* __restrict__ chart_b, const float* __restrict__ tex_b) {
    if (k < 128)  return chart_w[(k >> 4) * 1024 + h * 16 + (k & 15)];
    if (k < 144)  return tex_w[h * 16 + (k - 128)];
    if (k < 152)  return chart_b[(k - 144) * 64 + h];
    if (k == 152) return tex_b[h];
    return 0.0f;
}

__global__ __launch_bounds__(NT)
void topo_decoder_mma4(
    const float* __restrict__ z_geo, const float* __restrict__ z_tex,
    const float* __restrict__ chart_w, const float* __restrict__ chart_b,
    const float* __restrict__ router_w, const float* __restrict__ router_b,
    const float* __restrict__ centers,
    const float* __restrict__ tex_w, const float* __restrict__ tex_b,
    const float* __restrict__ ln_g, const float* __restrict__ ln_b,
    const float* __restrict__ w1, const float* __restrict__ b1,
    const float* __restrict__ w2, const float* __restrict__ b2,
    float* __restrict__ out, int B)
{
    extern __shared__ uint4 smq[];
    uint4* XI  = smq;
    uint4* B1I = XI + XI_N;
    uint4* B2I = B1I + B1I_N;
    uint4* B3I = B2I + B2I_N;
    float* smf = (float*)(B3I + B3I_N);

    const int tid = threadIdx.x;
    const int wid = tid >> 5;
    const int lane = tid & 31;
    const int g = lane >> 2;
    const int t = lane & 3;

    // ================== one-time weight packing ==================
    for (int idx = tid; idx < B1I_N; idx += NT) {
        int tt = idx & 3, n = (idx >> 2) & 63, ks = idx >> 8;
        int k0 = ks * 16 + 2 * tt;
        uint4 q;
        pack_pair(b1val(k0, n, chart_w, tex_w, chart_b, tex_b),
                  b1val(k0 + 1, n, chart_w, tex_w, chart_b, tex_b), q.x, q.z);
        pack_pair(b1val(k0 + 8, n, chart_w, tex_w, chart_b, tex_b),
                  b1val(k0 + 9, n, chart_w, tex_w, chart_b, tex_b), q.y, q.w);
        B1I[idx] = q;
    }
    for (int idx = tid; idx < B2I_N; idx += NT) {
        int tt = idx & 3, n = (idx >> 2) & 63, ks = idx >> 8;
        int k0 = ks * 16 + 2 * tt;
        uint4 q;
        pack_pair(w1[n * 64 + k0],     w1[n * 64 + k0 + 1], q.x, q.z);
        pack_pair(w1[n * 64 + k0 + 8], w1[n * 64 + k0 + 9], q.y, q.w);
        B2I[idx] = q;
    }
    for (int idx = tid; idx < B3I_N; idx += NT) {
        int tt = idx & 3, n = (idx >> 2) & 31, ks = idx >> 7;
        int k0 = ks * 16 + 2 * tt;
        uint4 q;
        pack_pair(w2[n * 64 + k0],     w2[n * 64 + k0 + 1], q.x, q.z);
        pack_pair(w2[n * 64 + k0 + 8], w2[n * 64 + k0 + 9], q.y, q.w);
        B3I[idx] = q;
    }
    if (tid < 64) {
        smf[F_LNG + tid] = ln_g[tid];
        smf[F_LNB + tid] = ln_b[tid];
        smf[F_BB1 + tid] = b1[tid];
    }
    if (tid < 32) smf[F_BB2 + tid] = b2[tid];
    if (tid < 128) { smf[F_CEN + tid] = centers[tid]; smf[F_RW + tid] = router_w[tid]; }
    if (tid < 8) {
        smf[F_RB + tid] = router_b[tid];
        float cs = 0.f;
        for (int l = 0; l < 16; ++l) cs = fmaf(centers[tid * 16 + l], centers[tid * 16 + l], cs);
        smf[F_CS + tid] = 1.0f - cs;
    }
    __syncthreads();

    const int nTiles = (B + TILE - 1) / TILE;
    const int xcol = wid * 16;
    const int rl = tid >> 1;          // staging row-in-tile
    const int half = tid & 1;

    for (int tile = blockIdx.x; tile < nTiles; tile += GRID_CTAS) {
        const int rowbase = tile * TILE + xcol;
        const int rawrow = tile * TILE + rl;
        const int srow = rawrow < B ? rawrow : (B - 1);

        // ================== prologue: split router ==================
        float zg[16], w8[8];
        {
            const float4* p = (const float4*)(z_geo + (size_t)srow * 16);
            #pragma unroll
            for (int q = 0; q < 4; ++q) {
                float4 v = p[q];
                zg[q*4+0]=v.x; zg[q*4+1]=v.y; zg[q*4+2]=v.z; zg[q*4+3]=v.w;
            }
            float z_sq = 0.f;
            #pragma unroll
            for (int l = 0; l < 16; ++l) z_sq = fmaf(zg[l], zg[l], z_sq);
            const float one_minus = 1.0f - z_sq;
            const float inv_tau = __fdividef(1.0f, fmaxf(2.0f * fmaxf(one_minus, 0.001f), 0.01f));

            const int cb = half * 4;
            float s[4], mx = -1e30f;
            #pragma unroll
            for (int i = 0; i < 4; ++i) {
                const int c = cb + i;
                float ds = 0.f, dr = 0.f;
                #pragma unroll
                for (int l = 0; l < 16; ++l) {
                    float cv = smf[F_CEN + c * 16 + l];
                    float d = zg[l] - cv;
                    ds = fmaf(d, d, ds);
                    dr = fmaf(zg[l], smf[F_RW + c * 16 + l], dr);
                }
                float denom = one_minus * smf[F_CS + c];
                float tt2 = fmaxf(2.0f * __fdividef(ds, denom + 0.001f), 0.001f);
                float rad = tt2 * (tt2 + 2.0f);
                float sq = rad * rsqrtf(rad);
                float dist = __logf(1.0f + tt2 + sq);
                s[i] = (-dist + 0.1f * (dr + smf[F_RB + c])) * inv_tau;
                mx = fmaxf(mx, s[i]);
            }
            mx = fmaxf(mx, __shfl_xor_sync(~0u, mx, 1));
            float wloc[4], psum = 0.f;
            #pragma unroll
            for (int i = 0; i < 4; ++i) { wloc[i] = __expf(s[i] - mx); psum += wloc[i]; }
            float ssum = psum + __shfl_xor_sync(~0u, psum, 1);
            const float inv_sum = __fdividef(1.0f, ssum);
            #pragma unroll
            for (int i = 0; i < 4; ++i) {
                float wi = wloc[i] * inv_sum;
                w8[cb + i] = wi;
                w8[(cb ^ 4) + i] = __shfl_xor_sync(~0u, wi, 1);
            }
            if (rawrow < B) {
                float* rout = out + (size_t)B * 32 + (size_t)rawrow * 8 + cb;
                *(float4*)rout = make_float4(w8[cb], w8[cb+1], w8[cb+2], w8[cb+3]);
            }
        }

        // staging helper for chart k-steps (ks<8): X = w8[ks]*zg
        #define STAGE_CHART(KS, SLOT) do {                                        \
            float wc = w8[KS];                                                    \
            _Pragma("unroll")                                                     \
            for (int tt = 0; tt < 4; ++tt) {                                      \
                uint4 q;                                                          \
                pack_pair(wc * zg[2*tt],   wc * zg[2*tt+1], q.x, q.z);            \
                pack_pair(wc * zg[2*tt+8], wc * zg[2*tt+9], q.y, q.w);            \
                XI[((SLOT) * 4 + tt) * XSTRIDE + rl] = q;                         \
            }                                                                     \
        } while (0)

        // ================== GEMM1 (phase-split over ks) ==================
        float acc[8][4];
        #pragma unroll
        for (int nb = 0; nb < 8; ++nb)
            #pragma unroll
            for (int j = 0; j < 4; ++j) acc[nb][j] = 0.f;

        // ---- phase 0: ks 0..4 ----
        if (half == 0) { STAGE_CHART(0, 0); STAGE_CHART(2, 2); STAGE_CHART(4, 4); }
        else           { STAGE_CHART(1, 1); STAGE_CHART(3, 3); }
        __syncwarp();
        #pragma unroll
        for (int ks = 0; ks < 5; ++ks) {
            uint4 qa = XI[(ks * 4 + t) * XSTRIDE + xcol + g];
            uint4 qb = XI[(ks * 4 + t) * XSTRIDE + xcol + g + 8];
            uint32_t ah[4] = { qa.x, qb.x, qa.y, qb.y };
            uint32_t al[4] = { qa.z, qb.z, qa.w, qb.w };
            #pragma unroll
            for (int nb = 0; nb < 8; ++nb) {
                uint4 qB = B1I[(ks * 64 + nb * 8 + g) * 4 + t];
                mma_bf16(acc[nb], ah, qB.x, qB.y);
                mma_bf16(acc[nb], al, qB.x, qB.y);
                mma_bf16(acc[nb], ah, qB.z, qB.w);
            }
        }
        __syncwarp();

        // ---- phase 1: ks 5..9 (slots 0..4) ----
        if (half == 0) {
            STAGE_CHART(6, 1);
            { // ks 8 : zt
                float zt[16];
                const float4* p2 = (const float4*)(z_tex + (size_t)srow * 16);
                #pragma unroll
                for (int q = 0; q < 4; ++q) {
                    float4 v = p2[q];
                    zt[q*4+0]=v.x; zt[q*4+1]=v.y; zt[q*4+2]=v.z; zt[q*4+3]=v.w;
                }
                #pragma unroll
                for (int tt = 0; tt < 4; ++tt) {
                    uint4 q;
                    pack_pair(zt[2*tt],   zt[2*tt+1], q.x, q.z);
                    pack_pair(zt[2*tt+8], zt[2*tt+9], q.y, q.w);
                    XI[(3 * 4 + tt) * XSTRIDE + rl] = q;
                }
            }
        } else {
            STAGE_CHART(5, 0); STAGE_CHART(7, 2);
            { // ks 9 : [w8 | 1 | 0pad]
                #pragma unroll
                for (int tt = 0; tt < 4; ++tt) {
                    uint4 q;
                    pack_pair(w8[2*tt], w8[2*tt+1], q.x, q.z);
                    pack_pair(tt == 0 ? 1.0f : 0.0f, 0.0f, q.y, q.w);
                    XI[(4 * 4 + tt) * XSTRIDE + rl] = q;
                }
            }
        }
        __syncwarp();
        #pragma unroll
        for (int ks = 0; ks < 5; ++ks) {
            uint4 qa = XI[(ks * 4 + t) * XSTRIDE + xcol + g];
            uint4 qb = XI[(ks * 4 + t) * XSTRIDE + xcol + g + 8];
            uint32_t ah[4] = { qa.x, qb.x, qa.y, qb.y };
            uint32_t al[4] = { qa.z, qb.z, qa.w, qb.w };
            #pragma unroll
            for (int nb = 0; nb < 8; ++nb) {
                uint4 qB = B1I[((ks + 5) * 64 + nb * 8 + g) * 4 + t];
                mma_bf16(acc[nb], ah, qB.x, qB.y);
                mma_bf16(acc[nb], al, qB.x, qB.y);
                mma_bf16(acc[nb], ah, qB.z, qB.w);
            }
        }
        __syncwarp();

        // ================== epilogue 1: LayerNorm + GELU -> A2 frags ==================
        uint32_t a2h[4][4], a2l[4][4];
        {
            float sum0 = 0.f, sum1 = 0.f, sq0 = 0.f, sq1 = 0.f;
            #pragma unroll
            for (int nb = 0; nb < 8; ++nb) {
                sum0 += acc[nb][0] + acc[nb][1];
                sum1 += acc[nb][2] + acc[nb][3];
                sq0 = fmaf(acc[nb][0], acc[nb][0], sq0); sq0 = fmaf(acc[nb][1], acc[nb][1], sq0);
                sq1 = fmaf(acc[nb][2], acc[nb][2], sq1); sq1 = fmaf(acc[nb][3], acc[nb][3], sq1);
            }
            sum0 += __shfl_xor_sync(~0u, sum0, 1); sum0 += __shfl_xor_sync(~0u, sum0, 2);
            sum1 += __shfl_xor_sync(~0u, sum1, 1); sum1 += __shfl_xor_sync(~0u, sum1, 2);
            sq0  += __shfl_xor_sync(~0u, sq0, 1);  sq0  += __shfl_xor_sync(~0u, sq0, 2);
            sq1  += __shfl_xor_sync(~0u, sq1, 1);  sq1  += __shfl_xor_sync(~0u, sq1, 2);
            const float mu0 = sum0 * (1.0f / 64.0f), mu1 = sum1 * (1.0f / 64.0f);
            const float rstd0 = rsqrtf(fmaf(-mu0, mu0, sq0 * (1.0f / 64.0f)) + 1e-5f);
            const float rstd1 = rsqrtf(fmaf(-mu1, mu1, sq1 * (1.0f / 64.0f)) + 1e-5f);

            #pragma unroll
            for (int ks = 0; ks < 4; ++ks) {
                float v00, v01, v10, v11, v20, v21, v30, v31;
                {
                    int nb = 2 * ks;
                    int col = nb * 8 + 2 * t;
                    float g0 = smf[F_LNG + col], g1 = smf[F_LNG + col + 1];
                    float e0 = smf[F_LNB + col], e1 = smf[F_LNB + col + 1];
                    v00 = gelu_fast(fmaf((acc[nb][0] - mu0) * rstd0, g0, e0));
                    v01 = gelu_fast(fmaf((acc[nb][1] - mu0) * rstd0, g1, e1));
                    v10 = gelu_fast(fmaf((acc[nb][2] - mu1) * rstd1, g0, e0));
                    v11 = gelu_fast(fmaf((acc[nb][3] - mu1) * rstd1, g1, e1));
                }
                {
                    int nb = 2 * ks + 1;
                    int col = nb * 8 + 2 * t;
                    float g0 = smf[F_LNG + col], g1 = smf[F_LNG + col + 1];
                    float e0 = smf[F_LNB + col], e1 = smf[F_LNB + col + 1];
                    v20 = gelu_fast(fmaf((acc[nb][0] - mu0) * rstd0, g0, e0));
                    v21 = gelu_fast(fmaf((acc[nb][1] - mu0) * rstd0, g1, e1));
                    v30 = gelu_fast(fmaf((acc[nb][2] - mu1) * rstd1, g0, e0));
                    v31 = gelu_fast(fmaf((acc[nb][3] - mu1) * rstd1, g1, e1));
                }
                pack_pair(v00, v01, a2h[ks][0], a2l[ks][0]);
                pack_pair(v10, v11, a2h[ks][1], a2l[ks][1]);
                pack_pair(v20, v21, a2h[ks][2], a2l[ks][2]);
                pack_pair(v30, v31, a2h[ks][3], a2l[ks][3]);
            }
        }

        // ================== GEMM2: [16x64] x [64x64] ==================
        #pragma unroll
        for (int nb = 0; nb < 8; ++nb)
            #pragma unroll
            for (int j = 0; j < 4; ++j) acc[nb][j] = 0.f;
        #pragma unroll
        for (int ks = 0; ks < 4; ++ks) {
            #pragma unroll
            for (int nb = 0; nb < 8; ++nb) {
                uint4 qB = B2I[(ks * 64 + nb * 8 + g) * 4 + t];
                mma_bf16(acc[nb], a2h[ks], qB.x, qB.y);
                mma_bf16(acc[nb], a2l[ks], qB.x, qB.y);
                mma_bf16(acc[nb], a2h[ks], qB.z, qB.w);
            }
        }

        // ================== epilogue 2: +b1, GELU -> A3 frags ==================
        uint32_t a3h[4][4], a3l[4][4];
        #pragma unroll
        for (int ks = 0; ks < 4; ++ks) {
            float v00, v01, v10, v11, v20, v21, v30, v31;
            {
                int nb = 2 * ks;
                int col = nb * 8 + 2 * t;
                float b0 = smf[F_BB1 + col], bb1v = smf[F_BB1 + col + 1];
                v00 = gelu_fast(acc[nb][0] + b0);
                v01 = gelu_fast(acc[nb][1] + bb1v);
                v10 = gelu_fast(acc[nb][2] + b0);
                v11 = gelu_fast(acc[nb][3] + bb1v);
            }
            {
                int nb = 2 * ks + 1;
                int col = nb * 8 + 2 * t;
                float b0 = smf[F_BB1 + col], bb1v = smf[F_BB1 + col + 1];
                v20 = gelu_fast(acc[nb][0] + b0);
                v21 = gelu_fast(acc[nb][1] + bb1v);
                v30 = gelu_fast(acc[nb][2] + b0);
                v31 = gelu_fast(acc[nb][3] + bb1v);
            }
            pack_pair(v00, v01, a3h[ks][0], a3l[ks][0]);
            pack_pair(v10, v11, a3h[ks][1], a3l[ks][1]);
            pack_pair(v20, v21, a3h[ks][2], a3l[ks][2]);
            pack_pair(v30, v31, a3h[ks][3], a3l[ks][3]);
        }

        // ================== GEMM3: [16x64] x [64x32] ==================
        float acc3[4][4];
        #pragma unroll
        for (int nb = 0; nb < 4; ++nb)
            #pragma unroll
            for (int j = 0; j < 4; ++j) acc3[nb][j] = 0.f;
        #pragma unroll
        for (int ks = 0; ks < 4; ++ks) {
            #pragma unroll
            for (int nb = 0; nb < 4; ++nb) {
                uint4 qB = B3I[(ks * 32 + nb * 8 + g) * 4 + t];
                mma_bf16(acc3[nb], a3h[ks], qB.x, qB.y);
                mma_bf16(acc3[nb], a3l[ks], qB.x, qB.y);
                mma_bf16(acc3[nb], a3h[ks], qB.z, qB.w);
            }
        }

        // ================== epilogue 3: +b2 -> out ==================
        #pragma unroll
        for (int nb = 0; nb < 4; ++nb) {
            int col = nb * 8 + 2 * t;
            float b20 = smf[F_BB2 + col], b21 = smf[F_BB2 + col + 1];
            if (rowbase + g < B)
                *(float2*)(out + (size_t)(rowbase + g) * 32 + col) =
                    make_float2(acc3[nb][0] + b20, acc3[nb][1] + b21);
            if (rowbase + g + 8 < B)
                *(float2*)(out + (size_t)(rowbase + g + 8) * 32 + col) =
                    make_float2(acc3[nb][2] + b20, acc3[nb][3] + b21);
        }
        __syncwarp();
    }
}

extern "C" void kernel_launch(void* const* d_in, const int* in_sizes, int n_in,
                              void* d_out, int out_size) {
    const float* z_geo    = (const float*)d_in[0];
    const float* z_tex    = (const float*)d_in[1];
    const float* chart_w  = (const float*)d_in[2];
    const float* chart_b  = (const float*)d_in[3];
    const float* router_w = (const float*)d_in[4];
    const float* router_b = (const float*)d_in[5];
    const float* centers  = (const float*)d_in[6];
    const float* tex_w    = (const float*)d_in[7];
    const float* tex_b    = (const float*)d_in[8];
    const float* ln_g     = (const float*)d_in[9];
    const float* ln_b     = (const float*)d_in[10];
    const float* w1       = (const float*)d_in[11];
    const float* b1       = (const float*)d_in[12];
    const float* w2       = (const float*)d_in[13];
    const float* b2       = (const float*)d_in[14];
    float* out = (float*)d_out;

    const int B = in_sizes[0] / 16;
    cudaFuncSetAttribute(topo_decoder_mma4,
                         cudaFuncAttributeMaxDynamicSharedMemorySize, SMEM_BYTES);
    topo_decoder_mma4<<<GRID_CTAS, NT, SMEM_BYTES>>>(
        z_geo, z_tex, chart_w, chart_b, router_w, router_b, centers,
        tex_w, tex_b, ln_g, ln_b, w1, b1, w2, b2, out, B);
}

// round 9
// speedup vs baseline: 4.6467x; 1.0290x over previous
#include <cuda_runtime.h>
#include <cuda_bf16.h>
#include <math.h>
#include <stdint.h>

#define NT 640
#define TILE 320
#define GRID_CTAS 148
#define XSTRIDE 322   // uint4 row stride (TILE+2): conflict-free for both STS.128 and LDS.128

// smem (uint4 units): XI 2*4*322 | B1I 2560 | B2I 1024 | B3I 512 | misc floats
#define XI_N   (2 * 4 * XSTRIDE)
#define B1I_N  2560
#define B2I_N  1024
#define B3I_N  512
#define MISC_F 512
#define SMEM_BYTES ((XI_N + B1I_N + B2I_N + B3I_N) * 16 + MISC_F * 4)
// misc float offsets
#define F_LNG 0
#define F_LNB 64
#define F_BB1 128
#define F_BB2 192
#define F_CEN 224
#define F_RW  352
#define F_RB  480
#define F_CS  488

// pack (v0 -> lo bf16, v1 -> hi bf16) + residual pair
__device__ __forceinline__ void pack_pair(float v0, float v1, uint32_t &hi, uint32_t &lo) {
    asm("cvt.rn.bf16x2.f32 %0, %1, %2;" : "=r"(hi) : "f"(v1), "f"(v0));
    float h0 = __uint_as_float(hi << 16);
    float h1 = __uint_as_float(hi & 0xffff0000u);
    asm("cvt.rn.bf16x2.f32 %0, %1, %2;" : "=r"(lo) : "f"(v1 - h1), "f"(v0 - h0));
}
__device__ __forceinline__ void mma_bf16(float* c, const uint32_t* a, uint32_t b0, uint32_t b1) {
    asm volatile(
        "mma.sync.aligned.m16n8k16.row.col.f32.bf16.bf16.f32 "
        "{%0,%1,%2,%3}, {%4,%5,%6,%7}, {%8,%9}, {%0,%1,%2,%3};"
        : "+f"(c[0]), "+f"(c[1]), "+f"(c[2]), "+f"(c[3])
        : "r"(a[0]), "r"(a[1]), "r"(a[2]), "r"(a[3]), "r"(b0), "r"(b1));
}
// branchless gelu: A&S 7.1.26 erf (|err| <= 1.5e-7)
__device__ __forceinline__ float gelu_fast(float x) {
    float ax = fabsf(x);
    float y = ax * 0.70710678118654752f;
    float t = __fdividef(1.0f, fmaf(0.3275911f, y, 1.0f));
    float p = fmaf(fmaf(fmaf(fmaf(1.061405429f, t, -1.453152027f), t,
                             1.421413741f), t, -0.284496736f), t, 0.254829592f) * t;
    float e = __expf(-y * y);
    return fmaxf(x, 0.0f) - 0.5f * ax * p * e;
}
__device__ __forceinline__ float b1val(int k, int h,
    const float* __restrict__ chart_w, const float* __restrict__ tex_w,
    const float* __restrict__ chart_b, const float* __restrict__ tex_b) {
    if (k < 128)  return chart_w[(k >> 4) * 1024 + h * 16 + (k & 15)];
    if (k < 144)  return tex_w[h * 16 + (k - 128)];
    if (k < 152)  return chart_b[(k - 144) * 64 + h];
    if (k == 152) return tex_b[h];
    return 0.0f;
}

__global__ __launch_bounds__(NT)
void topo_decoder_mma6(
    const float* __restrict__ z_geo, const float* __restrict__ z_tex,
    const float* __restrict__ chart_w, const float* __restrict__ chart_b,
    const float* __restrict__ router_w, const float* __restrict__ router_b,
    const float* __restrict__ centers,
    const float* __restrict__ tex_w, const float* __restrict__ tex_b,
    const float* __restrict__ ln_g, const float* __restrict__ ln_b,
    const float* __restrict__ w1, const float* __restrict__ b1,
    const float* __restrict__ w2, const float* __restrict__ b2,
    float* __restrict__ out, int B)
{
    extern __shared__ uint4 smq[];
    uint4* XI  = smq;
    uint4* B1I = XI + XI_N;
    uint4* B2I = B1I + B1I_N;
    uint4* B3I = B2I + B2I_N;
    float* smf = (float*)(B3I + B3I_N);

    const int tid = threadIdx.x;
    const int wid = tid >> 5;
    const int lane = tid & 31;
    const int g = lane >> 2;
    const int t = lane & 3;

    // ================== one-time weight packing ==================
    for (int idx = tid; idx < B1I_N; idx += NT) {
        int tt = idx & 3, n = (idx >> 2) & 63, ks = idx >> 8;
        int k0 = ks * 16 + 2 * tt;
        uint4 q;
        pack_pair(b1val(k0, n, chart_w, tex_w, chart_b, tex_b),
                  b1val(k0 + 1, n, chart_w, tex_w, chart_b, tex_b), q.x, q.z);
        pack_pair(b1val(k0 + 8, n, chart_w, tex_w, chart_b, tex_b),
                  b1val(k0 + 9, n, chart_w, tex_w, chart_b, tex_b), q.y, q.w);
        B1I[idx] = q;
    }
    for (int idx = tid; idx < B2I_N; idx += NT) {
        int tt = idx & 3, n = (idx >> 2) & 63, ks = idx >> 8;
        int k0 = ks * 16 + 2 * tt;
        uint4 q;
        pack_pair(w1[n * 64 + k0],     w1[n * 64 + k0 + 1], q.x, q.z);
        pack_pair(w1[n * 64 + k0 + 8], w1[n * 64 + k0 + 9], q.y, q.w);
        B2I[idx] = q;
    }
    for (int idx = tid; idx < B3I_N; idx += NT) {
        int tt = idx & 3, n = (idx >> 2) & 31, ks = idx >> 7;
        int k0 = ks * 16 + 2 * tt;
        uint4 q;
        pack_pair(w2[n * 64 + k0],     w2[n * 64 + k0 + 1], q.x, q.z);
        pack_pair(w2[n * 64 + k0 + 8], w2[n * 64 + k0 + 9], q.y, q.w);
        B3I[idx] = q;
    }
    if (tid < 64) {
        smf[F_LNG + tid] = ln_g[tid];
        smf[F_LNB + tid] = ln_b[tid];
        smf[F_BB1 + tid] = b1[tid];
    }
    if (tid < 32) smf[F_BB2 + tid] = b2[tid];
    if (tid < 128) { smf[F_CEN + tid] = centers[tid]; smf[F_RW + tid] = router_w[tid]; }
    if (tid < 8) {
        smf[F_RB + tid] = router_b[tid];
        float cs = 0.f;
        for (int l = 0; l < 16; ++l) cs = fmaf(centers[tid * 16 + l], centers[tid * 16 + l], cs);
        smf[F_CS + tid] = 1.0f - cs;
    }
    __syncthreads();

    const int nTiles = (B + TILE - 1) / TILE;
    const int xcol = wid * 16;
    const int rl = tid >> 1;          // staging row-in-tile
    const int half = tid & 1;

    for (int tile = blockIdx.x; tile < nTiles; tile += GRID_CTAS) {
        const int rowbase = tile * TILE + xcol;
        const int rawrow = tile * TILE + rl;
        const int srow = rawrow < B ? rawrow : (B - 1);

        // ================== prologue: split router ==================
        float zg[16], w8[8];
        {
            const float4* p = (const float4*)(z_geo + (size_t)srow * 16);
            #pragma unroll
            for (int q = 0; q < 4; ++q) {
                float4 v = p[q];
                zg[q*4+0]=v.x; zg[q*4+1]=v.y; zg[q*4+2]=v.z; zg[q*4+3]=v.w;
            }
            float z_sq = 0.f;
            #pragma unroll
            for (int l = 0; l < 16; ++l) z_sq = fmaf(zg[l], zg[l], z_sq);
            const float one_minus = 1.0f - z_sq;
            const float inv_tau = __fdividef(1.0f, fmaxf(2.0f * fmaxf(one_minus, 0.001f), 0.01f));

            const int cb = half * 4;
            float s[4], mx = -1e30f;
            #pragma unroll
            for (int i = 0; i < 4; ++i) {
                const int c = cb + i;
                float ds = 0.f, dr = 0.f;
                #pragma unroll
                for (int l = 0; l < 16; ++l) {
                    float cv = smf[F_CEN + c * 16 + l];
                    float d = zg[l] - cv;
                    ds = fmaf(d, d, ds);
                    dr = fmaf(zg[l], smf[F_RW + c * 16 + l], dr);
                }
                float denom = one_minus * smf[F_CS + c];
                float tt2 = fmaxf(2.0f * __fdividef(ds, denom + 0.001f), 0.001f);
                float rad = tt2 * (tt2 + 2.0f);
                float sq = rad * rsqrtf(rad);
                float dist = __logf(1.0f + tt2 + sq);
                s[i] = (-dist + 0.1f * (dr + smf[F_RB + c])) * inv_tau;
                mx = fmaxf(mx, s[i]);
            }
            mx = fmaxf(mx, __shfl_xor_sync(~0u, mx, 1));
            float wloc[4], psum = 0.f;
            #pragma unroll
            for (int i = 0; i < 4; ++i) { wloc[i] = __expf(s[i] - mx); psum += wloc[i]; }
            float ssum = psum + __shfl_xor_sync(~0u, psum, 1);
            const float inv_sum = __fdividef(1.0f, ssum);
            #pragma unroll
            for (int i = 0; i < 4; ++i) {
                float wi = wloc[i] * inv_sum;
                w8[cb + i] = wi;
                w8[(cb ^ 4) + i] = __shfl_xor_sync(~0u, wi, 1);
            }
            if (rawrow < B) {
                float* rout = out + (size_t)B * 32 + (size_t)rawrow * 8 + cb;
                *(float4*)rout = make_float4(w8[cb], w8[cb+1], w8[cb+2], w8[cb+3]);
            }
        }
        // prefetch zt slice this thread stages (ks 8)
        float4 ztA = *(const float4*)(z_tex + (size_t)srow * 16 + 4 * half);
        float4 ztB = *(const float4*)(z_tex + (size_t)srow * 16 + 4 * half + 8);
        // ks9 staging operands (avoid dynamic w8 indexing)
        const float wa0 = half ? w8[4] : w8[0];
        const float wa1 = half ? w8[5] : w8[1];
        const float wb0 = half ? w8[6] : w8[2];
        const float wb1 = half ? w8[7] : w8[3];

        // ================== GEMM1: 2-slot ring over ks ==================
        float acc[8][4];
        #pragma unroll
        for (int nb = 0; nb < 8; ++nb)
            #pragma unroll
            for (int j = 0; j < 4; ++j) acc[nb][j] = 0.f;

        #pragma unroll
        for (int p = 0; p < 10; ++p) {
            const int slot = p & 1;
            // ---- stage ks p (each thread: tt = 2*half, 2*half+1) ----
            if (p < 8) {
                const float wc = w8[p];
                #pragma unroll
                for (int j = 0; j < 2; ++j) {
                    const int tt = 2 * half + j;
                    uint4 q;
                    pack_pair(wc * zg[2*tt],   wc * zg[2*tt+1], q.x, q.z);
                    pack_pair(wc * zg[2*tt+8], wc * zg[2*tt+9], q.y, q.w);
                    XI[(slot * 4 + tt) * XSTRIDE + rl] = q;
                }
            } else if (p == 8) {
                {
                    uint4 q;
                    pack_pair(ztA.x, ztA.y, q.x, q.z);
                    pack_pair(ztB.x, ztB.y, q.y, q.w);
                    XI[(slot * 4 + 2 * half) * XSTRIDE + rl] = q;
                }
                {
                    uint4 q;
                    pack_pair(ztA.z, ztA.w, q.x, q.z);
                    pack_pair(ztB.z, ztB.w, q.y, q.w);
                    XI[(slot * 4 + 2 * half + 1) * XSTRIDE + rl] = q;
                }
            } else {
                {
                    uint4 q;
                    pack_pair(wa0, wa1, q.x, q.z);
                    pack_pair(half ? 0.0f : 1.0f, 0.0f, q.y, q.w);
                    XI[(slot * 4 + 2 * half) * XSTRIDE + rl] = q;
                }
                {
                    uint4 q;
                    pack_pair(wb0, wb1, q.x, q.z);
                    pack_pair(0.0f, 0.0f, q.y, q.w);
                    XI[(slot * 4 + 2 * half + 1) * XSTRIDE + rl] = q;
                }
            }
            __syncwarp();
            // ---- MMA ks p ----
            uint4 qa = XI[(slot * 4 + t) * XSTRIDE + xcol + g];
            uint4 qb = XI[(slot * 4 + t) * XSTRIDE + xcol + g + 8];
            uint32_t ah[4] = { qa.x, qb.x, qa.y, qb.y };
            uint32_t al[4] = { qa.z, qb.z, qa.w, qb.w };
            #pragma unroll
            for (int nb = 0; nb < 8; ++nb) {
                uint4 qB = B1I[(p * 64 + nb * 8 + g) * 4 + t];
                mma_bf16(acc[nb], ah, qB.x, qB.y);
                mma_bf16(acc[nb], al, qB.x, qB.y);
                mma_bf16(acc[nb], ah, qB.z, qB.w);
            }
        }
        __syncwarp();

        // ================== epilogue 1: LayerNorm + GELU -> A2 frags ==================
        uint32_t a2h[4][4], a2l[4][4];
        {
            float sum0 = 0.f, sum1 = 0.f, sq0 = 0.f, sq1 = 0.f;
            #pragma unroll
            for (int nb = 0; nb < 8; ++nb) {
                sum0 += acc[nb][0] + acc[nb][1];
                sum1 += acc[nb][2] + acc[nb][3];
                sq0 = fmaf(acc[nb][0], acc[nb][0], sq0); sq0 = fmaf(acc[nb][1], acc[nb][1], sq0);
                sq1 = fmaf(acc[nb][2], acc[nb][2], sq1); sq1 = fmaf(acc[nb][3], acc[nb][3], sq1);
            }
            sum0 += __shfl_xor_sync(~0u, sum0, 1); sum0 += __shfl_xor_sync(~0u, sum0, 2);
            sum1 += __shfl_xor_sync(~0u, sum1, 1); sum1 += __shfl_xor_sync(~0u, sum1, 2);
            sq0  += __shfl_xor_sync(~0u, sq0, 1);  sq0  += __shfl_xor_sync(~0u, sq0, 2);
            sq1  += __shfl_xor_sync(~0u, sq1, 1);  sq1  += __shfl_xor_sync(~0u, sq1, 2);
            const float mu0 = sum0 * (1.0f / 64.0f), mu1 = sum1 * (1.0f / 64.0f);
            const float rstd0 = rsqrtf(fmaf(-mu0, mu0, sq0 * (1.0f / 64.0f)) + 1e-5f);
            const float rstd1 = rsqrtf(fmaf(-mu1, mu1, sq1 * (1.0f / 64.0f)) + 1e-5f);

            #pragma unroll
            for (int ks = 0; ks < 4; ++ks) {
                float v00, v01, v10, v11, v20, v21, v30, v31;
                {
                    int nb = 2 * ks;
                    int col = nb * 8 + 2 * t;
                    float g0 = smf[F_LNG + col], g1 = smf[F_LNG + col + 1];
                    float e0 = smf[F_LNB + col], e1 = smf[F_LNB + col + 1];
                    v00 = gelu_fast(fmaf((acc[nb][0] - mu0) * rstd0, g0, e0));
                    v01 = gelu_fast(fmaf((acc[nb][1] - mu0) * rstd0, g1, e1));
                    v10 = gelu_fast(fmaf((acc[nb][2] - mu1) * rstd1, g0, e0));
                    v11 = gelu_fast(fmaf((acc[nb][3] - mu1) * rstd1, g1, e1));
                }
                {
                    int nb = 2 * ks + 1;
                    int col = nb * 8 + 2 * t;
                    float g0 = smf[F_LNG + col], g1 = smf[F_LNG + col + 1];
                    float e0 = smf[F_LNB + col], e1 = smf[F_LNB + col + 1];
                    v20 = gelu_fast(fmaf((acc[nb][0] - mu0) * rstd0, g0, e0));
                    v21 = gelu_fast(fmaf((acc[nb][1] - mu0) * rstd0, g1, e1));
                    v30 = gelu_fast(fmaf((acc[nb][2] - mu1) * rstd1, g0, e0));
                    v31 = gelu_fast(fmaf((acc[nb][3] - mu1) * rstd1, g1, e1));
                }
                pack_pair(v00, v01, a2h[ks][0], a2l[ks][0]);
                pack_pair(v10, v11, a2h[ks][1], a2l[ks][1]);
                pack_pair(v20, v21, a2h[ks][2], a2l[ks][2]);
                pack_pair(v30, v31, a2h[ks][3], a2l[ks][3]);
            }
        }

        // ================== GEMM2: [16x64] x [64x64] (full 3-pass) ==================
        #pragma unroll
        for (int nb = 0; nb < 8; ++nb)
            #pragma unroll
            for (int j = 0; j < 4; ++j) acc[nb][j] = 0.f;
        #pragma unroll
        for (int ks = 0; ks < 4; ++ks) {
            #pragma unroll
            for (int nb = 0; nb < 8; ++nb) {
                uint4 qB = B2I[(ks * 64 + nb * 8 + g) * 4 + t];
                mma_bf16(acc[nb], a2h[ks], qB.x, qB.y);
                mma_bf16(acc[nb], a2l[ks], qB.x, qB.y);
                mma_bf16(acc[nb], a2h[ks], qB.z, qB.w);
            }
        }

        // ================== epilogue 2: +b1, GELU -> A3 frags ==================
        uint32_t a3h[4][4], a3l[4][4];
        #pragma unroll
        for (int ks = 0; ks < 4; ++ks) {
            float v00, v01, v10, v11, v20, v21, v30, v31;
            {
                int nb = 2 * ks;
                int col = nb * 8 + 2 * t;
                float b0 = smf[F_BB1 + col], bb1v = smf[F_BB1 + col + 1];
                v00 = gelu_fast(acc[nb][0] + b0);
                v01 = gelu_fast(acc[nb][1] + bb1v);
                v10 = gelu_fast(acc[nb][2] + b0);
                v11 = gelu_fast(acc[nb][3] + bb1v);
            }
            {
                int nb = 2 * ks + 1;
                int col = nb * 8 + 2 * t;
                float b0 = smf[F_BB1 + col], bb1v = smf[F_BB1 + col + 1];
                v20 = gelu_fast(acc[nb][0] + b0);
                v21 = gelu_fast(acc[nb][1] + bb1v);
                v30 = gelu_fast(acc[nb][2] + b0);
                v31 = gelu_fast(acc[nb][3] + bb1v);
            }
            pack_pair(v00, v01, a3h[ks][0], a3l[ks][0]);
            pack_pair(v10, v11, a3h[ks][1], a3l[ks][1]);
            pack_pair(v20, v21, a3h[ks][2], a3l[ks][2]);
            pack_pair(v30, v31, a3h[ks][3], a3l[ks][3]);
        }

        // ================== GEMM3: [16x64] x [64x32] (full 3-pass) ==================
        float acc3[4][4];
        #pragma unroll
        for (int nb = 0; nb < 4; ++nb)
            #pragma unroll
            for (int j = 0; j < 4; ++j) acc3[nb][j] = 0.f;
        #pragma unroll
        for (int ks = 0; ks < 4; ++ks) {
            #pragma unroll
            for (int nb = 0; nb < 4; ++nb) {
                uint4 qB = B3I[(ks * 32 + nb * 8 + g) * 4 + t];
                mma_bf16(acc3[nb], a3h[ks], qB.x, qB.y);
                mma_bf16(acc3[nb], a3l[ks], qB.x, qB.y);
                mma_bf16(acc3[nb], a3h[ks], qB.z, qB.w);
            }
        }

        // ================== epilogue 3: +b2 -> out ==================
        #pragma unroll
        for (int nb = 0; nb < 4; ++nb) {
            int col = nb * 8 + 2 * t;
            float b20 = smf[F_BB2 + col], b21 = smf[F_BB2 + col + 1];
            if (rowbase + g < B)
                *(float2*)(out + (size_t)(rowbase + g) * 32 + col) =
                    make_float2(acc3[nb][0] + b20, acc3[nb][1] + b21);
            if (rowbase + g + 8 < B)
                *(float2*)(out + (size_t)(rowbase + g + 8) * 32 + col) =
                    make_float2(acc3[nb][2] + b20, acc3[nb][3] + b21);
        }
        __syncwarp();
    }
}

extern "C" void kernel_launch(void* const* d_in, const int* in_sizes, int n_in,
                              void* d_out, int out_size) {
    const float* z_geo    = (const float*)d_in[0];
    const float* z_tex    = (const float*)d_in[1];
    const float* chart_w  = (const float*)d_in[2];
    const float* chart_b  = (const float*)d_in[3];
    const float* router_w = (const float*)d_in[4];
    const float* router_b = (const float*)d_in[5];
    const float* centers  = (const float*)d_in[6];
    const float* tex_w    = (const float*)d_in[7];
    const float* tex_b    = (const float*)d_in[8];
    const float* ln_g     = (const float*)d_in[9];
    const float* ln_b     = (const float*)d_in[10];
    const float* w1       = (const float*)d_in[11];
    const float* b1       = (const float*)d_in[12];
    const float* w2       = (const float*)d_in[13];
    const float* b2       = (const float*)d_in[14];
    float* out = (float*)d_out;

    const int B = in_sizes[0] / 16;
    cudaFuncSetAttribute(topo_decoder_mma6,
                         cudaFuncAttributeMaxDynamicSharedMemorySize, SMEM_BYTES);
    topo_decoder_mma6<<<GRID_CTAS, NT, SMEM_BYTES>>>(
        z_geo, z_tex, chart_w, chart_b, router_w, router_b, centers,
        tex_w, tex_b, ln_g, ln_b, w1, b1, w2, b2, out, B);
}

// round 10
// speedup vs baseline: 5.5292x; 1.1899x over previous
#include <cuda_runtime.h>
#include <cuda_fp16.h>
#include <math.h>
#include <stdint.h>

#define NT 640
#define TILE 320
#define GRID_CTAS 148
#define XSTRIDE 322   // uint4 row stride (TILE+2): conflict-free for both STS.128 and LDS.128

// smem: XI (uint4) | B1I/B2I/B3I (uint2, fp16 hi-only) | misc floats
#define XI_N   (2 * 4 * XSTRIDE)          // uint4 count
#define B1I_N  2560                        // uint2 count
#define B2I_N  1024
#define B3I_N  512
#define MISC_F 512
#define SMEM_BYTES (XI_N * 16 + (B1I_N + B2I_N + B3I_N) * 8 + MISC_F * 4)
// misc float offsets
#define F_LNG 0
#define F_LNB 64
#define F_BB1 128
#define F_BB2 192
#define F_CEN 224
#define F_RW  352
#define F_RB  480
#define F_CS  488

// fp16 pack: (v0 -> lo half, v1 -> hi half)
__device__ __forceinline__ uint32_t pack_f16(float v0, float v1) {
    uint32_t h;
    asm("cvt.rn.f16x2.f32 %0, %1, %2;" : "=r"(h) : "f"(v1), "f"(v0));
    return h;
}
// fp16 hi + residual-lo pair
__device__ __forceinline__ void pack_pair_f16(float v0, float v1, uint32_t &hi, uint32_t &lo) {
    asm("cvt.rn.f16x2.f32 %0, %1, %2;" : "=r"(hi) : "f"(v1), "f"(v0));
    __half2 h = *reinterpret_cast<__half2*>(&hi);
    float h0 = __low2float(h), h1 = __high2float(h);
    asm("cvt.rn.f16x2.f32 %0, %1, %2;" : "=r"(lo) : "f"(v1 - h1), "f"(v0 - h0));
}
__device__ __forceinline__ void mma_f16(float* c, const uint32_t* a, uint32_t b0, uint32_t b1) {
    asm volatile(
        "mma.sync.aligned.m16n8k16.row.col.f32.f16.f16.f32 "
        "{%0,%1,%2,%3}, {%4,%5,%6,%7}, {%8,%9}, {%0,%1,%2,%3};"
        : "+f"(c[0]), "+f"(c[1]), "+f"(c[2]), "+f"(c[3])
        : "r"(a[0]), "r"(a[1]), "r"(a[2]), "r"(a[3]), "r"(b0), "r"(b1));
}
// branchless gelu: A&S 7.1.26 erf (|err| <= 1.5e-7)
__device__ __forceinline__ float gelu_fast(float x) {
    float ax = fabsf(x);
    float y = ax * 0.70710678118654752f;
    float t = __fdividef(1.0f, fmaf(0.3275911f, y, 1.0f));
    float p = fmaf(fmaf(fmaf(fmaf(1.061405429f, t, -1.453152027f), t,
                             1.421413741f), t, -0.284496736f), t, 0.254829592f) * t;
    float e = __expf(-y * y);
    return fmaxf(x, 0.0f) - 0.5f * ax * p * e;
}
__device__ __forceinline__ float b1val(int k, int h,
    const float* __restrict__ chart_w, const float* __restrict__ tex_w,
    const float* __restrict__ chart_b, const float* __restrict__ tex_b) {
    if (k < 128)  return chart_w[(k >> 4) * 1024 + h * 16 + (k & 15)];
    if (k < 144)  return tex_w[h * 16 + (k - 128)];
    if (k < 152)  return chart_b[(k - 144) * 64 + h];
    if (k == 152) return tex_b[h];
    return 0.0f;
}

__global__ __launch_bounds__(NT)
void topo_decoder_mma7(
    const float* __restrict__ z_geo, const float* __restrict__ z_tex,
    const float* __restrict__ chart_w, const float* __restrict__ chart_b,
    const float* __restrict__ router_w, const float* __restrict__ router_b,
    const float* __restrict__ centers,
    const float* __restrict__ tex_w, const float* __restrict__ tex_b,
    const float* __restrict__ ln_g, const float* __restrict__ ln_b,
    const float* __restrict__ w1, const float* __restrict__ b1,
    const float* __restrict__ w2, const float* __restrict__ b2,
    float* __restrict__ out, int B)
{
    extern __shared__ uint4 smq[];
    uint4* XI  = smq;
    uint2* B1I = (uint2*)(XI + XI_N);
    uint2* B2I = B1I + B1I_N;
    uint2* B3I = B2I + B2I_N;
    float* smf = (float*)(B3I + B3I_N);

    const int tid = threadIdx.x;
    const int wid = tid >> 5;
    const int lane = tid & 31;
    const int g = lane >> 2;
    const int t = lane & 3;

    // ================== one-time weight packing (fp16 hi only) ==================
    for (int idx = tid; idx < B1I_N; idx += NT) {
        int tt = idx & 3, n = (idx >> 2) & 63, ks = idx >> 8;
        int k0 = ks * 16 + 2 * tt;
        uint2 q;
        q.x = pack_f16(b1val(k0,     n, chart_w, tex_w, chart_b, tex_b),
                       b1val(k0 + 1, n, chart_w, tex_w, chart_b, tex_b));
        q.y = pack_f16(b1val(k0 + 8, n, chart_w, tex_w, chart_b, tex_b),
                       b1val(k0 + 9, n, chart_w, tex_w, chart_b, tex_b));
        B1I[idx] = q;
    }
    for (int idx = tid; idx < B2I_N; idx += NT) {
        int tt = idx & 3, n = (idx >> 2) & 63, ks = idx >> 8;
        int k0 = ks * 16 + 2 * tt;
        uint2 q;
        q.x = pack_f16(w1[n * 64 + k0],     w1[n * 64 + k0 + 1]);
        q.y = pack_f16(w1[n * 64 + k0 + 8], w1[n * 64 + k0 + 9]);
        B2I[idx] = q;
    }
    for (int idx = tid; idx < B3I_N; idx += NT) {
        int tt = idx & 3, n = (idx >> 2) & 31, ks = idx >> 7;
        int k0 = ks * 16 + 2 * tt;
        uint2 q;
        q.x = pack_f16(w2[n * 64 + k0],     w2[n * 64 + k0 + 1]);
        q.y = pack_f16(w2[n * 64 + k0 + 8], w2[n * 64 + k0 + 9]);
        B3I[idx] = q;
    }
    if (tid < 64) {
        smf[F_LNG + tid] = ln_g[tid];
        smf[F_LNB + tid] = ln_b[tid];
        smf[F_BB1 + tid] = b1[tid];
    }
    if (tid < 32) smf[F_BB2 + tid] = b2[tid];
    if (tid < 128) { smf[F_CEN + tid] = centers[tid]; smf[F_RW + tid] = router_w[tid]; }
    if (tid < 8) {
        smf[F_RB + tid] = router_b[tid];
        float cs = 0.f;
        for (int l = 0; l < 16; ++l) cs = fmaf(centers[tid * 16 + l], centers[tid * 16 + l], cs);
        smf[F_CS + tid] = 1.0f - cs;
    }
    __syncthreads();

    const int nTiles = (B + TILE - 1) / TILE;
    const int xcol = wid * 16;
    const int rl = tid >> 1;          // staging row-in-tile
    const int half = tid & 1;

    for (int tile = blockIdx.x; tile < nTiles; tile += GRID_CTAS) {
        const int rowbase = tile * TILE + xcol;
        const int rawrow = tile * TILE + rl;
        const int srow = rawrow < B ? rawrow : (B - 1);

        // ================== prologue: split router ==================
        float zg[16], w8[8];
        {
            const float4* p = (const float4*)(z_geo + (size_t)srow * 16);
            #pragma unroll
            for (int q = 0; q < 4; ++q) {
                float4 v = p[q];
                zg[q*4+0]=v.x; zg[q*4+1]=v.y; zg[q*4+2]=v.z; zg[q*4+3]=v.w;
            }
            float z_sq = 0.f;
            #pragma unroll
            for (int l = 0; l < 16; ++l) z_sq = fmaf(zg[l], zg[l], z_sq);
            const float one_minus = 1.0f - z_sq;
            const float inv_tau = __fdividef(1.0f, fmaxf(2.0f * fmaxf(one_minus, 0.001f), 0.01f));

            const int cb = half * 4;
            float s[4], mx = -1e30f;
            #pragma unroll
            for (int i = 0; i < 4; ++i) {
                const int c = cb + i;
                float ds = 0.f, dr = 0.f;
                #pragma unroll
                for (int l = 0; l < 16; ++l) {
                    float cv = smf[F_CEN + c * 16 + l];
                    float d = zg[l] - cv;
                    ds = fmaf(d, d, ds);
                    dr = fmaf(zg[l], smf[F_RW + c * 16 + l], dr);
                }
                float denom = one_minus * smf[F_CS + c];
                float tt2 = fmaxf(2.0f * __fdividef(ds, denom + 0.001f), 0.001f);
                float rad = tt2 * (tt2 + 2.0f);
                float sq = rad * rsqrtf(rad);
                float dist = __logf(1.0f + tt2 + sq);
                s[i] = (-dist + 0.1f * (dr + smf[F_RB + c])) * inv_tau;
                mx = fmaxf(mx, s[i]);
            }
            mx = fmaxf(mx, __shfl_xor_sync(~0u, mx, 1));
            float wloc[4], psum = 0.f;
            #pragma unroll
            for (int i = 0; i < 4; ++i) { wloc[i] = __expf(s[i] - mx); psum += wloc[i]; }
            float ssum = psum + __shfl_xor_sync(~0u, psum, 1);
            const float inv_sum = __fdividef(1.0f, ssum);
            #pragma unroll
            for (int i = 0; i < 4; ++i) {
                float wi = wloc[i] * inv_sum;
                w8[cb + i] = wi;
                w8[(cb ^ 4) + i] = __shfl_xor_sync(~0u, wi, 1);
            }
            if (rawrow < B) {
                float* rout = out + (size_t)B * 32 + (size_t)rawrow * 8 + cb;
                *(float4*)rout = make_float4(w8[cb], w8[cb+1], w8[cb+2], w8[cb+3]);
            }
        }
        // prefetch zt slice this thread stages (ks 8)
        float4 ztA = *(const float4*)(z_tex + (size_t)srow * 16 + 4 * half);
        float4 ztB = *(const float4*)(z_tex + (size_t)srow * 16 + 4 * half + 8);
        // ks9 staging operands (avoid dynamic w8 indexing)
        const float wa0 = half ? w8[4] : w8[0];
        const float wa1 = half ? w8[5] : w8[1];
        const float wb0 = half ? w8[6] : w8[2];
        const float wb1 = half ? w8[7] : w8[3];

        // ================== GEMM1: 2-slot ring over ks ==================
        float acc[8][4];
        #pragma unroll
        for (int nb = 0; nb < 8; ++nb)
            #pragma unroll
            for (int j = 0; j < 4; ++j) acc[nb][j] = 0.f;

        #pragma unroll
        for (int p = 0; p < 10; ++p) {
            const int slot = p & 1;
            // ---- stage ks p (each thread: tt = 2*half, 2*half+1) ----
            if (p < 8) {
                const float wc = w8[p];
                #pragma unroll
                for (int j = 0; j < 2; ++j) {
                    const int tt = 2 * half + j;
                    uint4 q;
                    pack_pair_f16(wc * zg[2*tt],   wc * zg[2*tt+1], q.x, q.z);
                    pack_pair_f16(wc * zg[2*tt+8], wc * zg[2*tt+9], q.y, q.w);
                    XI[(slot * 4 + tt) * XSTRIDE + rl] = q;
                }
            } else if (p == 8) {
                {
                    uint4 q;
                    pack_pair_f16(ztA.x, ztA.y, q.x, q.z);
                    pack_pair_f16(ztB.x, ztB.y, q.y, q.w);
                    XI[(slot * 4 + 2 * half) * XSTRIDE + rl] = q;
                }
                {
                    uint4 q;
                    pack_pair_f16(ztA.z, ztA.w, q.x, q.z);
                    pack_pair_f16(ztB.z, ztB.w, q.y, q.w);
                    XI[(slot * 4 + 2 * half + 1) * XSTRIDE + rl] = q;
                }
            } else {
                {
                    uint4 q;
                    pack_pair_f16(wa0, wa1, q.x, q.z);
                    pack_pair_f16(half ? 0.0f : 1.0f, 0.0f, q.y, q.w);
                    XI[(slot * 4 + 2 * half) * XSTRIDE + rl] = q;
                }
                {
                    uint4 q;
                    pack_pair_f16(wb0, wb1, q.x, q.z);
                    pack_pair_f16(0.0f, 0.0f, q.y, q.w);
                    XI[(slot * 4 + 2 * half + 1) * XSTRIDE + rl] = q;
                }
            }
            __syncwarp();
            // ---- MMA ks p: 2-pass (A hi + A lo) x (B fp16) ----
            uint4 qa = XI[(slot * 4 + t) * XSTRIDE + xcol + g];
            uint4 qb = XI[(slot * 4 + t) * XSTRIDE + xcol + g + 8];
            uint32_t ah[4] = { qa.x, qb.x, qa.y, qb.y };
            uint32_t al[4] = { qa.z, qb.z, qa.w, qb.w };
            #pragma unroll
            for (int nb = 0; nb < 8; ++nb) {
                uint2 qB = B1I[(p * 64 + nb * 8 + g) * 4 + t];
                mma_f16(acc[nb], ah, qB.x, qB.y);
                mma_f16(acc[nb], al, qB.x, qB.y);
            }
        }
        __syncwarp();

        // ================== epilogue 1: LayerNorm + GELU -> A2 frags ==================
        uint32_t a2h[4][4], a2l[4][4];
        {
            float sum0 = 0.f, sum1 = 0.f, sq0 = 0.f, sq1 = 0.f;
            #pragma unroll
            for (int nb = 0; nb < 8; ++nb) {
                sum0 += acc[nb][0] + acc[nb][1];
                sum1 += acc[nb][2] + acc[nb][3];
                sq0 = fmaf(acc[nb][0], acc[nb][0], sq0); sq0 = fmaf(acc[nb][1], acc[nb][1], sq0);
                sq1 = fmaf(acc[nb][2], acc[nb][2], sq1); sq1 = fmaf(acc[nb][3], acc[nb][3], sq1);
            }
            sum0 += __shfl_xor_sync(~0u, sum0, 1); sum0 += __shfl_xor_sync(~0u, sum0, 2);
            sum1 += __shfl_xor_sync(~0u, sum1, 1); sum1 += __shfl_xor_sync(~0u, sum1, 2);
            sq0  += __shfl_xor_sync(~0u, sq0, 1);  sq0  += __shfl_xor_sync(~0u, sq0, 2);
            sq1  += __shfl_xor_sync(~0u, sq1, 1);  sq1  += __shfl_xor_sync(~0u, sq1, 2);
            const float mu0 = sum0 * (1.0f / 64.0f), mu1 = sum1 * (1.0f / 64.0f);
            const float rstd0 = rsqrtf(fmaf(-mu0, mu0, sq0 * (1.0f / 64.0f)) + 1e-5f);
            const float rstd1 = rsqrtf(fmaf(-mu1, mu1, sq1 * (1.0f / 64.0f)) + 1e-5f);

            #pragma unroll
            for (int ks = 0; ks < 4; ++ks) {
                float v00, v01, v10, v11, v20, v21, v30, v31;
                {
                    int nb = 2 * ks;
                    int col = nb * 8 + 2 * t;
                    float g0 = smf[F_LNG + col], g1 = smf[F_LNG + col + 1];
                    float e0 = smf[F_LNB + col], e1 = smf[F_LNB + col + 1];
                    v00 = gelu_fast(fmaf((acc[nb][0] - mu0) * rstd0, g0, e0));
                    v01 = gelu_fast(fmaf((acc[nb][1] - mu0) * rstd0, g1, e1));
                    v10 = gelu_fast(fmaf((acc[nb][2] - mu1) * rstd1, g0, e0));
                    v11 = gelu_fast(fmaf((acc[nb][3] - mu1) * rstd1, g1, e1));
                }
                {
                    int nb = 2 * ks + 1;
                    int col = nb * 8 + 2 * t;
                    float g0 = smf[F_LNG + col], g1 = smf[F_LNG + col + 1];
                    float e0 = smf[F_LNB + col], e1 = smf[F_LNB + col + 1];
                    v20 = gelu_fast(fmaf((acc[nb][0] - mu0) * rstd0, g0, e0));
                    v21 = gelu_fast(fmaf((acc[nb][1] - mu0) * rstd0, g1, e1));
                    v30 = gelu_fast(fmaf((acc[nb][2] - mu1) * rstd1, g0, e0));
                    v31 = gelu_fast(fmaf((acc[nb][3] - mu1) * rstd1, g1, e1));
                }
                pack_pair_f16(v00, v01, a2h[ks][0], a2l[ks][0]);
                pack_pair_f16(v10, v11, a2h[ks][1], a2l[ks][1]);
                pack_pair_f16(v20, v21, a2h[ks][2], a2l[ks][2]);
                pack_pair_f16(v30, v31, a2h[ks][3], a2l[ks][3]);
            }
        }

        // ================== GEMM2: [16x64] x [64x64] (fp16 2-pass) ==================
        #pragma unroll
        for (int nb = 0; nb < 8; ++nb)
            #pragma unroll
            for (int j = 0; j < 4; ++j) acc[nb][j] = 0.f;
        #pragma unroll
        for (int ks = 0; ks < 4; ++ks) {
            #pragma unroll
            for (int nb = 0; nb < 8; ++nb) {
                uint2 qB = B2I[(ks * 64 + nb * 8 + g) * 4 + t];
                mma_f16(acc[nb], a2h[ks], qB.x, qB.y);
                mma_f16(acc[nb], a2l[ks], qB.x, qB.y);
            }
        }

        // ================== epilogue 2: +b1, GELU -> A3 frags ==================
        uint32_t a3h[4][4], a3l[4][4];
        #pragma unroll
        for (int ks = 0; ks < 4; ++ks) {
            float v00, v01, v10, v11, v20, v21, v30, v31;
            {
                int nb = 2 * ks;
                int col = nb * 8 + 2 * t;
                float b0 = smf[F_BB1 + col], bb1v = smf[F_BB1 + col + 1];
                v00 = gelu_fast(acc[nb][0] + b0);
                v01 = gelu_fast(acc[nb][1] + bb1v);
                v10 = gelu_fast(acc[nb][2] + b0);
                v11 = gelu_fast(acc[nb][3] + bb1v);
            }
            {
                int nb = 2 * ks + 1;
                int col = nb * 8 + 2 * t;
                float b0 = smf[F_BB1 + col], bb1v = smf[F_BB1 + col + 1];
                v20 = gelu_fast(acc[nb][0] + b0);
                v21 = gelu_fast(acc[nb][1] + bb1v);
                v30 = gelu_fast(acc[nb][2] + b0);
                v31 = gelu_fast(acc[nb][3] + bb1v);
            }
            pack_pair_f16(v00, v01, a3h[ks][0], a3l[ks][0]);
            pack_pair_f16(v10, v11, a3h[ks][1], a3l[ks][1]);
            pack_pair_f16(v20, v21, a3h[ks][2], a3l[ks][2]);
            pack_pair_f16(v30, v31, a3h[ks][3], a3l[ks][3]);
        }

        // ================== GEMM3: [16x64] x [64x32] (fp16 2-pass) ==================
        float acc3[4][4];
        #pragma unroll
        for (int nb = 0; nb < 4; ++nb)
            #pragma unroll
            for (int j = 0; j < 4; ++j) acc3[nb][j] = 0.f;
        #pragma unroll
        for (int ks = 0; ks < 4; ++ks) {
            #pragma unroll
            for (int nb = 0; nb < 4; ++nb) {
                uint2 qB = B3I[(ks * 32 + nb * 8 + g) * 4 + t];
                mma_f16(acc3[nb], a3h[ks], qB.x, qB.y);
                mma_f16(acc3[nb], a3l[ks], qB.x, qB.y);
            }
        }

        // ================== epilogue 3: +b2 -> out ==================
        #pragma unroll
        for (int nb = 0; nb < 4; ++nb) {
            int col = nb * 8 + 2 * t;
            float b20 = smf[F_BB2 + col], b21 = smf[F_BB2 + col + 1];
            if (rowbase + g < B)
                *(float2*)(out + (size_t)(rowbase + g) * 32 + col) =
                    make_float2(acc3[nb][0] + b20, acc3[nb][1] + b21);
            if (rowbase + g + 8 < B)
                *(float2*)(out + (size_t)(rowbase + g + 8) * 32 + col) =
                    make_float2(acc3[nb][2] + b20, acc3[nb][3] + b21);
        }
        __syncwarp();
    }
}

extern "C" void kernel_launch(void* const* d_in, const int* in_sizes, int n_in,
                              void* d_out, int out_size) {
    const float* z_geo    = (const float*)d_in[0];
    const float* z_tex    = (const float*)d_in[1];
    const float* chart_w  = (const float*)d_in[2];
    const float* chart_b  = (const float*)d_in[3];
    const float* router_w = (const float*)d_in[4];
    const float* router_b = (const float*)d_in[5];
    const float* centers  = (const float*)d_in[6];
    const float* tex_w    = (const float*)d_in[7];
    const float* tex_b    = (const float*)d_in[8];
    const float* ln_g     = (const float*)d_in[9];
    const float* ln_b     = (const float*)d_in[10];
    const float* w1       = (const float*)d_in[11];
    const float* b1       = (const float*)d_in[12];
    const float* w2       = (const float*)d_in[13];
    const float* b2       = (const float*)d_in[14];
    float* out = (float*)d_out;

    const int B = in_sizes[0] / 16;
    cudaFuncSetAttribute(topo_decoder_mma7,
                         cudaFuncAttributeMaxDynamicSharedMemorySize, SMEM_BYTES);
    topo_decoder_mma7<<<GRID_CTAS, NT, SMEM_BYTES>>>(
        z_geo, z_tex, chart_w, chart_b, router_w, router_b, centers,
        tex_w, tex_b, ln_g, ln_b, w1, b1, w2, b2, out, B);
}

// round 11
// speedup vs baseline: 5.9129x; 1.0694x over previous
#include <cuda_runtime.h>
#include <cuda_fp16.h>
#include <math.h>
#include <stdint.h>

#define NT 768
#define TILE 384
#define GRID_CTAS 148
#define XSTRIDE 386   // uint4 row stride (TILE+2): mod-32 == 2 -> conflict-free STS/LDS.128

// smem: XI (uint4) | B1I/B2I/B3I (uint2, fp16) | misc floats
#define XI_N   (2 * 4 * XSTRIDE)          // uint4 count
#define B1I_N  2560                        // uint2 count
#define B2I_N  1024
#define B3I_N  512
#define MISC_F 512
#define SMEM_BYTES (XI_N * 16 + (B1I_N + B2I_N + B3I_N) * 8 + MISC_F * 4)
// misc float offsets
#define F_LNG 0
#define F_LNB 64
#define F_BB1 128
#define F_BB2 192
#define F_CEN 224
#define F_RW  352
#define F_RB  480
#define F_CS  488

// fp16 pack: (v0 -> lo half, v1 -> hi half)
__device__ __forceinline__ uint32_t pack_f16(float v0, float v1) {
    uint32_t h;
    asm("cvt.rn.f16x2.f32 %0, %1, %2;" : "=r"(h) : "f"(v1), "f"(v0));
    return h;
}
// fp16 hi + residual-lo pair
__device__ __forceinline__ void pack_pair_f16(float v0, float v1, uint32_t &hi, uint32_t &lo) {
    asm("cvt.rn.f16x2.f32 %0, %1, %2;" : "=r"(hi) : "f"(v1), "f"(v0));
    __half2 h = *reinterpret_cast<__half2*>(&hi);
    float h0 = __low2float(h), h1 = __high2float(h);
    asm("cvt.rn.f16x2.f32 %0, %1, %2;" : "=r"(lo) : "f"(v1 - h1), "f"(v0 - h0));
}
__device__ __forceinline__ void mma_f16(float* c, const uint32_t* a, uint32_t b0, uint32_t b1) {
    asm volatile(
        "mma.sync.aligned.m16n8k16.row.col.f32.f16.f16.f32 "
        "{%0,%1,%2,%3}, {%4,%5,%6,%7}, {%8,%9}, {%0,%1,%2,%3};"
        : "+f"(c[0]), "+f"(c[1]), "+f"(c[2]), "+f"(c[3])
        : "r"(a[0]), "r"(a[1]), "r"(a[2]), "r"(a[3]), "r"(b0), "r"(b1));
}
// branchless gelu: A&S 7.1.26 erf (|err| <= 1.5e-7)
__device__ __forceinline__ float gelu_fast(float x) {
    float ax = fabsf(x);
    float y = ax * 0.70710678118654752f;
    float t = __fdividef(1.0f, fmaf(0.3275911f, y, 1.0f));
    float p = fmaf(fmaf(fmaf(fmaf(1.061405429f, t, -1.453152027f), t,
                             1.421413741f), t, -0.284496736f), t, 0.254829592f) * t;
    float e = __expf(-y * y);
    return fmaxf(x, 0.0f) - 0.5f * ax * p * e;
}
__device__ __forceinline__ float b1val(int k, int h,
    const float* __restrict__ chart_w, const float* __restrict__ tex_w,
    const float* __restrict__ chart_b, const float* __restrict__ tex_b) {
    if (k < 128)  return chart_w[(k >> 4) * 1024 + h * 16 + (k & 15)];
    if (k < 144)  return tex_w[h * 16 + (k - 128)];
    if (k < 152)  return chart_b[(k - 144) * 64 + h];
    if (k == 152) return tex_b[h];
    return 0.0f;
}

__global__ __launch_bounds__(NT)
void topo_decoder_mma8(
    const float* __restrict__ z_geo, const float* __restrict__ z_tex,
    const float* __restrict__ chart_w, const float* __restrict__ chart_b,
    const float* __restrict__ router_w, const float* __restrict__ router_b,
    const float* __restrict__ centers,
    const float* __restrict__ tex_w, const float* __restrict__ tex_b,
    const float* __restrict__ ln_g, const float* __restrict__ ln_b,
    const float* __restrict__ w1, const float* __restrict__ b1,
    const float* __restrict__ w2, const float* __restrict__ b2,
    float* __restrict__ out, int B)
{
    extern __shared__ uint4 smq[];
    uint4* XI  = smq;
    uint2* B1I = (uint2*)(XI + XI_N);
    uint2* B2I = B1I + B1I_N;
    uint2* B3I = B2I + B2I_N;
    float* smf = (float*)(B3I + B3I_N);

    const int tid = threadIdx.x;
    const int wid = tid >> 5;
    const int lane = tid & 31;
    const int g = lane >> 2;
    const int t = lane & 3;

    // ================== one-time weight packing (fp16) ==================
    for (int idx = tid; idx < B1I_N; idx += NT) {
        int tt = idx & 3, n = (idx >> 2) & 63, ks = idx >> 8;
        int k0 = ks * 16 + 2 * tt;
        uint2 q;
        q.x = pack_f16(b1val(k0,     n, chart_w, tex_w, chart_b, tex_b),
                       b1val(k0 + 1, n, chart_w, tex_w, chart_b, tex_b));
        q.y = pack_f16(b1val(k0 + 8, n, chart_w, tex_w, chart_b, tex_b),
                       b1val(k0 + 9, n, chart_w, tex_w, chart_b, tex_b));
        B1I[idx] = q;
    }
    for (int idx = tid; idx < B2I_N; idx += NT) {
        int tt = idx & 3, n = (idx >> 2) & 63, ks = idx >> 8;
        int k0 = ks * 16 + 2 * tt;
        uint2 q;
        q.x = pack_f16(w1[n * 64 + k0],     w1[n * 64 + k0 + 1]);
        q.y = pack_f16(w1[n * 64 + k0 + 8], w1[n * 64 + k0 + 9]);
        B2I[idx] = q;
    }
    for (int idx = tid; idx < B3I_N; idx += NT) {
        int tt = idx & 3, n = (idx >> 2) & 31, ks = idx >> 7;
        int k0 = ks * 16 + 2 * tt;
        uint2 q;
        q.x = pack_f16(w2[n * 64 + k0],     w2[n * 64 + k0 + 1]);
        q.y = pack_f16(w2[n * 64 + k0 + 8], w2[n * 64 + k0 + 9]);
        B3I[idx] = q;
    }
    if (tid < 64) {
        smf[F_LNG + tid] = ln_g[tid];
        smf[F_LNB + tid] = ln_b[tid];
        smf[F_BB1 + tid] = b1[tid];
    }
    if (tid < 32) smf[F_BB2 + tid] = b2[tid];
    if (tid < 128) { smf[F_CEN + tid] = centers[tid]; smf[F_RW + tid] = router_w[tid]; }
    if (tid < 8) {
        smf[F_RB + tid] = router_b[tid];
        float cs = 0.f;
        for (int l = 0; l < 16; ++l) cs = fmaf(centers[tid * 16 + l], centers[tid * 16 + l], cs);
        smf[F_CS + tid] = 1.0f - cs;
    }
    __syncthreads();

    const int nTiles = (B + TILE - 1) / TILE;
    const int xcol = wid * 16;
    const int rl = tid >> 1;          // staging row-in-tile
    const int half = tid & 1;

    for (int tile = blockIdx.x; tile < nTiles; tile += GRID_CTAS) {
        const int rowbase = tile * TILE + xcol;
        const int rawrow = tile * TILE + rl;
        const int srow = rawrow < B ? rawrow : (B - 1);

        // ================== prologue: split router ==================
        float zg[16], w8[8];
        {
            const float4* p = (const float4*)(z_geo + (size_t)srow * 16);
            #pragma unroll
            for (int q = 0; q < 4; ++q) {
                float4 v = p[q];
                zg[q*4+0]=v.x; zg[q*4+1]=v.y; zg[q*4+2]=v.z; zg[q*4+3]=v.w;
            }
            float z_sq = 0.f;
            #pragma unroll
            for (int l = 0; l < 16; ++l) z_sq = fmaf(zg[l], zg[l], z_sq);
            const float one_minus = 1.0f - z_sq;
            const float inv_tau = __fdividef(1.0f, fmaxf(2.0f * fmaxf(one_minus, 0.001f), 0.01f));

            const int cb = half * 4;
            float s[4], mx = -1e30f;
            #pragma unroll
            for (int i = 0; i < 4; ++i) {
                const int c = cb + i;
                float ds = 0.f, dr = 0.f;
                #pragma unroll
                for (int l = 0; l < 16; ++l) {
                    float cv = smf[F_CEN + c * 16 + l];
                    float d = zg[l] - cv;
                    ds = fmaf(d, d, ds);
                    dr = fmaf(zg[l], smf[F_RW + c * 16 + l], dr);
                }
                float denom = one_minus * smf[F_CS + c];
                float tt2 = fmaxf(2.0f * __fdividef(ds, denom + 0.001f), 0.001f);
                float rad = tt2 * (tt2 + 2.0f);
                float sq = rad * rsqrtf(rad);
                float dist = __logf(1.0f + tt2 + sq);
                s[i] = (-dist + 0.1f * (dr + smf[F_RB + c])) * inv_tau;
                mx = fmaxf(mx, s[i]);
            }
            mx = fmaxf(mx, __shfl_xor_sync(~0u, mx, 1));
            float wloc[4], psum = 0.f;
            #pragma unroll
            for (int i = 0; i < 4; ++i) { wloc[i] = __expf(s[i] - mx); psum += wloc[i]; }
            float ssum = psum + __shfl_xor_sync(~0u, psum, 1);
            const float inv_sum = __fdividef(1.0f, ssum);
            #pragma unroll
            for (int i = 0; i < 4; ++i) {
                float wi = wloc[i] * inv_sum;
                w8[cb + i] = wi;
                w8[(cb ^ 4) + i] = __shfl_xor_sync(~0u, wi, 1);
            }
            if (rawrow < B) {
                float* rout = out + (size_t)B * 32 + (size_t)rawrow * 8 + cb;
                *(float4*)rout = make_float4(w8[cb], w8[cb+1], w8[cb+2], w8[cb+3]);
            }
        }
        // prefetch zt slice this thread stages (ks 8)
        float4 ztA = *(const float4*)(z_tex + (size_t)srow * 16 + 4 * half);
        float4 ztB = *(const float4*)(z_tex + (size_t)srow * 16 + 4 * half + 8);
        // ks9 staging operands (avoid dynamic w8 indexing)
        const float wa0 = half ? w8[4] : w8[0];
        const float wa1 = half ? w8[5] : w8[1];
        const float wb0 = half ? w8[6] : w8[2];
        const float wb1 = half ? w8[7] : w8[3];

        // ================== GEMM1: 2-slot ring over ks (A hi+lo, B fp16) ==========
        float acc[8][4];
        #pragma unroll
        for (int nb = 0; nb < 8; ++nb)
            #pragma unroll
            for (int j = 0; j < 4; ++j) acc[nb][j] = 0.f;

        #pragma unroll
        for (int p = 0; p < 10; ++p) {
            const int slot = p & 1;
            // ---- stage ks p (each thread: tt = 2*half, 2*half+1) ----
            if (p < 8) {
                const float wc = w8[p];
                #pragma unroll
                for (int j = 0; j < 2; ++j) {
                    const int tt = 2 * half + j;
                    uint4 q;
                    pack_pair_f16(wc * zg[2*tt],   wc * zg[2*tt+1], q.x, q.z);
                    pack_pair_f16(wc * zg[2*tt+8], wc * zg[2*tt+9], q.y, q.w);
                    XI[(slot * 4 + tt) * XSTRIDE + rl] = q;
                }
            } else if (p == 8) {
                {
                    uint4 q;
                    pack_pair_f16(ztA.x, ztA.y, q.x, q.z);
                    pack_pair_f16(ztB.x, ztB.y, q.y, q.w);
                    XI[(slot * 4 + 2 * half) * XSTRIDE + rl] = q;
                }
                {
                    uint4 q;
                    pack_pair_f16(ztA.z, ztA.w, q.x, q.z);
                    pack_pair_f16(ztB.z, ztB.w, q.y, q.w);
                    XI[(slot * 4 + 2 * half + 1) * XSTRIDE + rl] = q;
                }
            } else {
                {
                    uint4 q;
                    pack_pair_f16(wa0, wa1, q.x, q.z);
                    pack_pair_f16(half ? 0.0f : 1.0f, 0.0f, q.y, q.w);
                    XI[(slot * 4 + 2 * half) * XSTRIDE + rl] = q;
                }
                {
                    uint4 q;
                    pack_pair_f16(wb0, wb1, q.x, q.z);
                    pack_pair_f16(0.0f, 0.0f, q.y, q.w);
                    XI[(slot * 4 + 2 * half + 1) * XSTRIDE + rl] = q;
                }
            }
            __syncwarp();
            // ---- MMA ks p: 2-pass (A hi + A lo) x (B fp16) ----
            uint4 qa = XI[(slot * 4 + t) * XSTRIDE + xcol + g];
            uint4 qb = XI[(slot * 4 + t) * XSTRIDE + xcol + g + 8];
            uint32_t ah[4] = { qa.x, qb.x, qa.y, qb.y };
            uint32_t al[4] = { qa.z, qb.z, qa.w, qb.w };
            #pragma unroll
            for (int nb = 0; nb < 8; ++nb) {
                uint2 qB = B1I[(p * 64 + nb * 8 + g) * 4 + t];
                mma_f16(acc[nb], ah, qB.x, qB.y);
                mma_f16(acc[nb], al, qB.x, qB.y);
            }
        }
        __syncwarp();

        // ================== epilogue 1: LayerNorm + GELU -> A2 frags (hi only) =====
        uint32_t a2h[4][4];
        {
            float sum0 = 0.f, sum1 = 0.f, sq0 = 0.f, sq1 = 0.f;
            #pragma unroll
            for (int nb = 0; nb < 8; ++nb) {
                sum0 += acc[nb][0] + acc[nb][1];
                sum1 += acc[nb][2] + acc[nb][3];
                sq0 = fmaf(acc[nb][0], acc[nb][0], sq0); sq0 = fmaf(acc[nb][1], acc[nb][1], sq0);
                sq1 = fmaf(acc[nb][2], acc[nb][2], sq1); sq1 = fmaf(acc[nb][3], acc[nb][3], sq1);
            }
            sum0 += __shfl_xor_sync(~0u, sum0, 1); sum0 += __shfl_xor_sync(~0u, sum0, 2);
            sum1 += __shfl_xor_sync(~0u, sum1, 1); sum1 += __shfl_xor_sync(~0u, sum1, 2);
            sq0  += __shfl_xor_sync(~0u, sq0, 1);  sq0  += __shfl_xor_sync(~0u, sq0, 2);
            sq1  += __shfl_xor_sync(~0u, sq1, 1);  sq1  += __shfl_xor_sync(~0u, sq1, 2);
            const float mu0 = sum0 * (1.0f / 64.0f), mu1 = sum1 * (1.0f / 64.0f);
            const float rstd0 = rsqrtf(fmaf(-mu0, mu0, sq0 * (1.0f / 64.0f)) + 1e-5f);
            const float rstd1 = rsqrtf(fmaf(-mu1, mu1, sq1 * (1.0f / 64.0f)) + 1e-5f);

            #pragma unroll
            for (int ks = 0; ks < 4; ++ks) {
                float v00, v01, v10, v11, v20, v21, v30, v31;
                {
                    int nb = 2 * ks;
                    int col = nb * 8 + 2 * t;
                    float g0 = smf[F_LNG + col], g1 = smf[F_LNG + col + 1];
                    float e0 = smf[F_LNB + col], e1 = smf[F_LNB + col + 1];
                    v00 = gelu_fast(fmaf((acc[nb][0] - mu0) * rstd0, g0, e0));
                    v01 = gelu_fast(fmaf((acc[nb][1] - mu0) * rstd0, g1, e1));
                    v10 = gelu_fast(fmaf((acc[nb][2] - mu1) * rstd1, g0, e0));
                    v11 = gelu_fast(fmaf((acc[nb][3] - mu1) * rstd1, g1, e1));
                }
                {
                    int nb = 2 * ks + 1;
                    int col = nb * 8 + 2 * t;
                    float g0 = smf[F_LNG + col], g1 = smf[F_LNG + col + 1];
                    float e0 = smf[F_LNB + col], e1 = smf[F_LNB + col + 1];
                    v20 = gelu_fast(fmaf((acc[nb][0] - mu0) * rstd0, g0, e0));
                    v21 = gelu_fast(fmaf((acc[nb][1] - mu0) * rstd0, g1, e1));
                    v30 = gelu_fast(fmaf((acc[nb][2] - mu1) * rstd1, g0, e0));
                    v31 = gelu_fast(fmaf((acc[nb][3] - mu1) * rstd1, g1, e1));
                }
                a2h[ks][0] = pack_f16(v00, v01);
                a2h[ks][1] = pack_f16(v10, v11);
                a2h[ks][2] = pack_f16(v20, v21);
                a2h[ks][3] = pack_f16(v30, v31);
            }
        }

        // ================== GEMM2: [16x64] x [64x64] (fp16, A hi only) ============
        #pragma unroll
        for (int nb = 0; nb < 8; ++nb)
            #pragma unroll
            for (int j = 0; j < 4; ++j) acc[nb][j] = 0.f;
        #pragma unroll
        for (int ks = 0; ks < 4; ++ks) {
            #pragma unroll
            for (int nb = 0; nb < 8; ++nb) {
                uint2 qB = B2I[(ks * 64 + nb * 8 + g) * 4 + t];
                mma_f16(acc[nb], a2h[ks], qB.x, qB.y);
            }
        }

        // ================== epilogue 2: +b1, GELU -> A3 frags (hi only) ===========
        uint32_t a3h[4][4];
        #pragma unroll
        for (int ks = 0; ks < 4; ++ks) {
            float v00, v01, v10, v11, v20, v21, v30, v31;
            {
                int nb = 2 * ks;
                int col = nb * 8 + 2 * t;
                float b0 = smf[F_BB1 + col], bb1v = smf[F_BB1 + col + 1];
                v00 = gelu_fast(acc[nb][0] + b0);
                v01 = gelu_fast(acc[nb][1] + bb1v);
                v10 = gelu_fast(acc[nb][2] + b0);
                v11 = gelu_fast(acc[nb][3] + bb1v);
            }
            {
                int nb = 2 * ks + 1;
                int col = nb * 8 + 2 * t;
                float b0 = smf[F_BB1 + col], bb1v = smf[F_BB1 + col + 1];
                v20 = gelu_fast(acc[nb][0] + b0);
                v21 = gelu_fast(acc[nb][1] + bb1v);
                v30 = gelu_fast(acc[nb][2] + b0);
                v31 = gelu_fast(acc[nb][3] + bb1v);
            }
            a3h[ks][0] = pack_f16(v00, v01);
            a3h[ks][1] = pack_f16(v10, v11);
            a3h[ks][2] = pack_f16(v20, v21);
            a3h[ks][3] = pack_f16(v30, v31);
        }

        // ================== GEMM3: [16x64] x [64x32] (fp16, A hi only) ============
        float acc3[4][4];
        #pragma unroll
        for (int nb = 0; nb < 4; ++nb)
            #pragma unroll
            for (int j = 0; j < 4; ++j) acc3[nb][j] = 0.f;
        #pragma unroll
        for (int ks = 0; ks < 4; ++ks) {
            #pragma unroll
            for (int nb = 0; nb < 4; ++nb) {
                uint2 qB = B3I[(ks * 32 + nb * 8 + g) * 4 + t];
                mma_f16(acc3[nb], a3h[ks], qB.x, qB.y);
            }
        }

        // ================== epilogue 3: +b2 -> out ==================
        #pragma unroll
        for (int nb = 0; nb < 4; ++nb) {
            int col = nb * 8 + 2 * t;
            float b20 = smf[F_BB2 + col], b21 = smf[F_BB2 + col + 1];
            if (rowbase + g < B)
                *(float2*)(out + (size_t)(rowbase + g) * 32 + col) =
                    make_float2(acc3[nb][0] + b20, acc3[nb][1] + b21);
            if (rowbase + g + 8 < B)
                *(float2*)(out + (size_t)(rowbase + g + 8) * 32 + col) =
                    make_float2(acc3[nb][2] + b20, acc3[nb][3] + b21);
        }
        __syncwarp();
    }
}

extern "C" void kernel_launch(void* const* d_in, const int* in_sizes, int n_in,
                              void* d_out, int out_size) {
    const float* z_geo    = (const float*)d_in[0];
    const float* z_tex    = (const float*)d_in[1];
    const float* chart_w  = (const float*)d_in[2];
    const float* chart_b  = (const float*)d_in[3];
    const float* router_w = (const float*)d_in[4];
    const float* router_b = (const float*)d_in[5];
    const float* centers  = (const float*)d_in[6];
    const float* tex_w    = (const float*)d_in[7];
    const float* tex_b    = (const float*)d_in[8];
    const float* ln_g     = (const float*)d_in[9];
    const float* ln_b     = (const float*)d_in[10];
    const float* w1       = (const float*)d_in[11];
    const float* b1       = (const float*)d_in[12];
    const float* w2       = (const float*)d_in[13];
    const float* b2       = (const float*)d_in[14];
    float* out = (float*)d_out;

    const int B = in_sizes[0] / 16;
    cudaFuncSetAttribute(topo_decoder_mma8,
                         cudaFuncAttributeMaxDynamicSharedMemorySize, SMEM_BYTES);
    topo_decoder_mma8<<<GRID_CTAS, NT, SMEM_BYTES>>>(
        z_geo, z_tex, chart_w, chart_b, router_w, router_b, centers,
        tex_w, tex_b, ln_g, ln_b, w1, b1, w2, b2, out, B);
}

// round 12
// speedup vs baseline: 7.2554x; 1.2271x over previous
#include <cuda_runtime.h>
#include <cuda_fp16.h>
#include <math.h>
#include <stdint.h>

#define NT 896
#define TILE 448
#define GRID_CTAS 148
#define XSTRIDE 450   // uint2 row stride (TILE+2)

// smem: XI (uint2, fp16 hi only) | B1I/B2I/B3I (uint2, fp16) | misc floats
#define XI_N   (2 * 4 * XSTRIDE)          // uint2 count
#define B1I_N  2560                        // uint2 count
#define B2I_N  1024
#define B3I_N  512
#define MISC_F 512
#define SMEM_BYTES ((XI_N + B1I_N + B2I_N + B3I_N) * 8 + MISC_F * 4)
// misc float offsets
#define F_LNG 0
#define F_LNB 64
#define F_BB1 128
#define F_BB2 192
#define F_CEN 224
#define F_RW  352
#define F_RB  480
#define F_CS  488

// fp16 pack: (v0 -> lo half, v1 -> hi half)
__device__ __forceinline__ uint32_t pack_f16(float v0, float v1) {
    uint32_t h;
    asm("cvt.rn.f16x2.f32 %0, %1, %2;" : "=r"(h) : "f"(v1), "f"(v0));
    return h;
}
__device__ __forceinline__ void mma_f16(float* c, const uint32_t* a, uint32_t b0, uint32_t b1) {
    asm volatile(
        "mma.sync.aligned.m16n8k16.row.col.f32.f16.f16.f32 "
        "{%0,%1,%2,%3}, {%4,%5,%6,%7}, {%8,%9}, {%0,%1,%2,%3};"
        : "+f"(c[0]), "+f"(c[1]), "+f"(c[2]), "+f"(c[3])
        : "r"(a[0]), "r"(a[1]), "r"(a[2]), "r"(a[3]), "r"(b0), "r"(b1));
}
// branchless gelu: A&S 7.1.26 erf (|err| <= 1.5e-7)
__device__ __forceinline__ float gelu_fast(float x) {
    float ax = fabsf(x);
    float y = ax * 0.70710678118654752f;
    float t = __fdividef(1.0f, fmaf(0.3275911f, y, 1.0f));
    float p = fmaf(fmaf(fmaf(fmaf(1.061405429f, t, -1.453152027f), t,
                             1.421413741f), t, -0.284496736f), t, 0.254829592f) * t;
    float e = __expf(-y * y);
    return fmaxf(x, 0.0f) - 0.5f * ax * p * e;
}
__device__ __forceinline__ float b1val(int k, int h,
    const float* __restrict__ chart_w, const float* __restrict__ tex_w,
    const float* __restrict__ chart_b, const float* __restrict__ tex_b) {
    if (k < 128)  return chart_w[(k >> 4) * 1024 + h * 16 + (k & 15)];
    if (k < 144)  return tex_w[h * 16 + (k - 128)];
    if (k < 152)  return chart_b[(k - 144) * 64 + h];
    if (k == 152) return tex_b[h];
    return 0.0f;
}

__global__ __launch_bounds__(NT)
void topo_decoder_mma9(
    const float* __restrict__ z_geo, const float* __restrict__ z_tex,
    const float* __restrict__ chart_w, const float* __restrict__ chart_b,
    const float* __restrict__ router_w, const float* __restrict__ router_b,
    const float* __restrict__ centers,
    const float* __restrict__ tex_w, const float* __restrict__ tex_b,
    const float* __restrict__ ln_g, const float* __restrict__ ln_b,
    const float* __restrict__ w1, const float* __restrict__ b1,
    const float* __restrict__ w2, const float* __restrict__ b2,
    float* __restrict__ out, int B)
{
    extern __shared__ uint2 smu2[];
    uint2* XI  = smu2;
    uint2* B1I = XI + XI_N;
    uint2* B2I = B1I + B1I_N;
    uint2* B3I = B2I + B2I_N;
    float* smf = (float*)(B3I + B3I_N);

    const int tid = threadIdx.x;
    const int wid = tid >> 5;
    const int lane = tid & 31;
    const int g = lane >> 2;
    const int t = lane & 3;

    // ================== one-time weight packing (fp16) ==================
    for (int idx = tid; idx < B1I_N; idx += NT) {
        int tt = idx & 3, n = (idx >> 2) & 63, ks = idx >> 8;
        int k0 = ks * 16 + 2 * tt;
        uint2 q;
        q.x = pack_f16(b1val(k0,     n, chart_w, tex_w, chart_b, tex_b),
                       b1val(k0 + 1, n, chart_w, tex_w, chart_b, tex_b));
        q.y = pack_f16(b1val(k0 + 8, n, chart_w, tex_w, chart_b, tex_b),
                       b1val(k0 + 9, n, chart_w, tex_w, chart_b, tex_b));
        B1I[idx] = q;
    }
    for (int idx = tid; idx < B2I_N; idx += NT) {
        int tt = idx & 3, n = (idx >> 2) & 63, ks = idx >> 8;
        int k0 = ks * 16 + 2 * tt;
        uint2 q;
        q.x = pack_f16(w1[n * 64 + k0],     w1[n * 64 + k0 + 1]);
        q.y = pack_f16(w1[n * 64 + k0 + 8], w1[n * 64 + k0 + 9]);
        B2I[idx] = q;
    }
    for (int idx = tid; idx < B3I_N; idx += NT) {
        int tt = idx & 3, n = (idx >> 2) & 31, ks = idx >> 7;
        int k0 = ks * 16 + 2 * tt;
        uint2 q;
        q.x = pack_f16(w2[n * 64 + k0],     w2[n * 64 + k0 + 1]);
        q.y = pack_f16(w2[n * 64 + k0 + 8], w2[n * 64 + k0 + 9]);
        B3I[idx] = q;
    }
    if (tid < 64) {
        smf[F_LNG + tid] = ln_g[tid];
        smf[F_LNB + tid] = ln_b[tid];
        smf[F_BB1 + tid] = b1[tid];
    }
    if (tid < 32) smf[F_BB2 + tid] = b2[tid];
    if (tid < 128) { smf[F_CEN + tid] = centers[tid]; smf[F_RW + tid] = router_w[tid]; }
    if (tid < 8) {
        smf[F_RB + tid] = router_b[tid];
        float cs = 0.f;
        for (int l = 0; l < 16; ++l) cs = fmaf(centers[tid * 16 + l], centers[tid * 16 + l], cs);
        smf[F_CS + tid] = 1.0f - cs;
    }
    __syncthreads();

    const int nTiles = (B + TILE - 1) / TILE;
    const int xcol = wid * 16;
    const int rl = tid >> 1;          // staging row-in-tile
    const int half = tid & 1;

    for (int tile = blockIdx.x; tile < nTiles; tile += GRID_CTAS) {
        const int rowbase = tile * TILE + xcol;
        const int rawrow = tile * TILE + rl;
        const int srow = rawrow < B ? rawrow : (B - 1);

        // ================== prologue: split router ==================
        float zg[16], w8[8];
        {
            const float4* p = (const float4*)(z_geo + (size_t)srow * 16);
            #pragma unroll
            for (int q = 0; q < 4; ++q) {
                float4 v = p[q];
                zg[q*4+0]=v.x; zg[q*4+1]=v.y; zg[q*4+2]=v.z; zg[q*4+3]=v.w;
            }
            float z_sq = 0.f;
            #pragma unroll
            for (int l = 0; l < 16; ++l) z_sq = fmaf(zg[l], zg[l], z_sq);
            const float one_minus = 1.0f - z_sq;
            const float inv_tau = __fdividef(1.0f, fmaxf(2.0f * fmaxf(one_minus, 0.001f), 0.01f));

            const int cb = half * 4;
            float s[4], mx = -1e30f;
            #pragma unroll
            for (int i = 0; i < 4; ++i) {
                const int c = cb + i;
                float ds = 0.f, dr = 0.f;
                #pragma unroll
                for (int l = 0; l < 16; ++l) {
                    float cv = smf[F_CEN + c * 16 + l];
                    float d = zg[l] - cv;
                    ds = fmaf(d, d, ds);
                    dr = fmaf(zg[l], smf[F_RW + c * 16 + l], dr);
                }
                float denom = one_minus * smf[F_CS + c];
                float tt2 = fmaxf(2.0f * __fdividef(ds, denom + 0.001f), 0.001f);
                float rad = tt2 * (tt2 + 2.0f);
                float sq = rad * rsqrtf(rad);
                float dist = __logf(1.0f + tt2 + sq);
                s[i] = (-dist + 0.1f * (dr + smf[F_RB + c])) * inv_tau;
                mx = fmaxf(mx, s[i]);
            }
            mx = fmaxf(mx, __shfl_xor_sync(~0u, mx, 1));
            float wloc[4], psum = 0.f;
            #pragma unroll
            for (int i = 0; i < 4; ++i) { wloc[i] = __expf(s[i] - mx); psum += wloc[i]; }
            float ssum = psum + __shfl_xor_sync(~0u, psum, 1);
            const float inv_sum = __fdividef(1.0f, ssum);
            #pragma unroll
            for (int i = 0; i < 4; ++i) {
                float wi = wloc[i] * inv_sum;
                w8[cb + i] = wi;
                w8[(cb ^ 4) + i] = __shfl_xor_sync(~0u, wi, 1);
            }
            if (rawrow < B) {
                float* rout = out + (size_t)B * 32 + (size_t)rawrow * 8 + cb;
                *(float4*)rout = make_float4(w8[cb], w8[cb+1], w8[cb+2], w8[cb+3]);
            }
        }
        // prefetch zt slice this thread stages (ks 8)
        float4 ztA = *(const float4*)(z_tex + (size_t)srow * 16 + 4 * half);
        float4 ztB = *(const float4*)(z_tex + (size_t)srow * 16 + 4 * half + 8);
        // ks9 staging operands (avoid dynamic w8 indexing)
        const float wa0 = half ? w8[4] : w8[0];
        const float wa1 = half ? w8[5] : w8[1];
        const float wb0 = half ? w8[6] : w8[2];
        const float wb1 = half ? w8[7] : w8[3];

        // ================== GEMM1: 2-slot ring over ks (fp16, A hi only) ==========
        float acc[8][4];
        #pragma unroll
        for (int nb = 0; nb < 8; ++nb)
            #pragma unroll
            for (int j = 0; j < 4; ++j) acc[nb][j] = 0.f;

        #pragma unroll
        for (int p = 0; p < 10; ++p) {
            const int slot = p & 1;
            // ---- stage ks p (each thread: tt = 2*half, 2*half+1) ----
            if (p < 8) {
                const float wc = w8[p];
                #pragma unroll
                for (int j = 0; j < 2; ++j) {
                    const int tt = 2 * half + j;
                    uint2 q;
                    q.x = pack_f16(wc * zg[2*tt],   wc * zg[2*tt+1]);
                    q.y = pack_f16(wc * zg[2*tt+8], wc * zg[2*tt+9]);
                    XI[(slot * 4 + tt) * XSTRIDE + rl] = q;
                }
            } else if (p == 8) {
                {
                    uint2 q;
                    q.x = pack_f16(ztA.x, ztA.y);
                    q.y = pack_f16(ztB.x, ztB.y);
                    XI[(slot * 4 + 2 * half) * XSTRIDE + rl] = q;
                }
                {
                    uint2 q;
                    q.x = pack_f16(ztA.z, ztA.w);
                    q.y = pack_f16(ztB.z, ztB.w);
                    XI[(slot * 4 + 2 * half + 1) * XSTRIDE + rl] = q;
                }
            } else {
                {
                    uint2 q;
                    q.x = pack_f16(wa0, wa1);
                    q.y = pack_f16(half ? 0.0f : 1.0f, 0.0f);
                    XI[(slot * 4 + 2 * half) * XSTRIDE + rl] = q;
                }
                {
                    uint2 q;
                    q.x = pack_f16(wb0, wb1);
                    q.y = 0u;
                    XI[(slot * 4 + 2 * half + 1) * XSTRIDE + rl] = q;
                }
            }
            __syncwarp();
            // ---- MMA ks p ----
            uint2 qa = XI[(slot * 4 + t) * XSTRIDE + xcol + g];
            uint2 qb = XI[(slot * 4 + t) * XSTRIDE + xcol + g + 8];
            uint32_t ah[4] = { qa.x, qb.x, qa.y, qb.y };
            #pragma unroll
            for (int nb = 0; nb < 8; ++nb) {
                uint2 qB = B1I[(p * 64 + nb * 8 + g) * 4 + t];
                mma_f16(acc[nb], ah, qB.x, qB.y);
            }
        }
        __syncwarp();

        // ================== epilogue 1: LayerNorm + GELU -> A2 frags =====
        uint32_t a2h[4][4];
        {
            float sum0 = 0.f, sum1 = 0.f, sq0 = 0.f, sq1 = 0.f;
            #pragma unroll
            for (int nb = 0; nb < 8; ++nb) {
                sum0 += acc[nb][0] + acc[nb][1];
                sum1 += acc[nb][2] + acc[nb][3];
                sq0 = fmaf(acc[nb][0], acc[nb][0], sq0); sq0 = fmaf(acc[nb][1], acc[nb][1], sq0);
                sq1 = fmaf(acc[nb][2], acc[nb][2], sq1); sq1 = fmaf(acc[nb][3], acc[nb][3], sq1);
            }
            sum0 += __shfl_xor_sync(~0u, sum0, 1); sum0 += __shfl_xor_sync(~0u, sum0, 2);
            sum1 += __shfl_xor_sync(~0u, sum1, 1); sum1 += __shfl_xor_sync(~0u, sum1, 2);
            sq0  += __shfl_xor_sync(~0u, sq0, 1);  sq0  += __shfl_xor_sync(~0u, sq0, 2);
            sq1  += __shfl_xor_sync(~0u, sq1, 1);  sq1  += __shfl_xor_sync(~0u, sq1, 2);
            const float mu0 = sum0 * (1.0f / 64.0f), mu1 = sum1 * (1.0f / 64.0f);
            const float rstd0 = rsqrtf(fmaf(-mu0, mu0, sq0 * (1.0f / 64.0f)) + 1e-5f);
            const float rstd1 = rsqrtf(fmaf(-mu1, mu1, sq1 * (1.0f / 64.0f)) + 1e-5f);

            #pragma unroll
            for (int ks = 0; ks < 4; ++ks) {
                float v00, v01, v10, v11, v20, v21, v30, v31;
                {
                    int nb = 2 * ks;
                    int col = nb * 8 + 2 * t;
                    float g0 = smf[F_LNG + col], g1 = smf[F_LNG + col + 1];
                    float e0 = smf[F_LNB + col], e1 = smf[F_LNB + col + 1];
                    v00 = gelu_fast(fmaf((acc[nb][0] - mu0) * rstd0, g0, e0));
                    v01 = gelu_fast(fmaf((acc[nb][1] - mu0) * rstd0, g1, e1));
                    v10 = gelu_fast(fmaf((acc[nb][2] - mu1) * rstd1, g0, e0));
                    v11 = gelu_fast(fmaf((acc[nb][3] - mu1) * rstd1, g1, e1));
                }
                {
                    int nb = 2 * ks + 1;
                    int col = nb * 8 + 2 * t;
                    float g0 = smf[F_LNG + col], g1 = smf[F_LNG + col + 1];
                    float e0 = smf[F_LNB + col], e1 = smf[F_LNB + col + 1];
                    v20 = gelu_fast(fmaf((acc[nb][0] - mu0) * rstd0, g0, e0));
                    v21 = gelu_fast(fmaf((acc[nb][1] - mu0) * rstd0, g1, e1));
                    v30 = gelu_fast(fmaf((acc[nb][2] - mu1) * rstd1, g0, e0));
                    v31 = gelu_fast(fmaf((acc[nb][3] - mu1) * rstd1, g1, e1));
                }
                a2h[ks][0] = pack_f16(v00, v01);
                a2h[ks][1] = pack_f16(v10, v11);
                a2h[ks][2] = pack_f16(v20, v21);
                a2h[ks][3] = pack_f16(v30, v31);
            }
        }

        // ================== GEMM2: [16x64] x [64x64] (fp16, A hi only) ============
        #pragma unroll
        for (int nb = 0; nb < 8; ++nb)
            #pragma unroll
            for (int j = 0; j < 4; ++j) acc[nb][j] = 0.f;
        #pragma unroll
        for (int ks = 0; ks < 4; ++ks) {
            #pragma unroll
            for (int nb = 0; nb < 8; ++nb) {
                uint2 qB = B2I[(ks * 64 + nb * 8 + g) * 4 + t];
                mma_f16(acc[nb], a2h[ks], qB.x, qB.y);
            }
        }

        // ================== epilogue 2: +b1, GELU -> A3 frags ===========
        uint32_t a3h[4][4];
        #pragma unroll
        for (int ks = 0; ks < 4; ++ks) {
            float v00, v01, v10, v11, v20, v21, v30, v31;
            {
                int nb = 2 * ks;
                int col = nb * 8 + 2 * t;
                float b0 = smf[F_BB1 + col], bb1v = smf[F_BB1 + col + 1];
                v00 = gelu_fast(acc[nb][0] + b0);
                v01 = gelu_fast(acc[nb][1] + bb1v);
                v10 = gelu_fast(acc[nb][2] + b0);
                v11 = gelu_fast(acc[nb][3] + bb1v);
            }
            {
                int nb = 2 * ks + 1;
                int col = nb * 8 + 2 * t;
                float b0 = smf[F_BB1 + col], bb1v = smf[F_BB1 + col + 1];
                v20 = gelu_fast(acc[nb][0] + b0);
                v21 = gelu_fast(acc[nb][1] + bb1v);
                v30 = gelu_fast(acc[nb][2] + b0);
                v31 = gelu_fast(acc[nb][3] + bb1v);
            }
            a3h[ks][0] = pack_f16(v00, v01);
            a3h[ks][1] = pack_f16(v10, v11);
            a3h[ks][2] = pack_f16(v20, v21);
            a3h[ks][3] = pack_f16(v30, v31);
        }

        // ================== GEMM3: [16x64] x [64x32] (fp16, A hi only) ============
        float acc3[4][4];
        #pragma unroll
        for (int nb = 0; nb < 4; ++nb)
            #pragma unroll
            for (int j = 0; j < 4; ++j) acc3[nb][j] = 0.f;
        #pragma unroll
        for (int ks = 0; ks < 4; ++ks) {
            #pragma unroll
            for (int nb = 0; nb < 4; ++nb) {
                uint2 qB = B3I[(ks * 32 + nb * 8 + g) * 4 + t];
                mma_f16(acc3[nb], a3h[ks], qB.x, qB.y);
            }
        }

        // ================== epilogue 3: +b2 -> out ==================
        #pragma unroll
        for (int nb = 0; nb < 4; ++nb) {
            int col = nb * 8 + 2 * t;
            float b20 = smf[F_BB2 + col], b21 = smf[F_BB2 + col + 1];
            if (rowbase + g < B)
                *(float2*)(out + (size_t)(rowbase + g) * 32 + col) =
                    make_float2(acc3[nb][0] + b20, acc3[nb][1] + b21);
            if (rowbase + g + 8 < B)
                *(float2*)(out + (size_t)(rowbase + g + 8) * 32 + col) =
                    make_float2(acc3[nb][2] + b20, acc3[nb][3] + b21);
        }
        __syncwarp();
    }
}

extern "C" void kernel_launch(void* const* d_in, const int* in_sizes, int n_in,
                              void* d_out, int out_size) {
    const float* z_geo    = (const float*)d_in[0];
    const float* z_tex    = (const float*)d_in[1];
    const float* chart_w  = (const float*)d_in[2];
    const float* chart_b  = (const float*)d_in[3];
    const float* router_w = (const float*)d_in[4];
    const float* router_b = (const float*)d_in[5];
    const float* centers  = (const float*)d_in[6];
    const float* tex_w    = (const float*)d_in[7];
    const float* tex_b    = (const float*)d_in[8];
    const float* ln_g     = (const float*)d_in[9];
    const float* ln_b     = (const float*)d_in[10];
    const float* w1       = (const float*)d_in[11];
    const float* b1       = (const float*)d_in[12];
    const float* w2       = (const float*)d_in[13];
    const float* b2       = (const float*)d_in[14];
    float* out = (float*)d_out;

    const int B = in_sizes[0] / 16;
    cudaFuncSetAttribute(topo_decoder_mma9,
                         cudaFuncAttributeMaxDynamicSharedMemorySize, SMEM_BYTES);
    topo_decoder_mma9<<<GRID_CTAS, NT, SMEM_BYTES>>>(
        z_geo, z_tex, chart_w, chart_b, router_w, router_b, centers,
        tex_w, tex_b, ln_g, ln_b, w1, b1, w2, b2, out, B);
}

// round 13
// speedup vs baseline: 7.9153x; 1.0910x over previous
#include <cuda_runtime.h>
#include <cuda_fp16.h>
#include <math.h>
#include <stdint.h>

#define NT 896
#define TILE 448
#define GRID_CTAS 152
#define XSTRIDE 450   // uint2 row stride (TILE+2)

// smem: XI (uint2, fp16) | B1I/B2I/B3I (uint2, fp16) | misc floats
#define XI_N   (2 * 4 * XSTRIDE)          // uint2 count
#define B1I_N  2560                        // uint2 count
#define B2I_N  1024
#define B3I_N  512
#define MISC_F 512
#define SMEM_BYTES ((XI_N + B1I_N + B2I_N + B3I_N) * 8 + MISC_F * 4)
// misc float offsets
#define F_LNG 0
#define F_LNB 64
#define F_BB1 128
#define F_BB2 192
#define F_CEN 224
#define F_RW  352
#define F_RB  480
#define F_CS  488

// fp16 pack: (v0 -> lo half, v1 -> hi half)
__device__ __forceinline__ uint32_t pack_f16(float v0, float v1) {
    uint32_t h;
    asm("cvt.rn.f16x2.f32 %0, %1, %2;" : "=r"(h) : "f"(v1), "f"(v0));
    return h;
}
__device__ __forceinline__ uint32_t h2mul(uint32_t a, uint32_t b) {
    uint32_t d;
    asm("mul.rn.f16x2 %0, %1, %2;" : "=r"(d) : "r"(a), "r"(b));
    return d;
}
__device__ __forceinline__ void mma_f16(float* c, const uint32_t* a, uint32_t b0, uint32_t b1) {
    asm volatile(
        "mma.sync.aligned.m16n8k16.row.col.f32.f16.f16.f32 "
        "{%0,%1,%2,%3}, {%4,%5,%6,%7}, {%8,%9}, {%0,%1,%2,%3};"
        : "+f"(c[0]), "+f"(c[1]), "+f"(c[2]), "+f"(c[3])
        : "r"(a[0]), "r"(a[1]), "r"(a[2]), "r"(a[3]), "r"(b0), "r"(b1));
}
// branchless gelu: A&S 7.1.25 3-term erf (|err| <= 2.5e-5)
__device__ __forceinline__ float gelu_fast(float x) {
    float ax = fabsf(x);
    float y = ax * 0.70710678118654752f;
    float t = __fdividef(1.0f, fmaf(0.47047f, y, 1.0f));
    float p = fmaf(fmaf(0.7478556f, t, -0.0958798f), t, 0.3480242f) * t;
    float e = __expf(-y * y);
    return fmaxf(x, 0.0f) - 0.5f * ax * p * e;
}
__device__ __forceinline__ float b1val(int k, int h,
    const float* __restrict__ chart_w, const float* __restrict__ tex_w,
    const float* __restrict__ chart_b, const float* __restrict__ tex_b) {
    if (k < 128)  return chart_w[(k >> 4) * 1024 + h * 16 + (k & 15)];
    if (k < 144)  return tex_w[h * 16 + (k - 128)];
    if (k < 152)  return chart_b[(k - 144) * 64 + h];
    if (k == 152) return tex_b[h];
    return 0.0f;
}

__global__ __launch_bounds__(NT)
void topo_decoder_mma10(
    const float* __restrict__ z_geo, const float* __restrict__ z_tex,
    const float* __restrict__ chart_w, const float* __restrict__ chart_b,
    const float* __restrict__ router_w, const float* __restrict__ router_b,
    const float* __restrict__ centers,
    const float* __restrict__ tex_w, const float* __restrict__ tex_b,
    const float* __restrict__ ln_g, const float* __restrict__ ln_b,
    const float* __restrict__ w1, const float* __restrict__ b1,
    const float* __restrict__ w2, const float* __restrict__ b2,
    float* __restrict__ out, int B)
{
    extern __shared__ uint2 smu2[];
    uint2* XI  = smu2;
    uint2* B1I = XI + XI_N;
    uint2* B2I = B1I + B1I_N;
    uint2* B3I = B2I + B2I_N;
    float* smf = (float*)(B3I + B3I_N);

    const int tid = threadIdx.x;
    const int wid = tid >> 5;
    const int lane = tid & 31;
    const int g = lane >> 2;
    const int t = lane & 3;

    // ================== one-time weight packing (fp16) ==================
    for (int idx = tid; idx < B1I_N; idx += NT) {
        int tt = idx & 3, n = (idx >> 2) & 63, ks = idx >> 8;
        int k0 = ks * 16 + 2 * tt;
        uint2 q;
        q.x = pack_f16(b1val(k0,     n, chart_w, tex_w, chart_b, tex_b),
                       b1val(k0 + 1, n, chart_w, tex_w, chart_b, tex_b));
        q.y = pack_f16(b1val(k0 + 8, n, chart_w, tex_w, chart_b, tex_b),
                       b1val(k0 + 9, n, chart_w, tex_w, chart_b, tex_b));
        B1I[idx] = q;
    }
    for (int idx = tid; idx < B2I_N; idx += NT) {
        int tt = idx & 3, n = (idx >> 2) & 63, ks = idx >> 8;
        int k0 = ks * 16 + 2 * tt;
        uint2 q;
        q.x = pack_f16(w1[n * 64 + k0],     w1[n * 64 + k0 + 1]);
        q.y = pack_f16(w1[n * 64 + k0 + 8], w1[n * 64 + k0 + 9]);
        B2I[idx] = q;
    }
    for (int idx = tid; idx < B3I_N; idx += NT) {
        int tt = idx & 3, n = (idx >> 2) & 31, ks = idx >> 7;
        int k0 = ks * 16 + 2 * tt;
        uint2 q;
        q.x = pack_f16(w2[n * 64 + k0],     w2[n * 64 + k0 + 1]);
        q.y = pack_f16(w2[n * 64 + k0 + 8], w2[n * 64 + k0 + 9]);
        B3I[idx] = q;
    }
    if (tid < 64) {
        smf[F_LNG + tid] = ln_g[tid];
        smf[F_LNB + tid] = ln_b[tid];
        smf[F_BB1 + tid] = b1[tid];
    }
    if (tid < 32) smf[F_BB2 + tid] = b2[tid];
    if (tid < 128) { smf[F_CEN + tid] = centers[tid]; smf[F_RW + tid] = router_w[tid]; }
    if (tid < 8) {
        smf[F_RB + tid] = router_b[tid];
        float cs = 0.f;
        for (int l = 0; l < 16; ++l) cs = fmaf(centers[tid * 16 + l], centers[tid * 16 + l], cs);
        smf[F_CS + tid] = 1.0f - cs;
    }
    __syncthreads();

    const int nTiles = (B + TILE - 1) / TILE;
    const int xcol = wid * 16;
    const int rl = tid >> 1;          // staging row-in-tile
    const int half = tid & 1;

    for (int tile = blockIdx.x; tile < nTiles; tile += GRID_CTAS) {
        const int rowbase = tile * TILE + xcol;
        const int rawrow = tile * TILE + rl;
        const int srow = rawrow < B ? rawrow : (B - 1);

        // ================== prologue: split router ==================
        uint32_t zgh0, zgh1, zgh2, zgh3;   // this thread's zg slice, fp16x2
        float w8[8];
        {
            float zg[16];
            const float4* p = (const float4*)(z_geo + (size_t)srow * 16);
            #pragma unroll
            for (int q = 0; q < 4; ++q) {
                float4 v = p[q];
                zg[q*4+0]=v.x; zg[q*4+1]=v.y; zg[q*4+2]=v.z; zg[q*4+3]=v.w;
            }
            float z_sq = 0.f;
            #pragma unroll
            for (int l = 0; l < 16; ++l) z_sq = fmaf(zg[l], zg[l], z_sq);
            const float one_minus = 1.0f - z_sq;
            const float inv_tau = __fdividef(1.0f, fmaxf(2.0f * fmaxf(one_minus, 0.001f), 0.01f));

            const int cb = half * 4;
            float s[4], mx = -1e30f;
            #pragma unroll
            for (int i = 0; i < 4; ++i) {
                const int c = cb + i;
                float ds = 0.f, dr = 0.f;
                #pragma unroll
                for (int l = 0; l < 16; ++l) {
                    float cv = smf[F_CEN + c * 16 + l];
                    float d = zg[l] - cv;
                    ds = fmaf(d, d, ds);
                    dr = fmaf(zg[l], smf[F_RW + c * 16 + l], dr);
                }
                float denom = one_minus * smf[F_CS + c];
                float tt2 = fmaxf(2.0f * __fdividef(ds, denom + 0.001f), 0.001f);
                float rad = tt2 * (tt2 + 2.0f);
                float sq = rad * rsqrtf(rad);
                float dist = __logf(1.0f + tt2 + sq);
                s[i] = (-dist + 0.1f * (dr + smf[F_RB + c])) * inv_tau;
                mx = fmaxf(mx, s[i]);
            }
            mx = fmaxf(mx, __shfl_xor_sync(~0u, mx, 1));
            float wloc[4], psum = 0.f;
            #pragma unroll
            for (int i = 0; i < 4; ++i) { wloc[i] = __expf(s[i] - mx); psum += wloc[i]; }
            float ssum = psum + __shfl_xor_sync(~0u, psum, 1);
            const float inv_sum = __fdividef(1.0f, ssum);
            #pragma unroll
            for (int i = 0; i < 4; ++i) {
                float wi = wloc[i] * inv_sum;
                w8[cb + i] = wi;
                w8[(cb ^ 4) + i] = __shfl_xor_sync(~0u, wi, 1);
            }
            if (rawrow < B) {
                float* rout = out + (size_t)B * 32 + (size_t)rawrow * 8 + cb;
                *(float4*)rout = make_float4(w8[cb], w8[cb+1], w8[cb+2], w8[cb+3]);
            }
            // this thread's staged zg pairs: tt = 2*half(+1) -> zg[4h..4h+3], zg[4h+8..4h+11]
            zgh0 = pack_f16(zg[4*half + 0], zg[4*half + 1]);
            zgh1 = pack_f16(zg[4*half + 2], zg[4*half + 3]);
            zgh2 = pack_f16(zg[4*half + 8], zg[4*half + 9]);
            zgh3 = pack_f16(zg[4*half + 10], zg[4*half + 11]);
        }
        // prefetch zt slice this thread stages (ks 8)
        float4 ztA = *(const float4*)(z_tex + (size_t)srow * 16 + 4 * half);
        float4 ztB = *(const float4*)(z_tex + (size_t)srow * 16 + 4 * half + 8);
        // ks9 staging operands (avoid dynamic w8 indexing)
        const float wa0 = half ? w8[4] : w8[0];
        const float wa1 = half ? w8[5] : w8[1];
        const float wb0 = half ? w8[6] : w8[2];
        const float wb1 = half ? w8[7] : w8[3];

        // ================== GEMM1: 2-slot ring over ks (fp16) ==========
        float acc[8][4];
        #pragma unroll
        for (int nb = 0; nb < 8; ++nb)
            #pragma unroll
            for (int j = 0; j < 4; ++j) acc[nb][j] = 0.f;

        #pragma unroll
        for (int p = 0; p < 10; ++p) {
            const int slot = p & 1;
            // ---- stage ks p (each thread: tt = 2*half, 2*half+1) ----
            if (p < 8) {
                const uint32_t wch = pack_f16(w8[p], w8[p]);
                uint2 q0, q1;
                q0.x = h2mul(wch, zgh0); q0.y = h2mul(wch, zgh2);
                q1.x = h2mul(wch, zgh1); q1.y = h2mul(wch, zgh3);
                XI[(slot * 4 + 2 * half)     * XSTRIDE + rl] = q0;
                XI[(slot * 4 + 2 * half + 1) * XSTRIDE + rl] = q1;
            } else if (p == 8) {
                uint2 q0, q1;
                q0.x = pack_f16(ztA.x, ztA.y); q0.y = pack_f16(ztB.x, ztB.y);
                q1.x = pack_f16(ztA.z, ztA.w); q1.y = pack_f16(ztB.z, ztB.w);
                XI[(slot * 4 + 2 * half)     * XSTRIDE + rl] = q0;
                XI[(slot * 4 + 2 * half + 1) * XSTRIDE + rl] = q1;
            } else {
                uint2 q0, q1;
                q0.x = pack_f16(wa0, wa1);
                q0.y = pack_f16(half ? 0.0f : 1.0f, 0.0f);
                q1.x = pack_f16(wb0, wb1);
                q1.y = 0u;
                XI[(slot * 4 + 2 * half)     * XSTRIDE + rl] = q0;
                XI[(slot * 4 + 2 * half + 1) * XSTRIDE + rl] = q1;
            }
            __syncwarp();
            // ---- MMA ks p ----
            uint2 qa = XI[(slot * 4 + t) * XSTRIDE + xcol + g];
            uint2 qb = XI[(slot * 4 + t) * XSTRIDE + xcol + g + 8];
            uint32_t ah[4] = { qa.x, qb.x, qa.y, qb.y };
            #pragma unroll
            for (int nb = 0; nb < 8; ++nb) {
                uint2 qB = B1I[(p * 64 + nb * 8 + g) * 4 + t];
                mma_f16(acc[nb], ah, qB.x, qB.y);
            }
        }
        __syncwarp();

        // ================== epilogue 1: LayerNorm + GELU -> A2 frags =====
        uint32_t a2h[4][4];
        {
            float sum0 = 0.f, sum1 = 0.f, sq0 = 0.f, sq1 = 0.f;
            #pragma unroll
            for (int nb = 0; nb < 8; ++nb) {
                sum0 += acc[nb][0] + acc[nb][1];
                sum1 += acc[nb][2] + acc[nb][3];
                sq0 = fmaf(acc[nb][0], acc[nb][0], sq0); sq0 = fmaf(acc[nb][1], acc[nb][1], sq0);
                sq1 = fmaf(acc[nb][2], acc[nb][2], sq1); sq1 = fmaf(acc[nb][3], acc[nb][3], sq1);
            }
            sum0 += __shfl_xor_sync(~0u, sum0, 1); sum0 += __shfl_xor_sync(~0u, sum0, 2);
            sum1 += __shfl_xor_sync(~0u, sum1, 1); sum1 += __shfl_xor_sync(~0u, sum1, 2);
            sq0  += __shfl_xor_sync(~0u, sq0, 1);  sq0  += __shfl_xor_sync(~0u, sq0, 2);
            sq1  += __shfl_xor_sync(~0u, sq1, 1);  sq1  += __shfl_xor_sync(~0u, sq1, 2);
            const float mu0 = sum0 * (1.0f / 64.0f), mu1 = sum1 * (1.0f / 64.0f);
            const float rstd0 = rsqrtf(fmaf(-mu0, mu0, sq0 * (1.0f / 64.0f)) + 1e-5f);
            const float rstd1 = rsqrtf(fmaf(-mu1, mu1, sq1 * (1.0f / 64.0f)) + 1e-5f);

            #pragma unroll
            for (int ks = 0; ks < 4; ++ks) {
                float v00, v01, v10, v11, v20, v21, v30, v31;
                {
                    int nb = 2 * ks;
                    int col = nb * 8 + 2 * t;
                    float g0 = smf[F_LNG + col], g1 = smf[F_LNG + col + 1];
                    float e0 = smf[F_LNB + col], e1 = smf[F_LNB + col + 1];
                    v00 = gelu_fast(fmaf((acc[nb][0] - mu0) * rstd0, g0, e0));
                    v01 = gelu_fast(fmaf((acc[nb][1] - mu0) * rstd0, g1, e1));
                    v10 = gelu_fast(fmaf((acc[nb][2] - mu1) * rstd1, g0, e0));
                    v11 = gelu_fast(fmaf((acc[nb][3] - mu1) * rstd1, g1, e1));
                }
                {
                    int nb = 2 * ks + 1;
                    int col = nb * 8 + 2 * t;
                    float g0 = smf[F_LNG + col], g1 = smf[F_LNG + col + 1];
                    float e0 = smf[F_LNB + col], e1 = smf[F_LNB + col + 1];
                    v20 = gelu_fast(fmaf((acc[nb][0] - mu0) * rstd0, g0, e0));
                    v21 = gelu_fast(fmaf((acc[nb][1] - mu0) * rstd0, g1, e1));
                    v30 = gelu_fast(fmaf((acc[nb][2] - mu1) * rstd1, g0, e0));
                    v31 = gelu_fast(fmaf((acc[nb][3] - mu1) * rstd1, g1, e1));
                }
                a2h[ks][0] = pack_f16(v00, v01);
                a2h[ks][1] = pack_f16(v10, v11);
                a2h[ks][2] = pack_f16(v20, v21);
                a2h[ks][3] = pack_f16(v30, v31);
            }
        }

        // ================== GEMM2: [16x64] x [64x64] (fp16) ============
        #pragma unroll
        for (int nb = 0; nb < 8; ++nb)
            #pragma unroll
            for (int j = 0; j < 4; ++j) acc[nb][j] = 0.f;
        #pragma unroll
        for (int ks = 0; ks < 4; ++ks) {
            #pragma unroll
            for (int nb = 0; nb < 8; ++nb) {
                uint2 qB = B2I[(ks * 64 + nb * 8 + g) * 4 + t];
                mma_f16(acc[nb], a2h[ks], qB.x, qB.y);
            }
        }

        // ================== epilogue 2: +b1, GELU -> A3 frags ===========
        uint32_t a3h[4][4];
        #pragma unroll
        for (int ks = 0; ks < 4; ++ks) {
            float v00, v01, v10, v11, v20, v21, v30, v31;
            {
                int nb = 2 * ks;
                int col = nb * 8 + 2 * t;
                float b0 = smf[F_BB1 + col], bb1v = smf[F_BB1 + col + 1];
                v00 = gelu_fast(acc[nb][0] + b0);
                v01 = gelu_fast(acc[nb][1] + bb1v);
                v10 = gelu_fast(acc[nb][2] + b0);
                v11 = gelu_fast(acc[nb][3] + bb1v);
            }
            {
                int nb = 2 * ks + 1;
                int col = nb * 8 + 2 * t;
                float b0 = smf[F_BB1 + col], bb1v = smf[F_BB1 + col + 1];
                v20 = gelu_fast(acc[nb][0] + b0);
                v21 = gelu_fast(acc[nb][1] + bb1v);
                v30 = gelu_fast(acc[nb][2] + b0);
                v31 = gelu_fast(acc[nb][3] + bb1v);
            }
            a3h[ks][0] = pack_f16(v00, v01);
            a3h[ks][1] = pack_f16(v10, v11);
            a3h[ks][2] = pack_f16(v20, v21);
            a3h[ks][3] = pack_f16(v30, v31);
        }

        // ================== GEMM3: [16x64] x [64x32] (fp16) ============
        float acc3[4][4];
        #pragma unroll
        for (int nb = 0; nb < 4; ++nb)
            #pragma unroll
            for (int j = 0; j < 4; ++j) acc3[nb][j] = 0.f;
        #pragma unroll
        for (int ks = 0; ks < 4; ++ks) {
            #pragma unroll
            for (int nb = 0; nb < 4; ++nb) {
                uint2 qB = B3I[(ks * 32 + nb * 8 + g) * 4 + t];
                mma_f16(acc3[nb], a3h[ks], qB.x, qB.y);
            }
        }

        // ================== epilogue 3: +b2 -> out ==================
        #pragma unroll
        for (int nb = 0; nb < 4; ++nb) {
            int col = nb * 8 + 2 * t;
            float b20 = smf[F_BB2 + col], b21 = smf[F_BB2 + col + 1];
            if (rowbase + g < B)
                *(float2*)(out + (size_t)(rowbase + g) * 32 + col) =
                    make_float2(acc3[nb][0] + b20, acc3[nb][1] + b21);
            if (rowbase + g + 8 < B)
                *(float2*)(out + (size_t)(rowbase + g + 8) * 32 + col) =
                    make_float2(acc3[nb][2] + b20, acc3[nb][3] + b21);
        }
        __syncwarp();
    }
}

extern "C" void kernel_launch(void* const* d_in, const int* in_sizes, int n_in,
                              void* d_out, int out_size) {
    const float* z_geo    = (const float*)d_in[0];
    const float* z_tex    = (const float*)d_in[1];
    const float* chart_w  = (const float*)d_in[2];
    const float* chart_b  = (const float*)d_in[3];
    const float* router_w = (const float*)d_in[4];
    const float* router_b = (const float*)d_in[5];
    const float* centers  = (const float*)d_in[6];
    const float* tex_w    = (const float*)d_in[7];
    const float* tex_b    = (const float*)d_in[8];
    const float* ln_g     = (const float*)d_in[9];
    const float* ln_b     = (const float*)d_in[10];
    const float* w1       = (const float*)d_in[11];
    const float* b1       = (const float*)d_in[12];
    const float* w2       = (const float*)d_in[13];
    const float* b2       = (const float*)d_in[14];
    float* out = (float*)d_out;

    const int B = in_sizes[0] / 16;
    cudaFuncSetAttribute(topo_decoder_mma10,
                         cudaFuncAttributeMaxDynamicSharedMemorySize, SMEM_BYTES);
    topo_decoder_mma10<<<GRID_CTAS, NT, SMEM_BYTES>>>(
        z_geo, z_tex, chart_w, chart_b, router_w, router_b, centers,
        tex_w, tex_b, ln_g, ln_b, w1, b1, w2, b2, out, B);
}

// round 14
// speedup vs baseline: 9.3491x; 1.1811x over previous
#include <cuda_runtime.h>
#include <cuda_fp16.h>
#include <math.h>
#include <stdint.h>

#define NT 896
#define TILE 448
#define GRID_CTAS 152
#define XSTRIDE 450   // uint2 row stride (TILE+2)

// smem: XI (uint2, fp16) | B1I/B2I/B3I (uint2, fp16) | misc floats
#define XI_N   (2 * 4 * XSTRIDE)          // uint2 count
#define B1I_N  2560                        // uint2 count
#define B2I_N  1024
#define B3I_N  512
#define MISC_F 544
#define SMEM_BYTES ((XI_N + B1I_N + B2I_N + B3I_N) * 8 + MISC_F * 4)
// misc float offsets
#define F_LNG  0
#define F_LNB  64
#define F_BB1  128
#define F_BB2  192
#define F_CEN  224
#define F_RW   352
#define F_RB   480
#define F_CS   488
#define F_BB1H 496   // 32 x uint32: b1 pairs packed fp16x2

// fp16 pack: (v0 -> lo half, v1 -> hi half)
__device__ __forceinline__ uint32_t pack_f16(float v0, float v1) {
    uint32_t h;
    asm("cvt.rn.f16x2.f32 %0, %1, %2;" : "=r"(h) : "f"(v1), "f"(v0));
    return h;
}
__device__ __forceinline__ uint32_t h2mul(uint32_t a, uint32_t b) {
    uint32_t d;
    asm("mul.rn.f16x2 %0, %1, %2;" : "=r"(d) : "r"(a), "r"(b));
    return d;
}
__device__ __forceinline__ uint32_t h2add(uint32_t a, uint32_t b) {
    uint32_t d;
    asm("add.rn.f16x2 %0, %1, %2;" : "=r"(d) : "r"(a), "r"(b));
    return d;
}
__device__ __forceinline__ uint32_t h2fma(uint32_t a, uint32_t b, uint32_t c) {
    uint32_t d;
    asm("fma.rn.f16x2 %0, %1, %2, %3;" : "=r"(d) : "r"(a), "r"(b), "r"(c));
    return d;
}
// tanh-form gelu on a packed fp16x2 pair: 0.5x(1+tanh(x(c0+c1 x^2)))
#define GH_C0 0x3A623A62u   // half2(0.7978846)
#define GH_C1 0x28910891u   // placeholder (set at runtime)
__device__ __forceinline__ uint32_t gelu_h2(uint32_t x, uint32_t c0, uint32_t c1, uint32_t chalf) {
    uint32_t x2 = h2mul(x, x);
    uint32_t p  = h2fma(c1, x2, c0);
    uint32_t inner = h2mul(x, p);
    uint32_t th;
    asm("tanh.approx.f16x2 %0, %1;" : "=r"(th) : "r"(inner));
    uint32_t q = h2fma(th, chalf, chalf);   // 0.5*tanh + 0.5
    return h2mul(x, q);
}
__device__ __forceinline__ void mma_f16(float* c, const uint32_t* a, uint32_t b0, uint32_t b1) {
    asm volatile(
        "mma.sync.aligned.m16n8k16.row.col.f32.f16.f16.f32 "
        "{%0,%1,%2,%3}, {%4,%5,%6,%7}, {%8,%9}, {%0,%1,%2,%3};"
        : "+f"(c[0]), "+f"(c[1]), "+f"(c[2]), "+f"(c[3])
        : "r"(a[0]), "r"(a[1]), "r"(a[2]), "r"(a[3]), "r"(b0), "r"(b1));
}
__device__ __forceinline__ float b1val(int k, int h,
    const float* __restrict__ chart_w, const float* __restrict__ tex_w,
    const float* __restrict__ chart_b, const float* __restrict__ tex_b) {
    if (k < 128)  return chart_w[(k >> 4) * 1024 + h * 16 + (k & 15)];
    if (k < 144)  return tex_w[h * 16 + (k - 128)];
    if (k < 152)  return chart_b[(k - 144) * 64 + h];
    if (k == 152) return tex_b[h];
    return 0.0f;
}

__global__ __launch_bounds__(NT)
void topo_decoder_mma11(
    const float* __restrict__ z_geo, const float* __restrict__ z_tex,
    const float* __restrict__ chart_w, const float* __restrict__ chart_b,
    const float* __restrict__ router_w, const float* __restrict__ router_b,
    const float* __restrict__ centers,
    const float* __restrict__ tex_w, const float* __restrict__ tex_b,
    const float* __restrict__ ln_g, const float* __restrict__ ln_b,
    const float* __restrict__ w1, const float* __restrict__ b1,
    const float* __restrict__ w2, const float* __restrict__ b2,
    float* __restrict__ out, int B)
{
    extern __shared__ uint2 smu2[];
    uint2* XI  = smu2;
    uint2* B1I = XI + XI_N;
    uint2* B2I = B1I + B1I_N;
    uint2* B3I = B2I + B2I_N;
    float* smf = (float*)(B3I + B3I_N);
    uint32_t* smw = (uint32_t*)smf;

    const int tid = threadIdx.x;
    const int wid = tid >> 5;
    const int lane = tid & 31;
    const int g = lane >> 2;
    const int t = lane & 3;

    // gelu constants (packed once; ptxas hoists)
    const uint32_t GC0 = pack_f16(0.7978845608f, 0.7978845608f);
    const uint32_t GC1 = pack_f16(0.03567740814f, 0.03567740814f);
    const uint32_t GHF = pack_f16(0.5f, 0.5f);

    // ================== one-time weight packing (fp16) ==================
    for (int idx = tid; idx < B1I_N; idx += NT) {
        int tt = idx & 3, n = (idx >> 2) & 63, ks = idx >> 8;
        int k0 = ks * 16 + 2 * tt;
        uint2 q;
        q.x = pack_f16(b1val(k0,     n, chart_w, tex_w, chart_b, tex_b),
                       b1val(k0 + 1, n, chart_w, tex_w, chart_b, tex_b));
        q.y = pack_f16(b1val(k0 + 8, n, chart_w, tex_w, chart_b, tex_b),
                       b1val(k0 + 9, n, chart_w, tex_w, chart_b, tex_b));
        B1I[idx] = q;
    }
    for (int idx = tid; idx < B2I_N; idx += NT) {
        int tt = idx & 3, n = (idx >> 2) & 63, ks = idx >> 8;
        int k0 = ks * 16 + 2 * tt;
        uint2 q;
        q.x = pack_f16(w1[n * 64 + k0],     w1[n * 64 + k0 + 1]);
        q.y = pack_f16(w1[n * 64 + k0 + 8], w1[n * 64 + k0 + 9]);
        B2I[idx] = q;
    }
    for (int idx = tid; idx < B3I_N; idx += NT) {
        int tt = idx & 3, n = (idx >> 2) & 31, ks = idx >> 7;
        int k0 = ks * 16 + 2 * tt;
        uint2 q;
        q.x = pack_f16(w2[n * 64 + k0],     w2[n * 64 + k0 + 1]);
        q.y = pack_f16(w2[n * 64 + k0 + 8], w2[n * 64 + k0 + 9]);
        B3I[idx] = q;
    }
    if (tid < 64) {
        smf[F_LNG + tid] = ln_g[tid];
        smf[F_LNB + tid] = ln_b[tid];
        smf[F_BB1 + tid] = b1[tid];
    }
    if (tid < 32) {
        smf[F_BB2 + tid] = b2[tid];
        smw[F_BB1H + tid] = pack_f16(b1[2 * tid], b1[2 * tid + 1]);
    }
    if (tid < 128) { smf[F_CEN + tid] = centers[tid]; smf[F_RW + tid] = router_w[tid]; }
    if (tid < 8) {
        smf[F_RB + tid] = router_b[tid];
        float cs = 0.f;
        for (int l = 0; l < 16; ++l) cs = fmaf(centers[tid * 16 + l], centers[tid * 16 + l], cs);
        smf[F_CS + tid] = 1.0f - cs;
    }
    __syncthreads();

    const int nTiles = (B + TILE - 1) / TILE;
    const int xcol = wid * 16;
    const int rl = tid >> 1;          // staging row-in-tile
    const int half = tid & 1;

    for (int tile = blockIdx.x; tile < nTiles; tile += GRID_CTAS) {
        const int rowbase = tile * TILE + xcol;
        const int rawrow = tile * TILE + rl;
        const int srow = rawrow < B ? rawrow : (B - 1);

        // ================== prologue: split router ==================
        uint32_t zgh0, zgh1, zgh2, zgh3;   // this thread's zg slice, fp16x2
        float w8[8];
        {
            float zg[16];
            const float4* p = (const float4*)(z_geo + (size_t)srow * 16);
            #pragma unroll
            for (int q = 0; q < 4; ++q) {
                float4 v = p[q];
                zg[q*4+0]=v.x; zg[q*4+1]=v.y; zg[q*4+2]=v.z; zg[q*4+3]=v.w;
            }
            float z_sq = 0.f;
            #pragma unroll
            for (int l = 0; l < 16; ++l) z_sq = fmaf(zg[l], zg[l], z_sq);
            const float one_minus = 1.0f - z_sq;
            const float inv_tau = __fdividef(1.0f, fmaxf(2.0f * fmaxf(one_minus, 0.001f), 0.01f));

            const int cb = half * 4;
            float s[4], mx = -1e30f;
            #pragma unroll
            for (int i = 0; i < 4; ++i) {
                const int c = cb + i;
                float ds = 0.f, dr = 0.f;
                #pragma unroll
                for (int l = 0; l < 16; ++l) {
                    float cv = smf[F_CEN + c * 16 + l];
                    float d = zg[l] - cv;
                    ds = fmaf(d, d, ds);
                    dr = fmaf(zg[l], smf[F_RW + c * 16 + l], dr);
                }
                float denom = one_minus * smf[F_CS + c];
                float tt2 = fmaxf(2.0f * __fdividef(ds, denom + 0.001f), 0.001f);
                float rad = tt2 * (tt2 + 2.0f);
                float sq = rad * rsqrtf(rad);
                float dist = __logf(1.0f + tt2 + sq);
                s[i] = (-dist + 0.1f * (dr + smf[F_RB + c])) * inv_tau;
                mx = fmaxf(mx, s[i]);
            }
            mx = fmaxf(mx, __shfl_xor_sync(~0u, mx, 1));
            float wloc[4], psum = 0.f;
            #pragma unroll
            for (int i = 0; i < 4; ++i) { wloc[i] = __expf(s[i] - mx); psum += wloc[i]; }
            float ssum = psum + __shfl_xor_sync(~0u, psum, 1);
            const float inv_sum = __fdividef(1.0f, ssum);
            #pragma unroll
            for (int i = 0; i < 4; ++i) {
                float wi = wloc[i] * inv_sum;
                w8[cb + i] = wi;
                w8[(cb ^ 4) + i] = __shfl_xor_sync(~0u, wi, 1);
            }
            if (rawrow < B) {
                float* rout = out + (size_t)B * 32 + (size_t)rawrow * 8 + cb;
                *(float4*)rout = make_float4(w8[cb], w8[cb+1], w8[cb+2], w8[cb+3]);
            }
            zgh0 = pack_f16(zg[4*half + 0], zg[4*half + 1]);
            zgh1 = pack_f16(zg[4*half + 2], zg[4*half + 3]);
            zgh2 = pack_f16(zg[4*half + 8], zg[4*half + 9]);
            zgh3 = pack_f16(zg[4*half + 10], zg[4*half + 11]);
        }
        // prefetch zt slice this thread stages (ks 8)
        float4 ztA = *(const float4*)(z_tex + (size_t)srow * 16 + 4 * half);
        float4 ztB = *(const float4*)(z_tex + (size_t)srow * 16 + 4 * half + 8);
        const float wa0 = half ? w8[4] : w8[0];
        const float wa1 = half ? w8[5] : w8[1];
        const float wb0 = half ? w8[6] : w8[2];
        const float wb1 = half ? w8[7] : w8[3];

        // ================== GEMM1: 2-slot ring over ks (fp16) ==========
        float acc[8][4];
        #pragma unroll
        for (int nb = 0; nb < 8; ++nb)
            #pragma unroll
            for (int j = 0; j < 4; ++j) acc[nb][j] = 0.f;

        #pragma unroll
        for (int p = 0; p < 10; ++p) {
            const int slot = p & 1;
            if (p < 8) {
                const uint32_t wch = pack_f16(w8[p], w8[p]);
                uint2 q0, q1;
                q0.x = h2mul(wch, zgh0); q0.y = h2mul(wch, zgh2);
                q1.x = h2mul(wch, zgh1); q1.y = h2mul(wch, zgh3);
                XI[(slot * 4 + 2 * half)     * XSTRIDE + rl] = q0;
                XI[(slot * 4 + 2 * half + 1) * XSTRIDE + rl] = q1;
            } else if (p == 8) {
                uint2 q0, q1;
                q0.x = pack_f16(ztA.x, ztA.y); q0.y = pack_f16(ztB.x, ztB.y);
                q1.x = pack_f16(ztA.z, ztA.w); q1.y = pack_f16(ztB.z, ztB.w);
                XI[(slot * 4 + 2 * half)     * XSTRIDE + rl] = q0;
                XI[(slot * 4 + 2 * half + 1) * XSTRIDE + rl] = q1;
            } else {
                uint2 q0, q1;
                q0.x = pack_f16(wa0, wa1);
                q0.y = pack_f16(half ? 0.0f : 1.0f, 0.0f);
                q1.x = pack_f16(wb0, wb1);
                q1.y = 0u;
                XI[(slot * 4 + 2 * half)     * XSTRIDE + rl] = q0;
                XI[(slot * 4 + 2 * half + 1) * XSTRIDE + rl] = q1;
            }
            __syncwarp();
            uint2 qa = XI[(slot * 4 + t) * XSTRIDE + xcol + g];
            uint2 qb = XI[(slot * 4 + t) * XSTRIDE + xcol + g + 8];
            uint32_t ah[4] = { qa.x, qb.x, qa.y, qb.y };
            #pragma unroll
            for (int nb = 0; nb < 8; ++nb) {
                uint2 qB = B1I[(p * 64 + nb * 8 + g) * 4 + t];
                mma_f16(acc[nb], ah, qB.x, qB.y);
            }
        }
        __syncwarp();

        // ================== epilogue 1: LayerNorm + GELU(h2) -> A2 frags =====
        uint32_t a2h[4][4];
        {
            float sum0 = 0.f, sum1 = 0.f, sq0 = 0.f, sq1 = 0.f;
            #pragma unroll
            for (int nb = 0; nb < 8; ++nb) {
                sum0 += acc[nb][0] + acc[nb][1];
                sum1 += acc[nb][2] + acc[nb][3];
                sq0 = fmaf(acc[nb][0], acc[nb][0], sq0); sq0 = fmaf(acc[nb][1], acc[nb][1], sq0);
                sq1 = fmaf(acc[nb][2], acc[nb][2], sq1); sq1 = fmaf(acc[nb][3], acc[nb][3], sq1);
            }
            sum0 += __shfl_xor_sync(~0u, sum0, 1); sum0 += __shfl_xor_sync(~0u, sum0, 2);
            sum1 += __shfl_xor_sync(~0u, sum1, 1); sum1 += __shfl_xor_sync(~0u, sum1, 2);
            sq0  += __shfl_xor_sync(~0u, sq0, 1);  sq0  += __shfl_xor_sync(~0u, sq0, 2);
            sq1  += __shfl_xor_sync(~0u, sq1, 1);  sq1  += __shfl_xor_sync(~0u, sq1, 2);
            const float mu0 = sum0 * (1.0f / 64.0f), mu1 = sum1 * (1.0f / 64.0f);
            const float rstd0 = rsqrtf(fmaf(-mu0, mu0, sq0 * (1.0f / 64.0f)) + 1e-5f);
            const float rstd1 = rsqrtf(fmaf(-mu1, mu1, sq1 * (1.0f / 64.0f)) + 1e-5f);
            const float nm0 = -mu0 * rstd0, nm1 = -mu1 * rstd1;

            #pragma unroll
            for (int ks = 0; ks < 4; ++ks) {
                #pragma unroll
                for (int jj = 0; jj < 2; ++jj) {
                    int nb = 2 * ks + jj;
                    int col = nb * 8 + 2 * t;
                    float g0 = smf[F_LNG + col], g1 = smf[F_LNG + col + 1];
                    float e0 = smf[F_LNB + col], e1 = smf[F_LNB + col + 1];
                    float t00 = fmaf(acc[nb][0], rstd0, nm0);
                    float t01 = fmaf(acc[nb][1], rstd0, nm0);
                    float t10 = fmaf(acc[nb][2], rstd1, nm1);
                    float t11 = fmaf(acc[nb][3], rstd1, nm1);
                    uint32_t u0 = pack_f16(fmaf(t00, g0, e0), fmaf(t01, g1, e1));
                    uint32_t u1 = pack_f16(fmaf(t10, g0, e0), fmaf(t11, g1, e1));
                    a2h[ks][2*jj]     = gelu_h2(u0, GC0, GC1, GHF);
                    a2h[ks][2*jj + 1] = gelu_h2(u1, GC0, GC1, GHF);
                }
            }
        }

        // ================== GEMM2: [16x64] x [64x64] (fp16) ============
        #pragma unroll
        for (int nb = 0; nb < 8; ++nb)
            #pragma unroll
            for (int j = 0; j < 4; ++j) acc[nb][j] = 0.f;
        #pragma unroll
        for (int ks = 0; ks < 4; ++ks) {
            #pragma unroll
            for (int nb = 0; nb < 8; ++nb) {
                uint2 qB = B2I[(ks * 64 + nb * 8 + g) * 4 + t];
                mma_f16(acc[nb], a2h[ks], qB.x, qB.y);
            }
        }

        // ================== epilogue 2: +b1(h2), GELU(h2) -> A3 frags ===========
        uint32_t a3h[4][4];
        #pragma unroll
        for (int ks = 0; ks < 4; ++ks) {
            #pragma unroll
            for (int jj = 0; jj < 2; ++jj) {
                int nb = 2 * ks + jj;
                uint32_t bb = smw[F_BB1H + nb * 4 + t];
                uint32_t u0 = h2add(pack_f16(acc[nb][0], acc[nb][1]), bb);
                uint32_t u1 = h2add(pack_f16(acc[nb][2], acc[nb][3]), bb);
                a3h[ks][2*jj]     = gelu_h2(u0, GC0, GC1, GHF);
                a3h[ks][2*jj + 1] = gelu_h2(u1, GC0, GC1, GHF);
            }
        }

        // ================== GEMM3: [16x64] x [64x32] (fp16) ============
        float acc3[4][4];
        #pragma unroll
        for (int nb = 0; nb < 4; ++nb)
            #pragma unroll
            for (int j = 0; j < 4; ++j) acc3[nb][j] = 0.f;
        #pragma unroll
        for (int ks = 0; ks < 4; ++ks) {
            #pragma unroll
            for (int nb = 0; nb < 4; ++nb) {
                uint2 qB = B3I[(ks * 32 + nb * 8 + g) * 4 + t];
                mma_f16(acc3[nb], a3h[ks], qB.x, qB.y);
            }
        }

        // ================== epilogue 3: +b2 -> out ==================
        #pragma unroll
        for (int nb = 0; nb < 4; ++nb) {
            int col = nb * 8 + 2 * t;
            float b20 = smf[F_BB2 + col], b21 = smf[F_BB2 + col + 1];
            if (rowbase + g < B)
                *(float2*)(out + (size_t)(rowbase + g) * 32 + col) =
                    make_float2(acc3[nb][0] + b20, acc3[nb][1] + b21);
            if (rowbase + g + 8 < B)
                *(float2*)(out + (size_t)(rowbase + g + 8) * 32 + col) =
                    make_float2(acc3[nb][2] + b20, acc3[nb][3] + b21);
        }
        __syncwarp();
    }
}

extern "C" void kernel_launch(void* const* d_in, const int* in_sizes, int n_in,
                              void* d_out, int out_size) {
    const float* z_geo    = (const float*)d_in[0];
    const float* z_tex    = (const float*)d_in[1];
    const float* chart_w  = (const float*)d_in[2];
    const float* chart_b  = (const float*)d_in[3];
    const float* router_w = (const float*)d_in[4];
    const float* router_b = (const float*)d_in[5];
    const float* centers  = (const float*)d_in[6];
    const float* tex_w    = (const float*)d_in[7];
    const float* tex_b    = (const float*)d_in[8];
    const float* ln_g     = (const float*)d_in[9];
    const float* ln_b     = (const float*)d_in[10];
    const float* w1       = (const float*)d_in[11];
    const float* b1       = (const float*)d_in[12];
    const float* w2       = (const float*)d_in[13];
    const float* b2       = (const float*)d_in[14];
    float* out = (float*)d_out;

    const int B = in_sizes[0] / 16;
    cudaFuncSetAttribute(topo_decoder_mma11,
                         cudaFuncAttributeMaxDynamicSharedMemorySize, SMEM_BYTES);
    topo_decoder_mma11<<<GRID_CTAS, NT, SMEM_BYTES>>>(
        z_geo, z_tex, chart_w, chart_b, router_w, router_b, centers,
        tex_w, tex_b, ln_g, ln_b, w1, b1, w2, b2, out, B);
}

// round 15
// speedup vs baseline: 9.7445x; 1.0423x over previous
#include <cuda_runtime.h>
#include <cuda_fp16.h>
#include <math.h>
#include <stdint.h>

#define NT 512
#define TILE 512
#define GRID_CTAS 152
#define XSTRIDE 520   // uint2 row stride: 8*520 mod 256 == 64 -> A-reads tile 2x128B phases

// smem: XI (uint2, fp16) | B1I/B2I/B3I (uint2, fp16) | misc floats
#define XI_N   (2 * 4 * XSTRIDE)          // uint2 count
#define B1I_N  2560                        // uint2 count
#define B2I_N  1024
#define B3I_N  512
#define MISC_F 544
#define SMEM_BYTES ((XI_N + B1I_N + B2I_N + B3I_N) * 8 + MISC_F * 4)
// misc float offsets
#define F_LNG  0
#define F_LNB  64
#define F_BB1  128
#define F_BB2  192
#define F_CEN  224
#define F_RW   352
#define F_RB   480
#define F_CS   488
#define F_BB1H 496   // 32 x uint32: b1 pairs packed fp16x2

__device__ __forceinline__ uint32_t pack_f16(float v0, float v1) {
    uint32_t h;
    asm("cvt.rn.f16x2.f32 %0, %1, %2;" : "=r"(h) : "f"(v1), "f"(v0));
    return h;
}
__device__ __forceinline__ uint32_t h2mul(uint32_t a, uint32_t b) {
    uint32_t d; asm("mul.rn.f16x2 %0, %1, %2;" : "=r"(d) : "r"(a), "r"(b)); return d;
}
__device__ __forceinline__ uint32_t h2add(uint32_t a, uint32_t b) {
    uint32_t d; asm("add.rn.f16x2 %0, %1, %2;" : "=r"(d) : "r"(a), "r"(b)); return d;
}
__device__ __forceinline__ uint32_t h2fma(uint32_t a, uint32_t b, uint32_t c) {
    uint32_t d; asm("fma.rn.f16x2 %0, %1, %2, %3;" : "=r"(d) : "r"(a), "r"(b), "r"(c)); return d;
}
// tanh-form gelu on a packed fp16x2 pair: 0.5x(1+tanh(x(c0+c1 x^2)))
__device__ __forceinline__ uint32_t gelu_h2(uint32_t x, uint32_t c0, uint32_t c1, uint32_t chalf) {
    uint32_t x2 = h2mul(x, x);
    uint32_t p  = h2fma(c1, x2, c0);
    uint32_t inner = h2mul(x, p);
    uint32_t th;
    asm("tanh.approx.f16x2 %0, %1;" : "=r"(th) : "r"(inner));
    uint32_t q = h2fma(th, chalf, chalf);
    return h2mul(x, q);
}
__device__ __forceinline__ void mma_f16(float* c, const uint32_t* a, uint32_t b0, uint32_t b1) {
    asm volatile(
        "mma.sync.aligned.m16n8k16.row.col.f32.f16.f16.f32 "
        "{%0,%1,%2,%3}, {%4,%5,%6,%7}, {%8,%9}, {%0,%1,%2,%3};"
        : "+f"(c[0]), "+f"(c[1]), "+f"(c[2]), "+f"(c[3])
        : "r"(a[0]), "r"(a[1]), "r"(a[2]), "r"(a[3]), "r"(b0), "r"(b1));
}
__device__ __forceinline__ float b1val(int k, int h,
    const float* __restrict__ chart_w, const float* __restrict__ tex_w,
    const float* __restrict__ chart_b, const float* __restrict__ tex_b) {
    if (k < 128)  return chart_w[(k >> 4) * 1024 + h * 16 + (k & 15)];
    if (k < 144)  return tex_w[h * 16 + (k - 128)];
    if (k < 152)  return chart_b[(k - 144) * 64 + h];
    if (k == 152) return tex_b[h];
    return 0.0f;
}

__global__ __launch_bounds__(NT)
void topo_decoder_mma12(
    const float* __restrict__ z_geo, const float* __restrict__ z_tex,
    const float* __restrict__ chart_w, const float* __restrict__ chart_b,
    const float* __restrict__ router_w, const float* __restrict__ router_b,
    const float* __restrict__ centers,
    const float* __restrict__ tex_w, const float* __restrict__ tex_b,
    const float* __restrict__ ln_g, const float* __restrict__ ln_b,
    const float* __restrict__ w1, const float* __restrict__ b1,
    const float* __restrict__ w2, const float* __restrict__ b2,
    float* __restrict__ out, int B)
{
    extern __shared__ uint2 smu2[];
    uint2* XI  = smu2;
    uint2* B1I = XI + XI_N;
    uint2* B2I = B1I + B1I_N;
    uint2* B3I = B2I + B2I_N;
    float* smf = (float*)(B3I + B3I_N);
    uint32_t* smw = (uint32_t*)smf;

    const int tid = threadIdx.x;
    const int wid = tid >> 5;
    const int lane = tid & 31;
    const int g = lane >> 2;
    const int t = lane & 3;

    const uint32_t GC0 = pack_f16(0.7978845608f, 0.7978845608f);
    const uint32_t GC1 = pack_f16(0.03567740814f, 0.03567740814f);
    const uint32_t GHF = pack_f16(0.5f, 0.5f);

    // ================== one-time weight packing (fp16) ==================
    for (int idx = tid; idx < B1I_N; idx += NT) {
        int tt = idx & 3, n = (idx >> 2) & 63, ks = idx >> 8;
        int k0 = ks * 16 + 2 * tt;
        uint2 q;
        q.x = pack_f16(b1val(k0,     n, chart_w, tex_w, chart_b, tex_b),
                       b1val(k0 + 1, n, chart_w, tex_w, chart_b, tex_b));
        q.y = pack_f16(b1val(k0 + 8, n, chart_w, tex_w, chart_b, tex_b),
                       b1val(k0 + 9, n, chart_w, tex_w, chart_b, tex_b));
        B1I[idx] = q;
    }
    for (int idx = tid; idx < B2I_N; idx += NT) {
        int tt = idx & 3, n = (idx >> 2) & 63, ks = idx >> 8;
        int k0 = ks * 16 + 2 * tt;
        uint2 q;
        q.x = pack_f16(w1[n * 64 + k0],     w1[n * 64 + k0 + 1]);
        q.y = pack_f16(w1[n * 64 + k0 + 8], w1[n * 64 + k0 + 9]);
        B2I[idx] = q;
    }
    for (int idx = tid; idx < B3I_N; idx += NT) {
        int tt = idx & 3, n = (idx >> 2) & 31, ks = idx >> 7;
        int k0 = ks * 16 + 2 * tt;
        uint2 q;
        q.x = pack_f16(w2[n * 64 + k0],     w2[n * 64 + k0 + 1]);
        q.y = pack_f16(w2[n * 64 + k0 + 8], w2[n * 64 + k0 + 9]);
        B3I[idx] = q;
    }
    if (tid < 64) {
        smf[F_LNG + tid] = ln_g[tid];
        smf[F_LNB + tid] = ln_b[tid];
        smf[F_BB1 + tid] = b1[tid];
    }
    if (tid < 32) {
        smf[F_BB2 + tid] = b2[tid];
        smw[F_BB1H + tid] = pack_f16(b1[2 * tid], b1[2 * tid + 1]);
    }
    if (tid < 128) { smf[F_CEN + tid] = centers[tid]; smf[F_RW + tid] = router_w[tid]; }
    if (tid < 8) {
        smf[F_RB + tid] = router_b[tid];
        float cs = 0.f;
        for (int l = 0; l < 16; ++l) cs = fmaf(centers[tid * 16 + l], centers[tid * 16 + l], cs);
        smf[F_CS + tid] = 1.0f - cs;
    }
    __syncthreads();

    const int nTiles = (B + TILE - 1) / TILE;
    const int xcol = wid * 32;        // this warp's 32 rows

    for (int tile = blockIdx.x; tile < nTiles; tile += GRID_CTAS) {
        const int rowbase = tile * TILE + xcol;
        const int rawrow = tile * TILE + tid;               // staging: 1 thread per row
        const int srow = rawrow < B ? rawrow : (B - 1);

        // ================== prologue: full router per thread ==================
        uint32_t zgh[8], zth[8];
        float w8[8];
        {
            float zg[16];
            const float4* p = (const float4*)(z_geo + (size_t)srow * 16);
            #pragma unroll
            for (int q = 0; q < 4; ++q) {
                float4 v = p[q];
                zg[q*4+0]=v.x; zg[q*4+1]=v.y; zg[q*4+2]=v.z; zg[q*4+3]=v.w;
            }
            float z_sq = 0.f;
            #pragma unroll
            for (int l = 0; l < 16; ++l) z_sq = fmaf(zg[l], zg[l], z_sq);
            const float one_minus = 1.0f - z_sq;
            const float inv_tau = __fdividef(1.0f, fmaxf(2.0f * fmaxf(one_minus, 0.001f), 0.01f));

            float mx = -1e30f;
            #pragma unroll
            for (int c = 0; c < 8; ++c) {
                float ds = 0.f, dr = 0.f;
                #pragma unroll
                for (int l = 0; l < 16; ++l) {
                    float cv = smf[F_CEN + c * 16 + l];
                    float d = zg[l] - cv;
                    ds = fmaf(d, d, ds);
                    dr = fmaf(zg[l], smf[F_RW + c * 16 + l], dr);
                }
                float denom = one_minus * smf[F_CS + c];
                float tt2 = fmaxf(2.0f * __fdividef(ds, denom + 0.001f), 0.001f);
                float rad = tt2 * (tt2 + 2.0f);
                float sq = rad * rsqrtf(rad);
                float dist = __logf(1.0f + tt2 + sq);
                w8[c] = (-dist + 0.1f * (dr + smf[F_RB + c])) * inv_tau;
                mx = fmaxf(mx, w8[c]);
            }
            float ssum = 0.f;
            #pragma unroll
            for (int c = 0; c < 8; ++c) { w8[c] = __expf(w8[c] - mx); ssum += w8[c]; }
            const float inv_sum = __fdividef(1.0f, ssum);
            #pragma unroll
            for (int c = 0; c < 8; ++c) w8[c] *= inv_sum;

            if (rawrow < B) {
                float* rout = out + (size_t)B * 32 + (size_t)rawrow * 8;
                ((float4*)rout)[0] = make_float4(w8[0], w8[1], w8[2], w8[3]);
                ((float4*)rout)[1] = make_float4(w8[4], w8[5], w8[6], w8[7]);
            }
            #pragma unroll
            for (int j = 0; j < 8; ++j) zgh[j] = pack_f16(zg[2*j], zg[2*j+1]);
            const float4* p2 = (const float4*)(z_tex + (size_t)srow * 16);
            #pragma unroll
            for (int q = 0; q < 4; ++q) {
                float4 v = p2[q];
                zth[2*q]   = pack_f16(v.x, v.y);
                zth[2*q+1] = pack_f16(v.z, v.w);
            }
        }

        // ================== GEMM1: 2-slot ring over ks, 2 m-blocks ==========
        float acc[2][8][4];
        #pragma unroll
        for (int mb = 0; mb < 2; ++mb)
            #pragma unroll
            for (int nb = 0; nb < 8; ++nb)
                #pragma unroll
                for (int j = 0; j < 4; ++j) acc[mb][nb][j] = 0.f;

        #pragma unroll
        for (int p = 0; p < 10; ++p) {
            const int slot = p & 1;
            // ---- stage ks p: this thread stages its full row (4 tt slots) ----
            if (p < 8) {
                const uint32_t wch = pack_f16(w8[p], w8[p]);
                #pragma unroll
                for (int tt = 0; tt < 4; ++tt) {
                    uint2 q;
                    q.x = h2mul(wch, zgh[tt]);
                    q.y = h2mul(wch, zgh[tt + 4]);
                    XI[(slot * 4 + tt) * XSTRIDE + tid] = q;
                }
            } else if (p == 8) {
                #pragma unroll
                for (int tt = 0; tt < 4; ++tt) {
                    uint2 q;
                    q.x = zth[tt];
                    q.y = zth[tt + 4];
                    XI[(slot * 4 + tt) * XSTRIDE + tid] = q;
                }
            } else {
                const uint32_t one0 = pack_f16(1.0f, 0.0f);
                #pragma unroll
                for (int tt = 0; tt < 4; ++tt) {
                    uint2 q;
                    q.x = pack_f16(w8[2*tt], w8[2*tt+1]);
                    q.y = (tt == 0) ? one0 : 0u;
                    XI[(slot * 4 + tt) * XSTRIDE + tid] = q;
                }
            }
            __syncwarp();
            // ---- MMA ks p: shared B across both m-blocks ----
            uint2 qa0 = XI[(slot * 4 + t) * XSTRIDE + xcol + g];
            uint2 qb0 = XI[(slot * 4 + t) * XSTRIDE + xcol + g + 8];
            uint2 qa1 = XI[(slot * 4 + t) * XSTRIDE + xcol + 16 + g];
            uint2 qb1 = XI[(slot * 4 + t) * XSTRIDE + xcol + 16 + g + 8];
            uint32_t ah0[4] = { qa0.x, qb0.x, qa0.y, qb0.y };
            uint32_t ah1[4] = { qa1.x, qb1.x, qa1.y, qb1.y };
            #pragma unroll
            for (int nb = 0; nb < 8; ++nb) {
                uint2 qB = B1I[(p * 64 + nb * 8 + g) * 4 + t];
                mma_f16(acc[0][nb], ah0, qB.x, qB.y);
                mma_f16(acc[1][nb], ah1, qB.x, qB.y);
            }
        }
        __syncwarp();

        // ================== epilogue 1: LayerNorm + GELU(h2) -> A2 frags =====
        uint32_t a2h[2][4][4];
        #pragma unroll
        for (int mb = 0; mb < 2; ++mb) {
            float sum0 = 0.f, sum1 = 0.f, sq0 = 0.f, sq1 = 0.f;
            #pragma unroll
            for (int nb = 0; nb < 8; ++nb) {
                sum0 += acc[mb][nb][0] + acc[mb][nb][1];
                sum1 += acc[mb][nb][2] + acc[mb][nb][3];
                sq0 = fmaf(acc[mb][nb][0], acc[mb][nb][0], sq0);
                sq0 = fmaf(acc[mb][nb][1], acc[mb][nb][1], sq0);
                sq1 = fmaf(acc[mb][nb][2], acc[mb][nb][2], sq1);
                sq1 = fmaf(acc[mb][nb][3], acc[mb][nb][3], sq1);
            }
            sum0 += __shfl_xor_sync(~0u, sum0, 1); sum0 += __shfl_xor_sync(~0u, sum0, 2);
            sum1 += __shfl_xor_sync(~0u, sum1, 1); sum1 += __shfl_xor_sync(~0u, sum1, 2);
            sq0  += __shfl_xor_sync(~0u, sq0, 1);  sq0  += __shfl_xor_sync(~0u, sq0, 2);
            sq1  += __shfl_xor_sync(~0u, sq1, 1);  sq1  += __shfl_xor_sync(~0u, sq1, 2);
            const float mu0 = sum0 * (1.0f / 64.0f), mu1 = sum1 * (1.0f / 64.0f);
            const float rstd0 = rsqrtf(fmaf(-mu0, mu0, sq0 * (1.0f / 64.0f)) + 1e-5f);
            const float rstd1 = rsqrtf(fmaf(-mu1, mu1, sq1 * (1.0f / 64.0f)) + 1e-5f);
            const float nm0 = -mu0 * rstd0, nm1 = -mu1 * rstd1;

            #pragma unroll
            for (int ks = 0; ks < 4; ++ks) {
                #pragma unroll
                for (int jj = 0; jj < 2; ++jj) {
                    int nb = 2 * ks + jj;
                    int col = nb * 8 + 2 * t;
                    float g0 = smf[F_LNG + col], g1 = smf[F_LNG + col + 1];
                    float e0 = smf[F_LNB + col], e1 = smf[F_LNB + col + 1];
                    float t00 = fmaf(acc[mb][nb][0], rstd0, nm0);
                    float t01 = fmaf(acc[mb][nb][1], rstd0, nm0);
                    float t10 = fmaf(acc[mb][nb][2], rstd1, nm1);
                    float t11 = fmaf(acc[mb][nb][3], rstd1, nm1);
                    uint32_t u0 = pack_f16(fmaf(t00, g0, e0), fmaf(t01, g1, e1));
                    uint32_t u1 = pack_f16(fmaf(t10, g0, e0), fmaf(t11, g1, e1));
                    a2h[mb][ks][2*jj]     = gelu_h2(u0, GC0, GC1, GHF);
                    a2h[mb][ks][2*jj + 1] = gelu_h2(u1, GC0, GC1, GHF);
                }
            }
        }

        // ================== GEMM2: shared B across m-blocks ============
        #pragma unroll
        for (int mb = 0; mb < 2; ++mb)
            #pragma unroll
            for (int nb = 0; nb < 8; ++nb)
                #pragma unroll
                for (int j = 0; j < 4; ++j) acc[mb][nb][j] = 0.f;
        #pragma unroll
        for (int ks = 0; ks < 4; ++ks) {
            #pragma unroll
            for (int nb = 0; nb < 8; ++nb) {
                uint2 qB = B2I[(ks * 64 + nb * 8 + g) * 4 + t];
                mma_f16(acc[0][nb], a2h[0][ks], qB.x, qB.y);
                mma_f16(acc[1][nb], a2h[1][ks], qB.x, qB.y);
            }
        }

        // ================== epilogue 2: +b1(h2), GELU(h2) -> A3 frags ===========
        uint32_t a3h[2][4][4];
        #pragma unroll
        for (int mb = 0; mb < 2; ++mb) {
            #pragma unroll
            for (int ks = 0; ks < 4; ++ks) {
                #pragma unroll
                for (int jj = 0; jj < 2; ++jj) {
                    int nb = 2 * ks + jj;
                    uint32_t bb = smw[F_BB1H + nb * 4 + t];
                    uint32_t u0 = h2add(pack_f16(acc[mb][nb][0], acc[mb][nb][1]), bb);
                    uint32_t u1 = h2add(pack_f16(acc[mb][nb][2], acc[mb][nb][3]), bb);
                    a3h[mb][ks][2*jj]     = gelu_h2(u0, GC0, GC1, GHF);
                    a3h[mb][ks][2*jj + 1] = gelu_h2(u1, GC0, GC1, GHF);
                }
            }
        }

        // ================== GEMM3: shared B across m-blocks ============
        float acc3[2][4][4];
        #pragma unroll
        for (int mb = 0; mb < 2; ++mb)
            #pragma unroll
            for (int nb = 0; nb < 4; ++nb)
                #pragma unroll
                for (int j = 0; j < 4; ++j) acc3[mb][nb][j] = 0.f;
        #pragma unroll
        for (int ks = 0; ks < 4; ++ks) {
            #pragma unroll
            for (int nb = 0; nb < 4; ++nb) {
                uint2 qB = B3I[(ks * 32 + nb * 8 + g) * 4 + t];
                mma_f16(acc3[0][nb], a3h[0][ks], qB.x, qB.y);
                mma_f16(acc3[1][nb], a3h[1][ks], qB.x, qB.y);
            }
        }

        // ================== epilogue 3: +b2 -> out ==================
        #pragma unroll
        for (int mb = 0; mb < 2; ++mb) {
            const int rb = rowbase + mb * 16;
            #pragma unroll
            for (int nb = 0; nb < 4; ++nb) {
                int col = nb * 8 + 2 * t;
                float b20 = smf[F_BB2 + col], b21 = smf[F_BB2 + col + 1];
                if (rb + g < B)
                    *(float2*)(out + (size_t)(rb + g) * 32 + col) =
                        make_float2(acc3[mb][nb][0] + b20, acc3[mb][nb][1] + b21);
                if (rb + g + 8 < B)
                    *(float2*)(out + (size_t)(rb + g + 8) * 32 + col) =
                        make_float2(acc3[mb][nb][2] + b20, acc3[mb][nb][3] + b21);
            }
        }
        __syncwarp();
    }
}

extern "C" void kernel_launch(void* const* d_in, const int* in_sizes, int n_in,
                              void* d_out, int out_size) {
    const float* z_geo    = (const float*)d_in[0];
    const float* z_tex    = (const float*)d_in[1];
    const float* chart_w  = (const float*)d_in[2];
    const float* chart_b  = (const float*)d_in[3];
    const float* router_w = (const float*)d_in[4];
    const float* router_b = (const float*)d_in[5];
    const float* centers  = (const float*)d_in[6];
    const float* tex_w    = (const float*)d_in[7];
    const float* tex_b    = (const float*)d_in[8];
    const float* ln_g     = (const float*)d_in[9];
    const float* ln_b     = (const float*)d_in[10];
    const float* w1       = (const float*)d_in[11];
    const float* b1       = (const float*)d_in[12];
    const float* w2       = (const float*)d_in[13];
    const float* b2       = (const float*)d_in[14];
    float* out = (float*)d_out;

    const int B = in_sizes[0] / 16;
    cudaFuncSetAttribute(topo_decoder_mma12,
                         cudaFuncAttributeMaxDynamicSharedMemorySize, SMEM_BYTES);
    topo_decoder_mma12<<<GRID_CTAS, NT, SMEM_BYTES>>>(
        z_geo, z_tex, chart_w, chart_b, router_w, router_b, centers,
        tex_w, tex_b, ln_g, ln_b, w1, b1, w2, b2, out, B);
}